// round 1
// baseline (speedup 1.0000x reference)
#include <cuda_runtime.h>
#include <cuda_bf16.h>
#include <math.h>

// Problem constants
#define BB 8
#define CC 512
#define CH 256
#define RR 64
#define NN 4096   // H*W = 64*64

// ---------------- scratch (device globals; no allocation) ----------------
__device__ float g_Wtop[256 * 512];
__device__ float g_Wbot[256 * 512];
__device__ float g_bqk[256];
__device__ float g_Wc[512 * 128];
__device__ float g_bout[512];
__device__ float g_qk[(size_t)BB * 256 * NN];          // rows: 0-63 q1, 64-127 k1, 128-191 q2, 192-255 k2
__device__ float g_E[(size_t)BB * NN * NN];            // exp(S), 536 MB
__device__ float g_Zinv[BB * NN];
__device__ float g_Gp[BB * 8 * 64 * 64];               // channel Gram partials (8 n-chunks)
__device__ float g_A[BB * 64 * 64];                    // channel attention
__device__ float g_osc[(size_t)BB * 128 * NN];         // rows 0-63 out_s, 64-127 out_c

// ---------------- weight folding ----------------
// Wtop[j][c] = sum_u proj[j][u] * wt[uoff+u][c]   (same for Wbot with wb)
__global__ void fold_qk(const float* __restrict__ wt, const float* __restrict__ wb,
                        const float* __restrict__ sw1, const float* __restrict__ sw2,
                        const float* __restrict__ cwq, const float* __restrict__ cwk) {
    int idx = blockIdx.x * blockDim.x + threadIdx.x;   // 0..131071
    int j = idx >> 9, c = idx & 511;
    const float* wrow; int uoff;
    if (j < 64)       { wrow = sw1 + j * 256;        uoff = 0;   }
    else if (j < 128) { wrow = sw2 + (j - 64) * 256; uoff = 0;   }
    else if (j < 192) { wrow = cwq + (j - 128) * 256; uoff = 256; }
    else              { wrow = cwk + (j - 192) * 256; uoff = 256; }
    float at = 0.f, ab = 0.f;
    #pragma unroll 8
    for (int u = 0; u < 256; ++u) {
        float w = wrow[u];
        at = fmaf(w, wt[(uoff + u) * 512 + c], at);
        ab = fmaf(w, wb[(uoff + u) * 512 + c], ab);
    }
    g_Wtop[idx] = at;
    g_Wbot[idx] = ab;
}

// Wc[o][t] : t<64 -> f_w[:, :256] @ s_wo ; t>=64 -> f_w[:, 256:] @ c_wo
__global__ void fold_out(const float* __restrict__ fw, const float* __restrict__ swo,
                         const float* __restrict__ cwo) {
    int idx = blockIdx.x * blockDim.x + threadIdx.x;   // 0..65535
    int o = idx >> 7, t = idx & 127;
    float acc = 0.f;
    if (t < 64) {
        #pragma unroll 8
        for (int u = 0; u < 256; ++u)
            acc = fmaf(fw[o * 512 + u], swo[u * 64 + t], acc);
    } else {
        int r = t - 64;
        #pragma unroll 8
        for (int u = 0; u < 256; ++u)
            acc = fmaf(fw[o * 512 + 256 + u], cwo[u * 64 + r], acc);
    }
    g_Wc[idx] = acc;
}

__global__ void fold_bias(const float* __restrict__ bt, const float* __restrict__ bb,
                          const float* __restrict__ sb1, const float* __restrict__ sb2,
                          const float* __restrict__ cbq, const float* __restrict__ cbk,
                          const float* __restrict__ fw,  const float* __restrict__ sbo,
                          const float* __restrict__ cbo, const float* __restrict__ fb,
                          const float* __restrict__ sw1, const float* __restrict__ sw2,
                          const float* __restrict__ cwq, const float* __restrict__ cwk) {
    int t = threadIdx.x;   // blockDim = 512
    if (t < 256) {
        const float* wrow; int uoff; float ob;
        int j = t;
        if (j < 64)       { wrow = sw1 + j * 256;        uoff = 0;   ob = sb1[j];       }
        else if (j < 128) { wrow = sw2 + (j - 64) * 256; uoff = 0;   ob = sb2[j - 64];  }
        else if (j < 192) { wrow = cwq + (j - 128) * 256; uoff = 256; ob = cbq[j - 128]; }
        else              { wrow = cwk + (j - 192) * 256; uoff = 256; ob = cbk[j - 192]; }
        float s = ob;
        for (int u = 0; u < 256; ++u)
            s = fmaf(wrow[u], bt[uoff + u] + bb[uoff + u], s);
        g_bqk[j] = s;
    }
    // output bias (all 512 threads)
    float s2 = fb[t];
    for (int u = 0; u < 256; ++u) {
        s2 = fmaf(fw[t * 512 + u],       sbo[u], s2);
        s2 = fmaf(fw[t * 512 + 256 + u], cbo[u], s2);
    }
    g_bout[t] = s2;
}

// ---------------- qk GEMM: qk[b][j][p] = Wtop[j]·top[b][:,p] + Wbot[j]·bot[b][:,p] + bqk[j]
__global__ void __launch_bounds__(256) qk_gemm(const float* __restrict__ top,
                                               const float* __restrict__ bot) {
    int b = blockIdx.z;
    int j0 = blockIdx.y * 64;
    int p0 = blockIdx.x * 64;
    int tx = threadIdx.x & 15, ty = threadIdx.x >> 4;
    __shared__ float As[16][68];
    __shared__ float Bs[16][64];
    float acc[4][4] = {};
    int ldA_j = threadIdx.x >> 2;
    int ldA_c = (threadIdx.x & 3) * 4;
    int ldB_c = threadIdx.x >> 4;
    int ldB_p = (threadIdx.x & 15) * 4;
    for (int step = 0; step < 64; ++step) {
        const float* W = (step < 32) ? g_Wtop : g_Wbot;
        const float* X = (step < 32) ? top : bot;
        int c0 = (step & 31) * 16;
        __syncthreads();
        {
            float4 v = *(const float4*)&W[(j0 + ldA_j) * 512 + c0 + ldA_c];
            As[ldA_c + 0][ldA_j] = v.x;
            As[ldA_c + 1][ldA_j] = v.y;
            As[ldA_c + 2][ldA_j] = v.z;
            As[ldA_c + 3][ldA_j] = v.w;
            float4 u = *(const float4*)&X[((size_t)(b * 512 + c0 + ldB_c)) * NN + p0 + ldB_p];
            *(float4*)&Bs[ldB_c][ldB_p] = u;
        }
        __syncthreads();
        #pragma unroll
        for (int c = 0; c < 16; ++c) {
            float4 a4 = *(float4*)&As[c][ty * 4];
            float4 b4 = *(float4*)&Bs[c][tx * 4];
            float aa[4] = {a4.x, a4.y, a4.z, a4.w};
            float bb2[4] = {b4.x, b4.y, b4.z, b4.w};
            #pragma unroll
            for (int i = 0; i < 4; ++i)
                #pragma unroll
                for (int j = 0; j < 4; ++j)
                    acc[i][j] = fmaf(aa[i], bb2[j], acc[i][j]);
        }
    }
    #pragma unroll
    for (int i = 0; i < 4; ++i) {
        int j = j0 + ty * 4 + i;
        float bias = g_bqk[j];
        float4 o;
        o.x = acc[i][0] + bias; o.y = acc[i][1] + bias;
        o.z = acc[i][2] + bias; o.w = acc[i][3] + bias;
        *(float4*)&g_qk[((size_t)(b * 256 + j)) * NN + p0 + tx * 4] = o;
    }
}

// ---------------- spatial pass A: E = exp(Q^T K), Zinv[n] = 1/sum_m E[n][m]
__global__ void __launch_bounds__(256) spatial_passA() {
    int b = blockIdx.y;
    int n0 = blockIdx.x * 64;
    int tx = threadIdx.x & 15, ty = threadIdx.x >> 4;
    __shared__ float Qs[64][68];   // [r][n]
    __shared__ float Ks[64][68];   // [r][m]
    int ld_r = threadIdx.x >> 4;
    int ld_c = (threadIdx.x & 15) * 4;
    // load Q tile (rows 0..63 of qk)
    #pragma unroll
    for (int k = 0; k < 4; ++k) {
        int r = ld_r + k * 16;
        float4 v = *(const float4*)&g_qk[((size_t)(b * 256 + r)) * NN + n0 + ld_c];
        *(float4*)&Qs[r][ld_c] = v;
    }
    float zacc[4] = {0.f, 0.f, 0.f, 0.f};
    size_t ebase = ((size_t)b) << 24;
    for (int mt = 0; mt < 64; ++mt) {
        int m0 = mt * 64;
        __syncthreads();
        #pragma unroll
        for (int k = 0; k < 4; ++k) {
            int r = ld_r + k * 16;
            float4 v = *(const float4*)&g_qk[((size_t)(b * 256 + 64 + r)) * NN + m0 + ld_c];
            *(float4*)&Ks[r][ld_c] = v;
        }
        __syncthreads();
        float s[4][4] = {};
        #pragma unroll 8
        for (int r = 0; r < 64; ++r) {
            float4 q4 = *(float4*)&Qs[r][ty * 4];
            float4 k4 = *(float4*)&Ks[r][tx * 4];
            float qa[4] = {q4.x, q4.y, q4.z, q4.w};
            float kb[4] = {k4.x, k4.y, k4.z, k4.w};
            #pragma unroll
            for (int i = 0; i < 4; ++i)
                #pragma unroll
                for (int j = 0; j < 4; ++j)
                    s[i][j] = fmaf(qa[i], kb[j], s[i][j]);
        }
        #pragma unroll
        for (int i = 0; i < 4; ++i) {
            int n = n0 + ty * 4 + i;
            float4 e;
            e.x = __expf(s[i][0]); e.y = __expf(s[i][1]);
            e.z = __expf(s[i][2]); e.w = __expf(s[i][3]);
            *(float4*)&g_E[ebase + (((size_t)n) << 12) + m0 + tx * 4] = e;
            zacc[i] += e.x + e.y + e.z + e.w;
        }
    }
    __syncthreads();
    float* zs = &Qs[0][0];   // reuse as flat 1024-float scratch
    #pragma unroll
    for (int i = 0; i < 4; ++i)
        zs[(ty * 4 + i) * 16 + tx] = zacc[i];
    __syncthreads();
    if (threadIdx.x < 64) {
        float s = 0.f;
        #pragma unroll
        for (int t = 0; t < 16; ++t) s += zs[threadIdx.x * 16 + t];
        g_Zinv[b * NN + n0 + threadIdx.x] = 1.0f / s;
    }
}

// ---------------- spatial pass B: out_s[r][m] = sum_n (K[r][n]*Zinv[n]) * E[n][m]
__global__ void __launch_bounds__(256) spatial_passB() {
    int b = blockIdx.y;
    int m0 = blockIdx.x * 64;
    int tx = threadIdx.x & 15, ty = threadIdx.x >> 4;
    __shared__ float Ks[64][68];   // [n][r]  (Kh transposed)
    __shared__ float Es[64][68];   // [n][m]
    float acc[4][4] = {};
    int ld_r = threadIdx.x >> 4;
    int ld_c = (threadIdx.x & 15) * 4;
    size_t ebase = ((size_t)b) << 24;
    for (int nt = 0; nt < 64; ++nt) {
        int n0 = nt * 64;
        __syncthreads();
        #pragma unroll
        for (int k = 0; k < 4; ++k) {
            int r = ld_r + k * 16;
            float4 v = *(const float4*)&g_qk[((size_t)(b * 256 + 64 + r)) * NN + n0 + ld_c];
            float4 z = *(const float4*)&g_Zinv[b * NN + n0 + ld_c];
            Ks[ld_c + 0][r] = v.x * z.x;
            Ks[ld_c + 1][r] = v.y * z.y;
            Ks[ld_c + 2][r] = v.z * z.z;
            Ks[ld_c + 3][r] = v.w * z.w;
            int n = ld_r + k * 16;
            float4 e = *(const float4*)&g_E[ebase + (((size_t)(n0 + n)) << 12) + m0 + ld_c];
            *(float4*)&Es[n][ld_c] = e;
        }
        __syncthreads();
        #pragma unroll 8
        for (int n = 0; n < 64; ++n) {
            float4 k4 = *(float4*)&Ks[n][ty * 4];
            float4 e4 = *(float4*)&Es[n][tx * 4];
            float ka[4] = {k4.x, k4.y, k4.z, k4.w};
            float eb[4] = {e4.x, e4.y, e4.z, e4.w};
            #pragma unroll
            for (int i = 0; i < 4; ++i)
                #pragma unroll
                for (int j = 0; j < 4; ++j)
                    acc[i][j] = fmaf(ka[i], eb[j], acc[i][j]);
        }
    }
    #pragma unroll
    for (int i = 0; i < 4; ++i) {
        float4 o;
        o.x = acc[i][0]; o.y = acc[i][1]; o.z = acc[i][2]; o.w = acc[i][3];
        *(float4*)&g_osc[((size_t)(b * 128 + ty * 4 + i)) * NN + m0 + tx * 4] = o;
    }
}

// ---------------- channel Gram partials: Gp[b][chunk][r][s] = sum_{n in chunk} q2[r][n] k2[s][n]
__global__ void __launch_bounds__(256) chan_gram() {
    int b = blockIdx.y;
    int chunk = blockIdx.x;             // 8 chunks of 512 n each
    int tx = threadIdx.x & 15, ty = threadIdx.x >> 4;
    __shared__ float Qc[64][68];        // [n][r]
    __shared__ float Kc[64][68];        // [n][s]
    float acc[4][4] = {};
    int ld_r = threadIdx.x >> 4;
    int ld_c = (threadIdx.x & 15) * 4;
    for (int sub = 0; sub < 8; ++sub) {
        int n0 = chunk * 512 + sub * 64;
        __syncthreads();
        #pragma unroll
        for (int k = 0; k < 4; ++k) {
            int r = ld_r + k * 16;
            float4 q = *(const float4*)&g_qk[((size_t)(b * 256 + 128 + r)) * NN + n0 + ld_c];
            Qc[ld_c + 0][r] = q.x; Qc[ld_c + 1][r] = q.y;
            Qc[ld_c + 2][r] = q.z; Qc[ld_c + 3][r] = q.w;
            float4 w = *(const float4*)&g_qk[((size_t)(b * 256 + 192 + r)) * NN + n0 + ld_c];
            Kc[ld_c + 0][r] = w.x; Kc[ld_c + 1][r] = w.y;
            Kc[ld_c + 2][r] = w.z; Kc[ld_c + 3][r] = w.w;
        }
        __syncthreads();
        #pragma unroll 8
        for (int n = 0; n < 64; ++n) {
            float4 q4 = *(float4*)&Qc[n][ty * 4];
            float4 k4 = *(float4*)&Kc[n][tx * 4];
            float qa[4] = {q4.x, q4.y, q4.z, q4.w};
            float kb[4] = {k4.x, k4.y, k4.z, k4.w};
            #pragma unroll
            for (int i = 0; i < 4; ++i)
                #pragma unroll
                for (int j = 0; j < 4; ++j)
                    acc[i][j] = fmaf(qa[i], kb[j], acc[i][j]);
        }
    }
    #pragma unroll
    for (int i = 0; i < 4; ++i)
        #pragma unroll
        for (int j = 0; j < 4; ++j)
            g_Gp[(b * 8 + chunk) * 4096 + (ty * 4 + i) * 64 + tx * 4 + j] = acc[i][j];
}

// ---------------- channel softmax (rows over s, with max subtraction)
__global__ void chan_softmax() {
    int r = blockIdx.x;
    int b = blockIdx.y;
    int s = threadIdx.x;   // 64 threads
    __shared__ float red[64];
    float v = 0.f;
    #pragma unroll
    for (int ch = 0; ch < 8; ++ch)
        v += g_Gp[(b * 8 + ch) * 4096 + r * 64 + s];
    red[s] = v;
    __syncthreads();
    for (int off = 32; off >= 1; off >>= 1) {
        if (s < off) red[s] = fmaxf(red[s], red[s + off]);
        __syncthreads();
    }
    float mx = red[0];
    __syncthreads();
    float e = __expf(v - mx);
    red[s] = e;
    __syncthreads();
    for (int off = 32; off >= 1; off >>= 1) {
        if (s < off) red[s] += red[s + off];
        __syncthreads();
    }
    g_A[b * 4096 + r * 64 + s] = e / red[0];
}

// ---------------- channel output: out_c[r][p] = sum_s A[r][s] * k2[s][p]
__global__ void __launch_bounds__(256) chan_out() {
    int b = blockIdx.y;
    int p = blockIdx.x * 256 + threadIdx.x;
    __shared__ float As[64][64];
    #pragma unroll
    for (int k = 0; k < 16; ++k)
        (&As[0][0])[threadIdx.x + k * 256] = g_A[b * 4096 + threadIdx.x + k * 256];
    __syncthreads();
    float kreg[64];
    #pragma unroll
    for (int s = 0; s < 64; ++s)
        kreg[s] = g_qk[((size_t)(b * 256 + 192 + s)) * NN + p];
    #pragma unroll 4
    for (int r = 0; r < 64; ++r) {
        float acc = 0.f;
        float4* arow = (float4*)&As[r][0];
        #pragma unroll
        for (int s4 = 0; s4 < 16; ++s4) {
            float4 a = arow[s4];
            acc = fmaf(a.x, kreg[s4 * 4 + 0], acc);
            acc = fmaf(a.y, kreg[s4 * 4 + 1], acc);
            acc = fmaf(a.z, kreg[s4 * 4 + 2], acc);
            acc = fmaf(a.w, kreg[s4 * 4 + 3], acc);
        }
        g_osc[((size_t)(b * 128 + 64 + r)) * NN + p] = acc;
    }
}

// ---------------- final GEMM: y[b][o][p] = sum_t Wc[o][t] * osc[b][t][p] + bout[o]
__global__ void __launch_bounds__(256) final_gemm(float* __restrict__ out) {
    int b = blockIdx.z;
    int o0 = blockIdx.y * 64;
    int p0 = blockIdx.x * 64;
    int tx = threadIdx.x & 15, ty = threadIdx.x >> 4;
    __shared__ float Ws[16][68];   // [t][o]
    __shared__ float Xs[16][64];   // [t][p]
    float acc[4][4] = {};
    int ldW_o = threadIdx.x >> 2;
    int ldW_t = (threadIdx.x & 3) * 4;
    int ldX_t = threadIdx.x >> 4;
    int ldX_p = (threadIdx.x & 15) * 4;
    for (int kt = 0; kt < 8; ++kt) {
        int t0 = kt * 16;
        __syncthreads();
        {
            float4 v = *(const float4*)&g_Wc[(o0 + ldW_o) * 128 + t0 + ldW_t];
            Ws[ldW_t + 0][ldW_o] = v.x;
            Ws[ldW_t + 1][ldW_o] = v.y;
            Ws[ldW_t + 2][ldW_o] = v.z;
            Ws[ldW_t + 3][ldW_o] = v.w;
            float4 u = *(const float4*)&g_osc[((size_t)(b * 128 + t0 + ldX_t)) * NN + p0 + ldX_p];
            *(float4*)&Xs[ldX_t][ldX_p] = u;
        }
        __syncthreads();
        #pragma unroll
        for (int t = 0; t < 16; ++t) {
            float4 w4 = *(float4*)&Ws[t][ty * 4];
            float4 x4 = *(float4*)&Xs[t][tx * 4];
            float wa[4] = {w4.x, w4.y, w4.z, w4.w};
            float xb[4] = {x4.x, x4.y, x4.z, x4.w};
            #pragma unroll
            for (int i = 0; i < 4; ++i)
                #pragma unroll
                for (int j = 0; j < 4; ++j)
                    acc[i][j] = fmaf(wa[i], xb[j], acc[i][j]);
        }
    }
    #pragma unroll
    for (int i = 0; i < 4; ++i) {
        int o = o0 + ty * 4 + i;
        float bias = g_bout[o];
        float4 y;
        y.x = acc[i][0] + bias; y.y = acc[i][1] + bias;
        y.z = acc[i][2] + bias; y.w = acc[i][3] + bias;
        *(float4*)&out[((size_t)(b * 512 + o)) * NN + p0 + tx * 4] = y;
    }
}

// ---------------- launch ----------------
extern "C" void kernel_launch(void* const* d_in, const int* in_sizes, int n_in,
                              void* d_out, int out_size) {
    const float* top  = (const float*)d_in[0];
    const float* bot  = (const float*)d_in[1];
    const float* wt   = (const float*)d_in[2];
    const float* bt   = (const float*)d_in[3];
    const float* wb   = (const float*)d_in[4];
    const float* bb   = (const float*)d_in[5];
    const float* s_w1 = (const float*)d_in[6];
    const float* s_b1 = (const float*)d_in[7];
    const float* s_w2 = (const float*)d_in[8];
    const float* s_b2 = (const float*)d_in[9];
    const float* s_wo = (const float*)d_in[10];
    const float* s_bo = (const float*)d_in[11];
    const float* c_wq = (const float*)d_in[12];
    const float* c_bq = (const float*)d_in[13];
    const float* c_wk = (const float*)d_in[14];
    const float* c_bk = (const float*)d_in[15];
    const float* c_wo = (const float*)d_in[16];
    const float* c_bo = (const float*)d_in[17];
    const float* f_w  = (const float*)d_in[18];
    const float* f_b  = (const float*)d_in[19];
    float* out = (float*)d_out;

    fold_qk<<<512, 256>>>(wt, wb, s_w1, s_w2, c_wq, c_wk);
    fold_out<<<256, 256>>>(f_w, s_wo, c_wo);
    fold_bias<<<1, 512>>>(bt, bb, s_b1, s_b2, c_bq, c_bk, f_w, s_bo, c_bo, f_b,
                          s_w1, s_w2, c_wq, c_wk);
    qk_gemm<<<dim3(64, 4, 8), 256>>>(top, bot);
    spatial_passA<<<dim3(64, 8), 256>>>();
    spatial_passB<<<dim3(64, 8), 256>>>();
    chan_gram<<<dim3(8, 8), 256>>>();
    chan_softmax<<<dim3(64, 8), 64>>>();
    chan_out<<<dim3(16, 8), 256>>>();
    final_gemm<<<dim3(64, 8, 8), 256>>>(out);
}

// round 2
// speedup vs baseline: 1.0220x; 1.0220x over previous
#include <cuda_runtime.h>
#include <cuda_bf16.h>
#include <math.h>

// Problem constants
#define BB 8
#define CC 512
#define CH 256
#define RR 64
#define NN 4096   // H*W = 64*64

typedef unsigned long long ull;

// ---------------- f32x2 packed helpers ----------------
__device__ __forceinline__ ull dup2(float x) {
    ull r; asm("mov.b64 %0, {%1, %1};" : "=l"(r) : "f"(x)); return r;
}
__device__ __forceinline__ void unpack2(ull v, float& x, float& y) {
    asm("mov.b64 {%0, %1}, %2;" : "=f"(x), "=f"(y) : "l"(v));
}
__device__ __forceinline__ void fma2(ull& d, ull a, ull b) {
    asm("fma.rn.f32x2 %0, %1, %2, %0;" : "+l"(d) : "l"(a), "l"(b));
}

// ---------------- scratch (device globals; no allocation) ----------------
__device__ float g_Wtop[256 * 512];
__device__ float g_Wbot[256 * 512];
__device__ float g_bqk[256];
__device__ float g_Wc[512 * 128];
__device__ float g_bout[512];
__device__ float g_qk[(size_t)BB * 256 * NN];          // rows: 0-63 q1, 64-127 k1, 128-191 q2, 192-255 k2
__device__ float g_E[(size_t)BB * NN * NN];            // exp(S), 536 MB
__device__ float g_Zinv[BB * NN];
__device__ float g_Gp[BB * 8 * 64 * 64];               // channel Gram partials (8 n-chunks)
__device__ float g_A[BB * 64 * 64];                    // channel attention
__device__ float g_osc[(size_t)BB * 128 * NN];         // rows 0-63 out_s, 64-127 out_c

// ---------------- weight folding ----------------
__global__ void fold_qk(const float* __restrict__ wt, const float* __restrict__ wb,
                        const float* __restrict__ sw1, const float* __restrict__ sw2,
                        const float* __restrict__ cwq, const float* __restrict__ cwk) {
    int idx = blockIdx.x * blockDim.x + threadIdx.x;   // 0..131071
    int j = idx >> 9, c = idx & 511;
    const float* wrow; int uoff;
    if (j < 64)       { wrow = sw1 + j * 256;        uoff = 0;   }
    else if (j < 128) { wrow = sw2 + (j - 64) * 256; uoff = 0;   }
    else if (j < 192) { wrow = cwq + (j - 128) * 256; uoff = 256; }
    else              { wrow = cwk + (j - 192) * 256; uoff = 256; }
    float at = 0.f, ab = 0.f;
    #pragma unroll 8
    for (int u = 0; u < 256; ++u) {
        float w = wrow[u];
        at = fmaf(w, wt[(uoff + u) * 512 + c], at);
        ab = fmaf(w, wb[(uoff + u) * 512 + c], ab);
    }
    g_Wtop[idx] = at;
    g_Wbot[idx] = ab;
}

__global__ void fold_out(const float* __restrict__ fw, const float* __restrict__ swo,
                         const float* __restrict__ cwo) {
    int idx = blockIdx.x * blockDim.x + threadIdx.x;   // 0..65535
    int o = idx >> 7, t = idx & 127;
    float acc = 0.f;
    if (t < 64) {
        #pragma unroll 8
        for (int u = 0; u < 256; ++u)
            acc = fmaf(fw[o * 512 + u], swo[u * 64 + t], acc);
    } else {
        int r = t - 64;
        #pragma unroll 8
        for (int u = 0; u < 256; ++u)
            acc = fmaf(fw[o * 512 + 256 + u], cwo[u * 64 + r], acc);
    }
    g_Wc[idx] = acc;
}

__global__ void fold_bias(const float* __restrict__ bt, const float* __restrict__ bb,
                          const float* __restrict__ sb1, const float* __restrict__ sb2,
                          const float* __restrict__ cbq, const float* __restrict__ cbk,
                          const float* __restrict__ fw,  const float* __restrict__ sbo,
                          const float* __restrict__ cbo, const float* __restrict__ fb,
                          const float* __restrict__ sw1, const float* __restrict__ sw2,
                          const float* __restrict__ cwq, const float* __restrict__ cwk) {
    int t = threadIdx.x;   // blockDim = 512
    if (t < 256) {
        const float* wrow; int uoff; float ob;
        int j = t;
        if (j < 64)       { wrow = sw1 + j * 256;        uoff = 0;   ob = sb1[j];       }
        else if (j < 128) { wrow = sw2 + (j - 64) * 256; uoff = 0;   ob = sb2[j - 64];  }
        else if (j < 192) { wrow = cwq + (j - 128) * 256; uoff = 256; ob = cbq[j - 128]; }
        else              { wrow = cwk + (j - 192) * 256; uoff = 256; ob = cbk[j - 192]; }
        float s = ob;
        for (int u = 0; u < 256; ++u)
            s = fmaf(wrow[u], bt[uoff + u] + bb[uoff + u], s);
        g_bqk[j] = s;
    }
    float s2 = fb[t];
    for (int u = 0; u < 256; ++u) {
        s2 = fmaf(fw[t * 512 + u],       sbo[u], s2);
        s2 = fmaf(fw[t * 512 + 256 + u], cbo[u], s2);
    }
    g_bout[t] = s2;
}

// ---------------- qk GEMM: qk[b][j][p] = Wtop[j]·top[b][:,p] + Wbot[j]·bot[b][:,p] + bqk[j]
__global__ void __launch_bounds__(256) qk_gemm(const float* __restrict__ top,
                                               const float* __restrict__ bot) {
    int b = blockIdx.z;
    int j0 = blockIdx.y * 64;
    int p0 = blockIdx.x * 64;
    int tx = threadIdx.x & 15, ty = threadIdx.x >> 4;
    __shared__ __align__(16) float As[16][68];
    __shared__ __align__(16) float Bs[16][64];
    ull acc2[4][2] = {};
    int ldA_j = threadIdx.x >> 2;
    int ldA_c = (threadIdx.x & 3) * 4;
    int ldB_c = threadIdx.x >> 4;
    int ldB_p = (threadIdx.x & 15) * 4;
    for (int step = 0; step < 64; ++step) {
        const float* W = (step < 32) ? g_Wtop : g_Wbot;
        const float* X = (step < 32) ? top : bot;
        int c0 = (step & 31) * 16;
        __syncthreads();
        {
            float4 v = *(const float4*)&W[(j0 + ldA_j) * 512 + c0 + ldA_c];
            As[ldA_c + 0][ldA_j] = v.x;
            As[ldA_c + 1][ldA_j] = v.y;
            As[ldA_c + 2][ldA_j] = v.z;
            As[ldA_c + 3][ldA_j] = v.w;
            float4 u = *(const float4*)&X[((size_t)(b * 512 + c0 + ldB_c)) * NN + p0 + ldB_p];
            *(float4*)&Bs[ldB_c][ldB_p] = u;
        }
        __syncthreads();
        #pragma unroll
        for (int c = 0; c < 16; ++c) {
            float4 a4 = *(float4*)&As[c][ty * 4];
            const ull* bp = (const ull*)&Bs[c][0];
            ull b0 = bp[tx * 2], b1 = bp[tx * 2 + 1];
            float aa[4] = {a4.x, a4.y, a4.z, a4.w};
            #pragma unroll
            for (int i = 0; i < 4; ++i) {
                ull ad = dup2(aa[i]);
                fma2(acc2[i][0], ad, b0);
                fma2(acc2[i][1], ad, b1);
            }
        }
    }
    #pragma unroll
    for (int i = 0; i < 4; ++i) {
        int j = j0 + ty * 4 + i;
        float bias = g_bqk[j];
        float o0, o1, o2, o3;
        unpack2(acc2[i][0], o0, o1);
        unpack2(acc2[i][1], o2, o3);
        float4 o;
        o.x = o0 + bias; o.y = o1 + bias; o.z = o2 + bias; o.w = o3 + bias;
        *(float4*)&g_qk[((size_t)(b * 256 + j)) * NN + p0 + tx * 4] = o;
    }
}

// ---------------- spatial pass A: E = exp(Q^T K), Zinv[n] = 1/sum_m E[n][m]
__global__ void __launch_bounds__(256) spatial_passA() {
    int b = blockIdx.y;
    int n0 = blockIdx.x * 64;
    int tx = threadIdx.x & 15, ty = threadIdx.x >> 4;
    __shared__ __align__(16) float Qs[64][68];   // [r][n]
    __shared__ __align__(16) float Ks[64][68];   // [r][m]
    int ld_r = threadIdx.x >> 4;
    int ld_c = (threadIdx.x & 15) * 4;
    #pragma unroll
    for (int k = 0; k < 4; ++k) {
        int r = ld_r + k * 16;
        float4 v = *(const float4*)&g_qk[((size_t)(b * 256 + r)) * NN + n0 + ld_c];
        *(float4*)&Qs[r][ld_c] = v;
    }
    float zacc[4] = {0.f, 0.f, 0.f, 0.f};
    size_t ebase = ((size_t)b) << 24;
    for (int mt = 0; mt < 64; ++mt) {
        int m0 = mt * 64;
        __syncthreads();
        #pragma unroll
        for (int k = 0; k < 4; ++k) {
            int r = ld_r + k * 16;
            float4 v = *(const float4*)&g_qk[((size_t)(b * 256 + 64 + r)) * NN + m0 + ld_c];
            *(float4*)&Ks[r][ld_c] = v;
        }
        __syncthreads();
        ull s2[4][2] = {};
        #pragma unroll 8
        for (int r = 0; r < 64; ++r) {
            float4 q4 = *(float4*)&Qs[r][ty * 4];
            const ull* kp = (const ull*)&Ks[r][0];
            ull k0 = kp[tx * 2], k1 = kp[tx * 2 + 1];
            float qa[4] = {q4.x, q4.y, q4.z, q4.w};
            #pragma unroll
            for (int i = 0; i < 4; ++i) {
                ull qd = dup2(qa[i]);
                fma2(s2[i][0], qd, k0);
                fma2(s2[i][1], qd, k1);
            }
        }
        #pragma unroll
        for (int i = 0; i < 4; ++i) {
            int n = n0 + ty * 4 + i;
            float s0, s1, s2v, s3;
            unpack2(s2[i][0], s0, s1);
            unpack2(s2[i][1], s2v, s3);
            float4 e;
            e.x = __expf(s0); e.y = __expf(s1);
            e.z = __expf(s2v); e.w = __expf(s3);
            *(float4*)&g_E[ebase + (((size_t)n) << 12) + m0 + tx * 4] = e;
            zacc[i] += e.x + e.y + e.z + e.w;
        }
    }
    __syncthreads();
    float* zs = &Qs[0][0];
    #pragma unroll
    for (int i = 0; i < 4; ++i)
        zs[(ty * 4 + i) * 16 + tx] = zacc[i];
    __syncthreads();
    if (threadIdx.x < 64) {
        float s = 0.f;
        #pragma unroll
        for (int t = 0; t < 16; ++t) s += zs[threadIdx.x * 16 + t];
        g_Zinv[b * NN + n0 + threadIdx.x] = 1.0f / s;
    }
}

// ---------------- spatial pass B: out_s[r][m] = sum_n (K[r][n]*Zinv[n]) * E[n][m]
__global__ void __launch_bounds__(256) spatial_passB() {
    int b = blockIdx.y;
    int m0 = blockIdx.x * 64;
    int tx = threadIdx.x & 15, ty = threadIdx.x >> 4;
    __shared__ __align__(16) float Ks[64][68];   // [n][r]
    __shared__ __align__(16) float Es[64][68];   // [n][m]
    ull acc2[4][2] = {};
    int ld_r = threadIdx.x >> 4;
    int ld_c = (threadIdx.x & 15) * 4;
    size_t ebase = ((size_t)b) << 24;
    for (int nt = 0; nt < 64; ++nt) {
        int n0 = nt * 64;
        __syncthreads();
        #pragma unroll
        for (int k = 0; k < 4; ++k) {
            int r = ld_r + k * 16;
            float4 v = *(const float4*)&g_qk[((size_t)(b * 256 + 64 + r)) * NN + n0 + ld_c];
            float4 z = *(const float4*)&g_Zinv[b * NN + n0 + ld_c];
            Ks[ld_c + 0][r] = v.x * z.x;
            Ks[ld_c + 1][r] = v.y * z.y;
            Ks[ld_c + 2][r] = v.z * z.z;
            Ks[ld_c + 3][r] = v.w * z.w;
            int n = ld_r + k * 16;
            float4 e = *(const float4*)&g_E[ebase + (((size_t)(n0 + n)) << 12) + m0 + ld_c];
            *(float4*)&Es[n][ld_c] = e;
        }
        __syncthreads();
        #pragma unroll 8
        for (int n = 0; n < 64; ++n) {
            float4 k4 = *(float4*)&Ks[n][ty * 4];
            const ull* ep = (const ull*)&Es[n][0];
            ull e0 = ep[tx * 2], e1 = ep[tx * 2 + 1];
            float ka[4] = {k4.x, k4.y, k4.z, k4.w};
            #pragma unroll
            for (int i = 0; i < 4; ++i) {
                ull kd = dup2(ka[i]);
                fma2(acc2[i][0], kd, e0);
                fma2(acc2[i][1], kd, e1);
            }
        }
    }
    #pragma unroll
    for (int i = 0; i < 4; ++i) {
        float o0, o1, o2, o3;
        unpack2(acc2[i][0], o0, o1);
        unpack2(acc2[i][1], o2, o3);
        float4 o;
        o.x = o0; o.y = o1; o.z = o2; o.w = o3;
        *(float4*)&g_osc[((size_t)(b * 128 + ty * 4 + i)) * NN + m0 + tx * 4] = o;
    }
}

// ---------------- channel Gram partials
__global__ void __launch_bounds__(256) chan_gram() {
    int b = blockIdx.y;
    int chunk = blockIdx.x;             // 8 chunks of 512 n each
    int tx = threadIdx.x & 15, ty = threadIdx.x >> 4;
    __shared__ __align__(16) float Qc[64][68];        // [n][r]
    __shared__ __align__(16) float Kc[64][68];        // [n][s]
    ull acc2[4][2] = {};
    int ld_r = threadIdx.x >> 4;
    int ld_c = (threadIdx.x & 15) * 4;
    for (int sub = 0; sub < 8; ++sub) {
        int n0 = chunk * 512 + sub * 64;
        __syncthreads();
        #pragma unroll
        for (int k = 0; k < 4; ++k) {
            int r = ld_r + k * 16;
            float4 q = *(const float4*)&g_qk[((size_t)(b * 256 + 128 + r)) * NN + n0 + ld_c];
            Qc[ld_c + 0][r] = q.x; Qc[ld_c + 1][r] = q.y;
            Qc[ld_c + 2][r] = q.z; Qc[ld_c + 3][r] = q.w;
            float4 w = *(const float4*)&g_qk[((size_t)(b * 256 + 192 + r)) * NN + n0 + ld_c];
            Kc[ld_c + 0][r] = w.x; Kc[ld_c + 1][r] = w.y;
            Kc[ld_c + 2][r] = w.z; Kc[ld_c + 3][r] = w.w;
        }
        __syncthreads();
        #pragma unroll 8
        for (int n = 0; n < 64; ++n) {
            float4 q4 = *(float4*)&Qc[n][ty * 4];
            const ull* kp = (const ull*)&Kc[n][0];
            ull k0 = kp[tx * 2], k1 = kp[tx * 2 + 1];
            float qa[4] = {q4.x, q4.y, q4.z, q4.w};
            #pragma unroll
            for (int i = 0; i < 4; ++i) {
                ull qd = dup2(qa[i]);
                fma2(acc2[i][0], qd, k0);
                fma2(acc2[i][1], qd, k1);
            }
        }
    }
    #pragma unroll
    for (int i = 0; i < 4; ++i) {
        float o0, o1, o2, o3;
        unpack2(acc2[i][0], o0, o1);
        unpack2(acc2[i][1], o2, o3);
        float* dst = &g_Gp[(b * 8 + chunk) * 4096 + (ty * 4 + i) * 64 + tx * 4];
        dst[0] = o0; dst[1] = o1; dst[2] = o2; dst[3] = o3;
    }
}

// ---------------- channel softmax
__global__ void chan_softmax() {
    int r = blockIdx.x;
    int b = blockIdx.y;
    int s = threadIdx.x;   // 64 threads
    __shared__ float red[64];
    float v = 0.f;
    #pragma unroll
    for (int ch = 0; ch < 8; ++ch)
        v += g_Gp[(b * 8 + ch) * 4096 + r * 64 + s];
    red[s] = v;
    __syncthreads();
    for (int off = 32; off >= 1; off >>= 1) {
        if (s < off) red[s] = fmaxf(red[s], red[s + off]);
        __syncthreads();
    }
    float mx = red[0];
    __syncthreads();
    float e = __expf(v - mx);
    red[s] = e;
    __syncthreads();
    for (int off = 32; off >= 1; off >>= 1) {
        if (s < off) red[s] += red[s + off];
        __syncthreads();
    }
    g_A[b * 4096 + r * 64 + s] = e / red[0];
}

// ---------------- channel output: out_c[r][p] = sum_s A[r][s] * k2[s][p]
__global__ void __launch_bounds__(256) chan_out() {
    int b = blockIdx.y;
    int p = blockIdx.x * 256 + threadIdx.x;
    __shared__ __align__(16) float As[64][64];
    #pragma unroll
    for (int k = 0; k < 16; ++k)
        (&As[0][0])[threadIdx.x + k * 256] = g_A[b * 4096 + threadIdx.x + k * 256];
    __syncthreads();
    float kreg[64];
    #pragma unroll
    for (int s = 0; s < 64; ++s)
        kreg[s] = g_qk[((size_t)(b * 256 + 192 + s)) * NN + p];
    ull kp2[32];
    #pragma unroll
    for (int s = 0; s < 32; ++s) {
        ull r; asm("mov.b64 %0, {%1, %2};" : "=l"(r) : "f"(kreg[2 * s]), "f"(kreg[2 * s + 1]));
        kp2[s] = r;
    }
    #pragma unroll 2
    for (int r = 0; r < 64; ++r) {
        ull acc = 0;
        const ull* arow = (const ull*)&As[r][0];
        #pragma unroll
        for (int s = 0; s < 32; ++s)
            fma2(acc, arow[s], kp2[s]);
        float lo, hi;
        unpack2(acc, lo, hi);
        g_osc[((size_t)(b * 128 + 64 + r)) * NN + p] = lo + hi;
    }
}

// ---------------- final GEMM: y[b][o][p] = sum_t Wc[o][t] * osc[b][t][p] + bout[o]
__global__ void __launch_bounds__(256) final_gemm(float* __restrict__ out) {
    int b = blockIdx.z;
    int o0 = blockIdx.y * 64;
    int p0 = blockIdx.x * 64;
    int tx = threadIdx.x & 15, ty = threadIdx.x >> 4;
    __shared__ __align__(16) float Ws[16][68];   // [t][o]
    __shared__ __align__(16) float Xs[16][64];   // [t][p]
    ull acc2[4][2] = {};
    int ldW_o = threadIdx.x >> 2;
    int ldW_t = (threadIdx.x & 3) * 4;
    int ldX_t = threadIdx.x >> 4;
    int ldX_p = (threadIdx.x & 15) * 4;
    for (int kt = 0; kt < 8; ++kt) {
        int t0 = kt * 16;
        __syncthreads();
        {
            float4 v = *(const float4*)&g_Wc[(o0 + ldW_o) * 128 + t0 + ldW_t];
            Ws[ldW_t + 0][ldW_o] = v.x;
            Ws[ldW_t + 1][ldW_o] = v.y;
            Ws[ldW_t + 2][ldW_o] = v.z;
            Ws[ldW_t + 3][ldW_o] = v.w;
            float4 u = *(const float4*)&g_osc[((size_t)(b * 128 + t0 + ldX_t)) * NN + p0 + ldX_p];
            *(float4*)&Xs[ldX_t][ldX_p] = u;
        }
        __syncthreads();
        #pragma unroll
        for (int t = 0; t < 16; ++t) {
            float4 w4 = *(float4*)&Ws[t][ty * 4];
            const ull* xp = (const ull*)&Xs[t][0];
            ull x0 = xp[tx * 2], x1 = xp[tx * 2 + 1];
            float wa[4] = {w4.x, w4.y, w4.z, w4.w};
            #pragma unroll
            for (int i = 0; i < 4; ++i) {
                ull wd = dup2(wa[i]);
                fma2(acc2[i][0], wd, x0);
                fma2(acc2[i][1], wd, x1);
            }
        }
    }
    #pragma unroll
    for (int i = 0; i < 4; ++i) {
        int o = o0 + ty * 4 + i;
        float bias = g_bout[o];
        float y0, y1, y2, y3;
        unpack2(acc2[i][0], y0, y1);
        unpack2(acc2[i][1], y2, y3);
        float4 y;
        y.x = y0 + bias; y.y = y1 + bias; y.z = y2 + bias; y.w = y3 + bias;
        *(float4*)&out[((size_t)(b * 512 + o)) * NN + p0 + tx * 4] = y;
    }
}

// ---------------- launch ----------------
extern "C" void kernel_launch(void* const* d_in, const int* in_sizes, int n_in,
                              void* d_out, int out_size) {
    const float* top  = (const float*)d_in[0];
    const float* bot  = (const float*)d_in[1];
    const float* wt   = (const float*)d_in[2];
    const float* bt   = (const float*)d_in[3];
    const float* wb   = (const float*)d_in[4];
    const float* bb   = (const float*)d_in[5];
    const float* s_w1 = (const float*)d_in[6];
    const float* s_b1 = (const float*)d_in[7];
    const float* s_w2 = (const float*)d_in[8];
    const float* s_b2 = (const float*)d_in[9];
    const float* s_wo = (const float*)d_in[10];
    const float* s_bo = (const float*)d_in[11];
    const float* c_wq = (const float*)d_in[12];
    const float* c_bq = (const float*)d_in[13];
    const float* c_wk = (const float*)d_in[14];
    const float* c_bk = (const float*)d_in[15];
    const float* c_wo = (const float*)d_in[16];
    const float* c_bo = (const float*)d_in[17];
    const float* f_w  = (const float*)d_in[18];
    const float* f_b  = (const float*)d_in[19];
    float* out = (float*)d_out;

    fold_qk<<<512, 256>>>(wt, wb, s_w1, s_w2, c_wq, c_wk);
    fold_out<<<256, 256>>>(f_w, s_wo, c_wo);
    fold_bias<<<1, 512>>>(bt, bb, s_b1, s_b2, c_bq, c_bk, f_w, s_bo, c_bo, f_b,
                          s_w1, s_w2, c_wq, c_wk);
    qk_gemm<<<dim3(64, 4, 8), 256>>>(top, bot);
    spatial_passA<<<dim3(64, 8), 256>>>();
    spatial_passB<<<dim3(64, 8), 256>>>();
    chan_gram<<<dim3(8, 8), 256>>>();
    chan_softmax<<<dim3(64, 8), 64>>>();
    chan_out<<<dim3(16, 8), 256>>>();
    final_gemm<<<dim3(64, 8, 8), 256>>>(out);
}

// round 3
// speedup vs baseline: 1.1056x; 1.0818x over previous
#include <cuda_runtime.h>
#include <cuda_bf16.h>
#include <math.h>

#define BB 8
#define NN 4096

typedef unsigned long long ull;

__device__ __forceinline__ ull dup2(float x) {
    ull r; asm("mov.b64 %0, {%1, %1};" : "=l"(r) : "f"(x)); return r;
}
__device__ __forceinline__ void unpack2(ull v, float& x, float& y) {
    asm("mov.b64 {%0, %1}, %2;" : "=f"(x), "=f"(y) : "l"(v));
}
__device__ __forceinline__ void fma2(ull& d, ull a, ull b) {
    asm("fma.rn.f32x2 %0, %1, %2, %0;" : "+l"(d) : "l"(a), "l"(b));
}

// ---------------- scratch ----------------
__device__ float g_Wtop[256 * 512];
__device__ float g_Wbot[256 * 512];
__device__ float g_bqk[256];
__device__ float g_Wc[512 * 128];
__device__ float g_bout[512];
__device__ float g_qk[(size_t)BB * 256 * NN];   // rows: 0-63 q1, 64-127 k1, 128-191 q2, 192-255 k2
__device__ float g_E[(size_t)BB * NN * NN];     // exp(S)
__device__ float g_Zinv[BB * NN];
__device__ float g_Gp[BB * 32 * 64 * 64];
__device__ float g_A[BB * 64 * 64];
__device__ float g_osc[(size_t)BB * 128 * NN];  // rows 0-63 out_s, 64-127 out_c

// ---------------- weight folding ----------------
__global__ void fold_qk(const float* __restrict__ wt, const float* __restrict__ wb,
                        const float* __restrict__ sw1, const float* __restrict__ sw2,
                        const float* __restrict__ cwq, const float* __restrict__ cwk) {
    int idx = blockIdx.x * blockDim.x + threadIdx.x;
    int j = idx >> 9, c = idx & 511;
    const float* wrow; int uoff;
    if (j < 64)       { wrow = sw1 + j * 256;        uoff = 0;   }
    else if (j < 128) { wrow = sw2 + (j - 64) * 256; uoff = 0;   }
    else if (j < 192) { wrow = cwq + (j - 128) * 256; uoff = 256; }
    else              { wrow = cwk + (j - 192) * 256; uoff = 256; }
    float at = 0.f, ab = 0.f;
    #pragma unroll 8
    for (int u = 0; u < 256; ++u) {
        float w = wrow[u];
        at = fmaf(w, wt[(uoff + u) * 512 + c], at);
        ab = fmaf(w, wb[(uoff + u) * 512 + c], ab);
    }
    g_Wtop[idx] = at;
    g_Wbot[idx] = ab;
}

__global__ void fold_out(const float* __restrict__ fw, const float* __restrict__ swo,
                         const float* __restrict__ cwo) {
    int idx = blockIdx.x * blockDim.x + threadIdx.x;
    int o = idx >> 7, t = idx & 127;
    float acc = 0.f;
    if (t < 64) {
        #pragma unroll 8
        for (int u = 0; u < 256; ++u)
            acc = fmaf(fw[o * 512 + u], swo[u * 64 + t], acc);
    } else {
        int r = t - 64;
        #pragma unroll 8
        for (int u = 0; u < 256; ++u)
            acc = fmaf(fw[o * 512 + 256 + u], cwo[u * 64 + r], acc);
    }
    g_Wc[idx] = acc;
}

__global__ void fold_bias(const float* __restrict__ bt, const float* __restrict__ bb,
                          const float* __restrict__ sb1, const float* __restrict__ sb2,
                          const float* __restrict__ cbq, const float* __restrict__ cbk,
                          const float* __restrict__ fw,  const float* __restrict__ sbo,
                          const float* __restrict__ cbo, const float* __restrict__ fb,
                          const float* __restrict__ sw1, const float* __restrict__ sw2,
                          const float* __restrict__ cwq, const float* __restrict__ cwk) {
    int t = threadIdx.x;   // 512
    if (t < 256) {
        const float* wrow; int uoff; float ob;
        int j = t;
        if (j < 64)       { wrow = sw1 + j * 256;        uoff = 0;   ob = sb1[j];       }
        else if (j < 128) { wrow = sw2 + (j - 64) * 256; uoff = 0;   ob = sb2[j - 64];  }
        else if (j < 192) { wrow = cwq + (j - 128) * 256; uoff = 256; ob = cbq[j - 128]; }
        else              { wrow = cwk + (j - 192) * 256; uoff = 256; ob = cbk[j - 192]; }
        float s = ob;
        for (int u = 0; u < 256; ++u)
            s = fmaf(wrow[u], bt[uoff + u] + bb[uoff + u], s);
        g_bqk[j] = s;
    }
    float s2 = fb[t];
    for (int u = 0; u < 256; ++u) {
        s2 = fmaf(fw[t * 512 + u],       sbo[u], s2);
        s2 = fmaf(fw[t * 512 + 256 + u], cbo[u], s2);
    }
    g_bout[t] = s2;
}

// ---------------- qk GEMM (128x128 tile, 8x8/thread) ----------------
__global__ void __launch_bounds__(256, 2) qk_gemm(const float* __restrict__ top,
                                                  const float* __restrict__ bot) {
    int b = blockIdx.z;
    int j0 = blockIdx.y * 128;
    int p0 = blockIdx.x * 128;
    int t = threadIdx.x, tx = t & 15, ty = t >> 4;
    __shared__ __align__(16) float As[16][132];   // [c][j]
    __shared__ __align__(16) float Bs[16][128];   // [c][p]
    ull acc2[8][4] = {};
    for (int step = 0; step < 64; ++step) {
        const float* W = (step < 32) ? g_Wtop : g_Wbot;
        const float* X = (step < 32) ? top : bot;
        int c0 = (step & 31) * 16;
        __syncthreads();
        #pragma unroll
        for (int i = 0; i < 2; ++i) {
            int l = t + i * 256;
            int jA = l & 127, cq = l >> 7;
            float4 v = *(const float4*)&W[(size_t)(j0 + jA) * 512 + c0 + cq * 4];
            As[cq * 4 + 0][jA] = v.x;
            As[cq * 4 + 1][jA] = v.y;
            As[cq * 4 + 2][jA] = v.z;
            As[cq * 4 + 3][jA] = v.w;
            int cB = l >> 5, p4 = (l & 31) * 4;
            *(float4*)&Bs[cB][p4] =
                *(const float4*)&X[((size_t)(b * 512 + c0 + cB)) * NN + p0 + p4];
        }
        __syncthreads();
        #pragma unroll
        for (int c = 0; c < 16; ++c) {
            ulonglong2 a0 = *(const ulonglong2*)&As[c][ty * 8];
            ulonglong2 a1 = *(const ulonglong2*)&As[c][ty * 8 + 4];
            ulonglong2 b0 = *(const ulonglong2*)&Bs[c][tx * 8];
            ulonglong2 b1 = *(const ulonglong2*)&Bs[c][tx * 8 + 4];
            float af[8];
            unpack2(a0.x, af[0], af[1]); unpack2(a0.y, af[2], af[3]);
            unpack2(a1.x, af[4], af[5]); unpack2(a1.y, af[6], af[7]);
            #pragma unroll
            for (int i = 0; i < 8; ++i) {
                ull ad = dup2(af[i]);
                fma2(acc2[i][0], ad, b0.x);
                fma2(acc2[i][1], ad, b0.y);
                fma2(acc2[i][2], ad, b1.x);
                fma2(acc2[i][3], ad, b1.y);
            }
        }
    }
    #pragma unroll
    for (int i = 0; i < 8; ++i) {
        int j = j0 + ty * 8 + i;
        float bias = g_bqk[j];
        float o[8];
        unpack2(acc2[i][0], o[0], o[1]); unpack2(acc2[i][1], o[2], o[3]);
        unpack2(acc2[i][2], o[4], o[5]); unpack2(acc2[i][3], o[6], o[7]);
        float4 v0 = {o[0] + bias, o[1] + bias, o[2] + bias, o[3] + bias};
        float4 v1 = {o[4] + bias, o[5] + bias, o[6] + bias, o[7] + bias};
        size_t base = ((size_t)(b * 256 + j)) * NN + p0 + tx * 8;
        *(float4*)&g_qk[base] = v0;
        *(float4*)&g_qk[base + 4] = v1;
    }
}

// ---------------- spatial pass A: E = exp(Q^T K), Zinv ----------------
__global__ void __launch_bounds__(256, 2) spatial_passA() {
    int b = blockIdx.y;
    int n0 = blockIdx.x * 128;
    int t = threadIdx.x, tx = t & 15, ty = t >> 4;
    extern __shared__ __align__(16) float dsm[];
    float (*Qs)[128] = (float(*)[128])dsm;            // [r][n]
    float (*Ks)[128] = (float(*)[128])(dsm + 64 * 128); // [r][m]
    #pragma unroll
    for (int i = 0; i < 8; ++i) {
        int l = t + i * 256;
        int r = l >> 5, c4 = (l & 31) * 4;
        *(float4*)&Qs[r][c4] =
            *(const float4*)&g_qk[((size_t)(b * 256 + r)) * NN + n0 + c4];
    }
    float zacc[8] = {};
    size_t ebase = ((size_t)b) << 24;
    for (int mt = 0; mt < 32; ++mt) {
        int m0 = mt * 128;
        __syncthreads();
        #pragma unroll
        for (int i = 0; i < 8; ++i) {
            int l = t + i * 256;
            int r = l >> 5, c4 = (l & 31) * 4;
            *(float4*)&Ks[r][c4] =
                *(const float4*)&g_qk[((size_t)(b * 256 + 64 + r)) * NN + m0 + c4];
        }
        __syncthreads();
        ull s2[8][4] = {};
        #pragma unroll 8
        for (int r = 0; r < 64; ++r) {
            ulonglong2 a0 = *(const ulonglong2*)&Qs[r][ty * 8];
            ulonglong2 a1 = *(const ulonglong2*)&Qs[r][ty * 8 + 4];
            ulonglong2 b0 = *(const ulonglong2*)&Ks[r][tx * 8];
            ulonglong2 b1 = *(const ulonglong2*)&Ks[r][tx * 8 + 4];
            float af[8];
            unpack2(a0.x, af[0], af[1]); unpack2(a0.y, af[2], af[3]);
            unpack2(a1.x, af[4], af[5]); unpack2(a1.y, af[6], af[7]);
            #pragma unroll
            for (int i = 0; i < 8; ++i) {
                ull ad = dup2(af[i]);
                fma2(s2[i][0], ad, b0.x);
                fma2(s2[i][1], ad, b0.y);
                fma2(s2[i][2], ad, b1.x);
                fma2(s2[i][3], ad, b1.y);
            }
        }
        #pragma unroll
        for (int i = 0; i < 8; ++i) {
            int n = n0 + ty * 8 + i;
            float o[8];
            unpack2(s2[i][0], o[0], o[1]); unpack2(s2[i][1], o[2], o[3]);
            unpack2(s2[i][2], o[4], o[5]); unpack2(s2[i][3], o[6], o[7]);
            float e[8];
            #pragma unroll
            for (int k = 0; k < 8; ++k) e[k] = __expf(o[k]);
            zacc[i] += (e[0] + e[1]) + (e[2] + e[3]) + (e[4] + e[5]) + (e[6] + e[7]);
            float4 v0 = {e[0], e[1], e[2], e[3]};
            float4 v1 = {e[4], e[5], e[6], e[7]};
            size_t base = ebase + (((size_t)n) << 12) + m0 + tx * 8;
            *(float4*)&g_E[base] = v0;
            *(float4*)&g_E[base + 4] = v1;
        }
    }
    __syncthreads();
    float* zb = dsm + 64 * 128;   // reuse Ks
    #pragma unroll
    for (int i = 0; i < 8; ++i)
        zb[(ty * 8 + i) * 16 + tx] = zacc[i];
    __syncthreads();
    if (t < 128) {
        float s = 0.f;
        #pragma unroll
        for (int k = 0; k < 16; ++k) s += zb[t * 16 + k];
        g_Zinv[b * NN + n0 + t] = 1.0f / s;
    }
}

// ---------------- spatial pass B: out_s = (K*Zinv) @ E ----------------
__global__ void __launch_bounds__(256, 2) spatial_passB() {
    int b = blockIdx.y;
    int m0 = blockIdx.x * 128;
    int t = threadIdx.x, tx = t & 31, ty = t >> 5;   // tx: 4 m, ty: 8 r
    extern __shared__ __align__(16) float dsm[];
    float (*Ks)[64] = (float(*)[64])dsm;               // [n][r] (K*Zinv transposed)
    float (*Es)[128] = (float(*)[128])(dsm + 64 * 64); // [n][m]
    ull acc2[4][4] = {};   // r-pairs x 4 m
    size_t ebase = ((size_t)b) << 24;
    for (int nt = 0; nt < 64; ++nt) {
        int n0 = nt * 64;
        __syncthreads();
        #pragma unroll
        for (int i = 0; i < 4; ++i) {
            int l = t + i * 256;
            int r = l & 63, n4 = (l >> 6) * 4;
            float4 v = *(const float4*)&g_qk[((size_t)(b * 256 + 64 + r)) * NN + n0 + n4];
            float4 z = *(const float4*)&g_Zinv[b * NN + n0 + n4];
            Ks[n4 + 0][r] = v.x * z.x;
            Ks[n4 + 1][r] = v.y * z.y;
            Ks[n4 + 2][r] = v.z * z.z;
            Ks[n4 + 3][r] = v.w * z.w;
        }
        #pragma unroll
        for (int i = 0; i < 8; ++i) {
            int l = t + i * 256;
            int n = l >> 5, m4 = (l & 31) * 4;
            *(float4*)&Es[n][m4] =
                *(const float4*)&g_E[ebase + (((size_t)(n0 + n)) << 12) + m0 + m4];
        }
        __syncthreads();
        #pragma unroll 8
        for (int n = 0; n < 64; ++n) {
            ulonglong2 a0 = *(const ulonglong2*)&Ks[n][ty * 8];
            ulonglong2 a1 = *(const ulonglong2*)&Ks[n][ty * 8 + 4];
            float4 bv = *(const float4*)&Es[n][tx * 4];
            ull bd0 = dup2(bv.x), bd1 = dup2(bv.y), bd2 = dup2(bv.z), bd3 = dup2(bv.w);
            fma2(acc2[0][0], a0.x, bd0); fma2(acc2[0][1], a0.x, bd1);
            fma2(acc2[0][2], a0.x, bd2); fma2(acc2[0][3], a0.x, bd3);
            fma2(acc2[1][0], a0.y, bd0); fma2(acc2[1][1], a0.y, bd1);
            fma2(acc2[1][2], a0.y, bd2); fma2(acc2[1][3], a0.y, bd3);
            fma2(acc2[2][0], a1.x, bd0); fma2(acc2[2][1], a1.x, bd1);
            fma2(acc2[2][2], a1.x, bd2); fma2(acc2[2][3], a1.x, bd3);
            fma2(acc2[3][0], a1.y, bd0); fma2(acc2[3][1], a1.y, bd1);
            fma2(acc2[3][2], a1.y, bd2); fma2(acc2[3][3], a1.y, bd3);
        }
    }
    #pragma unroll
    for (int rp = 0; rp < 4; ++rp) {
        float lo[4], hi[4];
        unpack2(acc2[rp][0], lo[0], hi[0]);
        unpack2(acc2[rp][1], lo[1], hi[1]);
        unpack2(acc2[rp][2], lo[2], hi[2]);
        unpack2(acc2[rp][3], lo[3], hi[3]);
        int r = ty * 8 + rp * 2;
        float4 v0 = {lo[0], lo[1], lo[2], lo[3]};
        float4 v1 = {hi[0], hi[1], hi[2], hi[3]};
        *(float4*)&g_osc[((size_t)(b * 128 + r)) * NN + m0 + tx * 4] = v0;
        *(float4*)&g_osc[((size_t)(b * 128 + r + 1)) * NN + m0 + tx * 4] = v1;
    }
}

// ---------------- channel Gram partials (32 chunks) ----------------
__global__ void __launch_bounds__(256) chan_gram() {
    int b = blockIdx.y;
    int chunk = blockIdx.x;             // 32 chunks of 128 n
    int tx = threadIdx.x & 15, ty = threadIdx.x >> 4;
    __shared__ __align__(16) float Qc[64][68];
    __shared__ __align__(16) float Kc[64][68];
    ull acc2[4][2] = {};
    int ld_r = threadIdx.x >> 4;
    int ld_c = (threadIdx.x & 15) * 4;
    for (int sub = 0; sub < 2; ++sub) {
        int n0 = chunk * 128 + sub * 64;
        __syncthreads();
        #pragma unroll
        for (int k = 0; k < 4; ++k) {
            int r = ld_r + k * 16;
            float4 q = *(const float4*)&g_qk[((size_t)(b * 256 + 128 + r)) * NN + n0 + ld_c];
            Qc[ld_c + 0][r] = q.x; Qc[ld_c + 1][r] = q.y;
            Qc[ld_c + 2][r] = q.z; Qc[ld_c + 3][r] = q.w;
            float4 w = *(const float4*)&g_qk[((size_t)(b * 256 + 192 + r)) * NN + n0 + ld_c];
            Kc[ld_c + 0][r] = w.x; Kc[ld_c + 1][r] = w.y;
            Kc[ld_c + 2][r] = w.z; Kc[ld_c + 3][r] = w.w;
        }
        __syncthreads();
        #pragma unroll 8
        for (int n = 0; n < 64; ++n) {
            float4 q4 = *(float4*)&Qc[n][ty * 4];
            const ull* kp = (const ull*)&Kc[n][0];
            ull k0 = kp[tx * 2], k1 = kp[tx * 2 + 1];
            float qa[4] = {q4.x, q4.y, q4.z, q4.w};
            #pragma unroll
            for (int i = 0; i < 4; ++i) {
                ull qd = dup2(qa[i]);
                fma2(acc2[i][0], qd, k0);
                fma2(acc2[i][1], qd, k1);
            }
        }
    }
    #pragma unroll
    for (int i = 0; i < 4; ++i) {
        float o0, o1, o2, o3;
        unpack2(acc2[i][0], o0, o1);
        unpack2(acc2[i][1], o2, o3);
        float* dst = &g_Gp[(b * 32 + chunk) * 4096 + (ty * 4 + i) * 64 + tx * 4];
        dst[0] = o0; dst[1] = o1; dst[2] = o2; dst[3] = o3;
    }
}

__global__ void chan_softmax() {
    int r = blockIdx.x;
    int b = blockIdx.y;
    int s = threadIdx.x;   // 64
    __shared__ float red[64];
    float v = 0.f;
    #pragma unroll
    for (int ch = 0; ch < 32; ++ch)
        v += g_Gp[(b * 32 + ch) * 4096 + r * 64 + s];
    red[s] = v;
    __syncthreads();
    for (int off = 32; off >= 1; off >>= 1) {
        if (s < off) red[s] = fmaxf(red[s], red[s + off]);
        __syncthreads();
    }
    float mx = red[0];
    __syncthreads();
    float e = __expf(v - mx);
    red[s] = e;
    __syncthreads();
    for (int off = 32; off >= 1; off >>= 1) {
        if (s < off) red[s] += red[s + off];
        __syncthreads();
    }
    g_A[b * 4096 + r * 64 + s] = e / red[0];
}

__global__ void __launch_bounds__(256) chan_out() {
    int b = blockIdx.y;
    int p = blockIdx.x * 256 + threadIdx.x;
    __shared__ __align__(16) float As[64][64];
    #pragma unroll
    for (int k = 0; k < 16; ++k)
        (&As[0][0])[threadIdx.x + k * 256] = g_A[b * 4096 + threadIdx.x + k * 256];
    __syncthreads();
    float kreg[64];
    #pragma unroll
    for (int s = 0; s < 64; ++s)
        kreg[s] = g_qk[((size_t)(b * 256 + 192 + s)) * NN + p];
    ull kp2[32];
    #pragma unroll
    for (int s = 0; s < 32; ++s) {
        ull r; asm("mov.b64 %0, {%1, %2};" : "=l"(r) : "f"(kreg[2 * s]), "f"(kreg[2 * s + 1]));
        kp2[s] = r;
    }
    #pragma unroll 2
    for (int r = 0; r < 64; ++r) {
        ull acc = 0;
        const ull* arow = (const ull*)&As[r][0];
        #pragma unroll
        for (int s = 0; s < 32; ++s)
            fma2(acc, arow[s], kp2[s]);
        float lo, hi;
        unpack2(acc, lo, hi);
        g_osc[((size_t)(b * 128 + 64 + r)) * NN + p] = lo + hi;
    }
}

// ---------------- final GEMM (128x128 tile) ----------------
__global__ void __launch_bounds__(256, 2) final_gemm(float* __restrict__ out) {
    int b = blockIdx.z;
    int o0 = blockIdx.y * 128;
    int p0 = blockIdx.x * 128;
    int t = threadIdx.x, tx = t & 15, ty = t >> 4;
    __shared__ __align__(16) float As[16][132];   // [t][o]
    __shared__ __align__(16) float Bs[16][128];   // [t][p]
    ull acc2[8][4] = {};
    for (int step = 0; step < 8; ++step) {
        int t0 = step * 16;
        __syncthreads();
        #pragma unroll
        for (int i = 0; i < 2; ++i) {
            int l = t + i * 256;
            int oA = l & 127, tq = l >> 7;
            float4 v = *(const float4*)&g_Wc[(o0 + oA) * 128 + t0 + tq * 4];
            As[tq * 4 + 0][oA] = v.x;
            As[tq * 4 + 1][oA] = v.y;
            As[tq * 4 + 2][oA] = v.z;
            As[tq * 4 + 3][oA] = v.w;
            int cB = l >> 5, p4 = (l & 31) * 4;
            *(float4*)&Bs[cB][p4] =
                *(const float4*)&g_osc[((size_t)(b * 128 + t0 + cB)) * NN + p0 + p4];
        }
        __syncthreads();
        #pragma unroll
        for (int c = 0; c < 16; ++c) {
            ulonglong2 a0 = *(const ulonglong2*)&As[c][ty * 8];
            ulonglong2 a1 = *(const ulonglong2*)&As[c][ty * 8 + 4];
            ulonglong2 b0 = *(const ulonglong2*)&Bs[c][tx * 8];
            ulonglong2 b1 = *(const ulonglong2*)&Bs[c][tx * 8 + 4];
            float af[8];
            unpack2(a0.x, af[0], af[1]); unpack2(a0.y, af[2], af[3]);
            unpack2(a1.x, af[4], af[5]); unpack2(a1.y, af[6], af[7]);
            #pragma unroll
            for (int i = 0; i < 8; ++i) {
                ull ad = dup2(af[i]);
                fma2(acc2[i][0], ad, b0.x);
                fma2(acc2[i][1], ad, b0.y);
                fma2(acc2[i][2], ad, b1.x);
                fma2(acc2[i][3], ad, b1.y);
            }
        }
    }
    #pragma unroll
    for (int i = 0; i < 8; ++i) {
        int o = o0 + ty * 8 + i;
        float bias = g_bout[o];
        float of[8];
        unpack2(acc2[i][0], of[0], of[1]); unpack2(acc2[i][1], of[2], of[3]);
        unpack2(acc2[i][2], of[4], of[5]); unpack2(acc2[i][3], of[6], of[7]);
        float4 v0 = {of[0] + bias, of[1] + bias, of[2] + bias, of[3] + bias};
        float4 v1 = {of[4] + bias, of[5] + bias, of[6] + bias, of[7] + bias};
        size_t base = ((size_t)(b * 512 + o)) * NN + p0 + tx * 8;
        *(float4*)&out[base] = v0;
        *(float4*)&out[base + 4] = v1;
    }
}

// ---------------- launch ----------------
extern "C" void kernel_launch(void* const* d_in, const int* in_sizes, int n_in,
                              void* d_out, int out_size) {
    const float* top  = (const float*)d_in[0];
    const float* bot  = (const float*)d_in[1];
    const float* wt   = (const float*)d_in[2];
    const float* bt   = (const float*)d_in[3];
    const float* wb   = (const float*)d_in[4];
    const float* bb   = (const float*)d_in[5];
    const float* s_w1 = (const float*)d_in[6];
    const float* s_b1 = (const float*)d_in[7];
    const float* s_w2 = (const float*)d_in[8];
    const float* s_b2 = (const float*)d_in[9];
    const float* s_wo = (const float*)d_in[10];
    const float* s_bo = (const float*)d_in[11];
    const float* c_wq = (const float*)d_in[12];
    const float* c_bq = (const float*)d_in[13];
    const float* c_wk = (const float*)d_in[14];
    const float* c_bk = (const float*)d_in[15];
    const float* c_wo = (const float*)d_in[16];
    const float* c_bo = (const float*)d_in[17];
    const float* f_w  = (const float*)d_in[18];
    const float* f_b  = (const float*)d_in[19];
    float* out = (float*)d_out;

    cudaFuncSetAttribute(spatial_passA, cudaFuncAttributeMaxDynamicSharedMemorySize, 65536);
    cudaFuncSetAttribute(spatial_passB, cudaFuncAttributeMaxDynamicSharedMemorySize, 49152);

    fold_qk<<<512, 256>>>(wt, wb, s_w1, s_w2, c_wq, c_wk);
    fold_out<<<256, 256>>>(f_w, s_wo, c_wo);
    fold_bias<<<1, 512>>>(bt, bb, s_b1, s_b2, c_bq, c_bk, f_w, s_bo, c_bo, f_b,
                          s_w1, s_w2, c_wq, c_wk);
    qk_gemm<<<dim3(32, 2, 8), 256>>>(top, bot);
    spatial_passA<<<dim3(32, 8), 256, 65536>>>();
    spatial_passB<<<dim3(32, 8), 256, 49152>>>();
    chan_gram<<<dim3(32, 8), 256>>>();
    chan_softmax<<<dim3(64, 8), 64>>>();
    chan_out<<<dim3(16, 8), 256>>>();
    final_gemm<<<dim3(32, 4, 8), 256>>>(out);
}

// round 6
// speedup vs baseline: 1.2335x; 1.1156x over previous
#include <cuda_runtime.h>
#include <cuda_bf16.h>
#include <stdint.h>
#include <math.h>

#define BB 8
#define NN 4096

typedef unsigned long long ull;

__device__ __forceinline__ ull dup2(float x) {
    ull r; asm("mov.b64 %0, {%1, %1};" : "=l"(r) : "f"(x)); return r;
}
__device__ __forceinline__ void unpack2(ull v, float& x, float& y) {
    asm("mov.b64 {%0, %1}, %2;" : "=f"(x), "=f"(y) : "l"(v));
}
__device__ __forceinline__ void fma2(ull& d, ull a, ull b) {
    asm("fma.rn.f32x2 %0, %1, %2, %0;" : "+l"(d) : "l"(a), "l"(b));
}

__device__ __forceinline__ unsigned smem_u32(const void* p) {
    unsigned a;
    asm("{ .reg .u64 t; cvta.to.shared.u64 t, %1; cvt.u32.u64 %0, t; }" : "=r"(a) : "l"(p));
    return a;
}
__device__ __forceinline__ void ldsm4(unsigned* r, unsigned addr) {
    asm volatile("ldmatrix.sync.aligned.m8n8.x4.shared.b16 {%0,%1,%2,%3}, [%4];"
        : "=r"(r[0]), "=r"(r[1]), "=r"(r[2]), "=r"(r[3]) : "r"(addr));
}
__device__ __forceinline__ void mma_bf16(float* c, const unsigned* a, const unsigned* b) {
    asm volatile("mma.sync.aligned.m16n8k16.row.col.f32.bf16.bf16.f32 "
        "{%0,%1,%2,%3}, {%4,%5,%6,%7}, {%8,%9}, {%0,%1,%2,%3};"
        : "+f"(c[0]), "+f"(c[1]), "+f"(c[2]), "+f"(c[3])
        : "r"(a[0]), "r"(a[1]), "r"(a[2]), "r"(a[3]), "r"(b[0]), "r"(b[1]));
}

// ---------------- scratch ----------------
__device__ float g_Wtop[256 * 512];
__device__ float g_Wbot[256 * 512];
__device__ float g_bqk[256];
__device__ float g_Wc[512 * 128];
__device__ float g_bout[512];
__device__ float g_qk[(size_t)BB * 256 * NN];   // rows: 0-63 q1, 64-127 k1, 128-191 q2, 192-255 k2
__device__ float g_E[(size_t)BB * NN * NN];     // exp(S)
__device__ float g_Zinv[BB * NN];
__device__ float g_Gp[BB * 32 * 64 * 64];
__device__ float g_A[BB * 64 * 64];
__device__ float g_osc[(size_t)BB * 128 * NN];  // rows 0-63 out_s, 64-127 out_c
__device__ __nv_bfloat16 g_Wh[256 * 1024];      // folded W bf16 hi, K-major [j][c]
__device__ __nv_bfloat16 g_Wl[256 * 1024];      // bf16 lo
__device__ __nv_bfloat16 g_Xh[(size_t)BB * NN * 1024];  // input transposed [b][p][c] hi
__device__ __nv_bfloat16 g_Xl[(size_t)BB * NN * 1024];  // lo

// ---------------- weight folding ----------------
__global__ void fold_qk(const float* __restrict__ wt, const float* __restrict__ wb,
                        const float* __restrict__ sw1, const float* __restrict__ sw2,
                        const float* __restrict__ cwq, const float* __restrict__ cwk) {
    int idx = blockIdx.x * blockDim.x + threadIdx.x;
    int j = idx >> 9, c = idx & 511;
    const float* wrow; int uoff;
    if (j < 64)       { wrow = sw1 + j * 256;        uoff = 0;   }
    else if (j < 128) { wrow = sw2 + (j - 64) * 256; uoff = 0;   }
    else if (j < 192) { wrow = cwq + (j - 128) * 256; uoff = 256; }
    else              { wrow = cwk + (j - 192) * 256; uoff = 256; }
    float at = 0.f, ab = 0.f;
    #pragma unroll 8
    for (int u = 0; u < 256; ++u) {
        float w = wrow[u];
        at = fmaf(w, wt[(uoff + u) * 512 + c], at);
        ab = fmaf(w, wb[(uoff + u) * 512 + c], ab);
    }
    g_Wtop[idx] = at;
    g_Wbot[idx] = ab;
}

__global__ void fold_out(const float* __restrict__ fw, const float* __restrict__ swo,
                         const float* __restrict__ cwo) {
    int idx = blockIdx.x * blockDim.x + threadIdx.x;
    int o = idx >> 7, t = idx & 127;
    float acc = 0.f;
    if (t < 64) {
        #pragma unroll 8
        for (int u = 0; u < 256; ++u)
            acc = fmaf(fw[o * 512 + u], swo[u * 64 + t], acc);
    } else {
        int r = t - 64;
        #pragma unroll 8
        for (int u = 0; u < 256; ++u)
            acc = fmaf(fw[o * 512 + 256 + u], cwo[u * 64 + r], acc);
    }
    g_Wc[idx] = acc;
}

__global__ void fold_bias(const float* __restrict__ bt, const float* __restrict__ bb,
                          const float* __restrict__ sb1, const float* __restrict__ sb2,
                          const float* __restrict__ cbq, const float* __restrict__ cbk,
                          const float* __restrict__ fw,  const float* __restrict__ sbo,
                          const float* __restrict__ cbo, const float* __restrict__ fb,
                          const float* __restrict__ sw1, const float* __restrict__ sw2,
                          const float* __restrict__ cwq, const float* __restrict__ cwk) {
    int t = threadIdx.x;   // 512
    if (t < 256) {
        const float* wrow; int uoff; float ob;
        int j = t;
        if (j < 64)       { wrow = sw1 + j * 256;        uoff = 0;   ob = sb1[j];       }
        else if (j < 128) { wrow = sw2 + (j - 64) * 256; uoff = 0;   ob = sb2[j - 64];  }
        else if (j < 192) { wrow = cwq + (j - 128) * 256; uoff = 256; ob = cbq[j - 128]; }
        else              { wrow = cwk + (j - 192) * 256; uoff = 256; ob = cbk[j - 192]; }
        float s = ob;
        for (int u = 0; u < 256; ++u)
            s = fmaf(wrow[u], bt[uoff + u] + bb[uoff + u], s);
        g_bqk[j] = s;
    }
    float s2 = fb[t];
    for (int u = 0; u < 256; ++u) {
        s2 = fmaf(fw[t * 512 + u],       sbo[u], s2);
        s2 = fmaf(fw[t * 512 + 256 + u], cbo[u], s2);
    }
    g_bout[t] = s2;
}

// ---------------- bf16 hi/lo conversion of folded W ----------------
__global__ void conv_w() {
    int idx = blockIdx.x * 256 + threadIdx.x;   // 262144
    int j = idx >> 10, c = idx & 1023;
    float v = (c < 512) ? g_Wtop[j * 512 + c] : g_Wbot[j * 512 + c - 512];
    __nv_bfloat16 h = __float2bfloat16(v);
    __nv_bfloat16 l = __float2bfloat16(v - __bfloat162float(h));
    g_Wh[idx] = h;
    g_Wl[idx] = l;
}

// ---------------- transpose + bf16 hi/lo of inputs: [b][c][p] -> [b][p][c] ----------------
__global__ void conv_x(const float* __restrict__ top, const float* __restrict__ bot) {
    __shared__ float sh[32][33];
    int b = blockIdx.z;
    int c0 = blockIdx.y * 32;   // 0..1023
    int p0 = blockIdx.x * 32;
    const float* src = (c0 < 512) ? top : bot;
    int cs = c0 & 511;
    int tx = threadIdx.x, ty = threadIdx.y;   // 32 x 8
    #pragma unroll
    for (int k = 0; k < 4; ++k) {
        int i = ty + k * 8;
        sh[i][tx] = src[((size_t)(b * 512 + cs + i)) * NN + p0 + tx];
    }
    __syncthreads();
    #pragma unroll
    for (int k = 0; k < 4; ++k) {
        int i = ty + k * 8;
        float v = sh[tx][i];
        __nv_bfloat16 h = __float2bfloat16(v);
        __nv_bfloat16 l = __float2bfloat16(v - __bfloat162float(h));
        size_t o = ((size_t)(b * NN + p0 + i)) * 1024 + c0 + tx;
        g_Xh[o] = h;
        g_Xl[o] = l;
    }
}

// ---------------- qk GEMM via mma.sync (HMMA bf16, split hi/lo 3-pass) ----------------
// D[128 j][128 p] per CTA; K = 1024 in 16 chunks of 64.
// smem: 4 tiles of 128 rows x 72 bf16 (pad 8): Ah, Al, Bh, Bl  (73728 B)
#define TS (128 * 72 * 2)           // 18432 bytes per tile
#define QK2_SMEM (4 * TS)
__global__ void __launch_bounds__(256) qk_tc2() {
    extern __shared__ __align__(16) char smem[];
    unsigned sb = smem_u32(smem);
    int t = threadIdx.x;
    int wid = t >> 5, lid = t & 31;
    int b = blockIdx.z;
    int j0 = blockIdx.y * 128;
    int p0 = blockIdx.x * 128;
    int wr = wid & 1;          // j half (64 rows)
    int wc = wid >> 1;         // p quarter (32 cols)

    const __nv_bfloat16* srcs[4] = {
        g_Wh + (size_t)j0 * 1024,
        g_Wl + (size_t)j0 * 1024,
        g_Xh + ((size_t)b * NN + p0) * 1024,
        g_Xl + ((size_t)b * NN + p0) * 1024
    };

    // per-thread fragment address components
    unsigned aAddr = sb + (unsigned)((wr * 64 + (lid & 15)) * 144 + (lid >> 4) * 16);
    unsigned bAddr = sb + 2 * TS +
        (unsigned)((wc * 32 + ((lid >> 4) & 1) * 8 + (lid & 7)) * 144 + ((lid >> 3) & 1) * 16);

    float c[4][4][4] = {};

    for (int ch = 0; ch < 16; ++ch) {
        int c0 = ch * 64;
        __syncthreads();
        // load 4 tiles: 128 rows x 64 bf16 each
        #pragma unroll
        for (int tile = 0; tile < 4; ++tile) {
            char* base = smem + tile * TS;
            const __nv_bfloat16* s = srcs[tile];
            #pragma unroll
            for (int rep = 0; rep < 4; ++rep) {
                int u = t + rep * 256;
                int r = u >> 3, q = u & 7;
                uint4 v = *(const uint4*)(s + (size_t)r * 1024 + c0 + q * 8);
                *(uint4*)(base + r * 144 + q * 16) = v;
            }
        }
        __syncthreads();
        #pragma unroll
        for (int ks = 0; ks < 4; ++ks) {
            unsigned bh[2][4], bl[2][4];
            ldsm4(bh[0], bAddr + ks * 32);                 // n-tiles 0,1 hi
            ldsm4(bh[1], bAddr + 16 * 144 + ks * 32);      // n-tiles 2,3 hi
            ldsm4(bl[0], bAddr + TS + ks * 32);            // lo
            ldsm4(bl[1], bAddr + TS + 16 * 144 + ks * 32);
            #pragma unroll
            for (int mt = 0; mt < 4; ++mt) {
                unsigned ah[4], al[4];
                ldsm4(ah, aAddr + mt * 2304 + ks * 32);
                ldsm4(al, aAddr + TS + mt * 2304 + ks * 32);
                #pragma unroll
                for (int nt = 0; nt < 4; ++nt) {
                    const unsigned* bhp = &bh[nt >> 1][(nt & 1) * 2];
                    const unsigned* blp = &bl[nt >> 1][(nt & 1) * 2];
                    mma_bf16(c[mt][nt], ah, bhp);
                    mma_bf16(c[mt][nt], ah, blp);
                    mma_bf16(c[mt][nt], al, bhp);
                }
            }
        }
    }

    // epilogue: c fragment (m16n8 f32): lane g=lid>>2 tig=lid&3
    int g = lid >> 2, tig = lid & 3;
    #pragma unroll
    for (int mt = 0; mt < 4; ++mt) {
        int jrow0 = j0 + wr * 64 + mt * 16 + g;
        float b0 = g_bqk[jrow0], b1 = g_bqk[jrow0 + 8];
        size_t r0 = ((size_t)(b * 256 + jrow0)) * NN;
        size_t r1 = r0 + (size_t)8 * NN;
        #pragma unroll
        for (int nt = 0; nt < 4; ++nt) {
            int pc = p0 + wc * 32 + nt * 8 + tig * 2;
            float2 v0 = {c[mt][nt][0] + b0, c[mt][nt][1] + b0};
            float2 v1 = {c[mt][nt][2] + b1, c[mt][nt][3] + b1};
            *(float2*)&g_qk[r0 + pc] = v0;
            *(float2*)&g_qk[r1 + pc] = v1;
        }
    }
}

// ---------------- spatial pass A: E = exp(Q^T K), Zinv ----------------
__global__ void __launch_bounds__(256, 2) spatial_passA() {
    int b = blockIdx.y;
    int n0 = blockIdx.x * 128;
    int t = threadIdx.x, tx = t & 15, ty = t >> 4;
    extern __shared__ __align__(16) float dsm[];
    float (*Qs)[128] = (float(*)[128])dsm;
    float (*Ks)[128] = (float(*)[128])(dsm + 64 * 128);
    #pragma unroll
    for (int i = 0; i < 8; ++i) {
        int l = t + i * 256;
        int r = l >> 5, c4 = (l & 31) * 4;
        *(float4*)&Qs[r][c4] =
            *(const float4*)&g_qk[((size_t)(b * 256 + r)) * NN + n0 + c4];
    }
    float zacc[8] = {};
    size_t ebase = ((size_t)b) << 24;
    for (int mt = 0; mt < 32; ++mt) {
        int m0 = mt * 128;
        __syncthreads();
        #pragma unroll
        for (int i = 0; i < 8; ++i) {
            int l = t + i * 256;
            int r = l >> 5, c4 = (l & 31) * 4;
            *(float4*)&Ks[r][c4] =
                *(const float4*)&g_qk[((size_t)(b * 256 + 64 + r)) * NN + m0 + c4];
        }
        __syncthreads();
        ull s2[8][4] = {};
        #pragma unroll 8
        for (int r = 0; r < 64; ++r) {
            ulonglong2 a0 = *(const ulonglong2*)&Qs[r][ty * 8];
            ulonglong2 a1 = *(const ulonglong2*)&Qs[r][ty * 8 + 4];
            ulonglong2 b0 = *(const ulonglong2*)&Ks[r][tx * 8];
            ulonglong2 b1 = *(const ulonglong2*)&Ks[r][tx * 8 + 4];
            float af[8];
            unpack2(a0.x, af[0], af[1]); unpack2(a0.y, af[2], af[3]);
            unpack2(a1.x, af[4], af[5]); unpack2(a1.y, af[6], af[7]);
            #pragma unroll
            for (int i = 0; i < 8; ++i) {
                ull ad = dup2(af[i]);
                fma2(s2[i][0], ad, b0.x);
                fma2(s2[i][1], ad, b0.y);
                fma2(s2[i][2], ad, b1.x);
                fma2(s2[i][3], ad, b1.y);
            }
        }
        #pragma unroll
        for (int i = 0; i < 8; ++i) {
            int n = n0 + ty * 8 + i;
            float o[8];
            unpack2(s2[i][0], o[0], o[1]); unpack2(s2[i][1], o[2], o[3]);
            unpack2(s2[i][2], o[4], o[5]); unpack2(s2[i][3], o[6], o[7]);
            float e[8];
            #pragma unroll
            for (int k = 0; k < 8; ++k) e[k] = __expf(o[k]);
            zacc[i] += (e[0] + e[1]) + (e[2] + e[3]) + (e[4] + e[5]) + (e[6] + e[7]);
            float4 v0 = {e[0], e[1], e[2], e[3]};
            float4 v1 = {e[4], e[5], e[6], e[7]};
            size_t base = ebase + (((size_t)n) << 12) + m0 + tx * 8;
            *(float4*)&g_E[base] = v0;
            *(float4*)&g_E[base + 4] = v1;
        }
    }
    __syncthreads();
    float* zb = dsm + 64 * 128;
    #pragma unroll
    for (int i = 0; i < 8; ++i)
        zb[(ty * 8 + i) * 16 + tx] = zacc[i];
    __syncthreads();
    if (t < 128) {
        float s = 0.f;
        #pragma unroll
        for (int k = 0; k < 16; ++k) s += zb[t * 16 + k];
        g_Zinv[b * NN + n0 + t] = 1.0f / s;
    }
}

// ---------------- spatial pass B: out_s = (K*Zinv) @ E ----------------
__global__ void __launch_bounds__(256, 2) spatial_passB() {
    int b = blockIdx.y;
    int m0 = blockIdx.x * 128;
    int t = threadIdx.x, tx = t & 31, ty = t >> 5;
    extern __shared__ __align__(16) float dsm[];
    float (*Ks)[64] = (float(*)[64])dsm;
    float (*Es)[128] = (float(*)[128])(dsm + 64 * 64);
    ull acc2[4][4] = {};
    size_t ebase = ((size_t)b) << 24;
    for (int nt = 0; nt < 64; ++nt) {
        int n0 = nt * 64;
        __syncthreads();
        #pragma unroll
        for (int i = 0; i < 4; ++i) {
            int l = t + i * 256;
            int r = l & 63, n4 = (l >> 6) * 4;
            float4 v = *(const float4*)&g_qk[((size_t)(b * 256 + 64 + r)) * NN + n0 + n4];
            float4 z = *(const float4*)&g_Zinv[b * NN + n0 + n4];
            Ks[n4 + 0][r] = v.x * z.x;
            Ks[n4 + 1][r] = v.y * z.y;
            Ks[n4 + 2][r] = v.z * z.z;
            Ks[n4 + 3][r] = v.w * z.w;
        }
        #pragma unroll
        for (int i = 0; i < 8; ++i) {
            int l = t + i * 256;
            int n = l >> 5, m4 = (l & 31) * 4;
            *(float4*)&Es[n][m4] =
                *(const float4*)&g_E[ebase + (((size_t)(n0 + n)) << 12) + m0 + m4];
        }
        __syncthreads();
        #pragma unroll 8
        for (int n = 0; n < 64; ++n) {
            ulonglong2 a0 = *(const ulonglong2*)&Ks[n][ty * 8];
            ulonglong2 a1 = *(const ulonglong2*)&Ks[n][ty * 8 + 4];
            float4 bv = *(const float4*)&Es[n][tx * 4];
            ull bd0 = dup2(bv.x), bd1 = dup2(bv.y), bd2 = dup2(bv.z), bd3 = dup2(bv.w);
            fma2(acc2[0][0], a0.x, bd0); fma2(acc2[0][1], a0.x, bd1);
            fma2(acc2[0][2], a0.x, bd2); fma2(acc2[0][3], a0.x, bd3);
            fma2(acc2[1][0], a0.y, bd0); fma2(acc2[1][1], a0.y, bd1);
            fma2(acc2[1][2], a0.y, bd2); fma2(acc2[1][3], a0.y, bd3);
            fma2(acc2[2][0], a1.x, bd0); fma2(acc2[2][1], a1.x, bd1);
            fma2(acc2[2][2], a1.x, bd2); fma2(acc2[2][3], a1.x, bd3);
            fma2(acc2[3][0], a1.y, bd0); fma2(acc2[3][1], a1.y, bd1);
            fma2(acc2[3][2], a1.y, bd2); fma2(acc2[3][3], a1.y, bd3);
        }
    }
    #pragma unroll
    for (int rp = 0; rp < 4; ++rp) {
        float lo[4], hi[4];
        unpack2(acc2[rp][0], lo[0], hi[0]);
        unpack2(acc2[rp][1], lo[1], hi[1]);
        unpack2(acc2[rp][2], lo[2], hi[2]);
        unpack2(acc2[rp][3], lo[3], hi[3]);
        int r = ty * 8 + rp * 2;
        float4 v0 = {lo[0], lo[1], lo[2], lo[3]};
        float4 v1 = {hi[0], hi[1], hi[2], hi[3]};
        *(float4*)&g_osc[((size_t)(b * 128 + r)) * NN + m0 + tx * 4] = v0;
        *(float4*)&g_osc[((size_t)(b * 128 + r + 1)) * NN + m0 + tx * 4] = v1;
    }
}

// ---------------- channel Gram partials (32 chunks) ----------------
__global__ void __launch_bounds__(256) chan_gram() {
    int b = blockIdx.y;
    int chunk = blockIdx.x;
    int tx = threadIdx.x & 15, ty = threadIdx.x >> 4;
    __shared__ __align__(16) float Qc[64][68];
    __shared__ __align__(16) float Kc[64][68];
    ull acc2[4][2] = {};
    int ld_r = threadIdx.x >> 4;
    int ld_c = (threadIdx.x & 15) * 4;
    for (int sub = 0; sub < 2; ++sub) {
        int n0 = chunk * 128 + sub * 64;
        __syncthreads();
        #pragma unroll
        for (int k = 0; k < 4; ++k) {
            int r = ld_r + k * 16;
            float4 q = *(const float4*)&g_qk[((size_t)(b * 256 + 128 + r)) * NN + n0 + ld_c];
            Qc[ld_c + 0][r] = q.x; Qc[ld_c + 1][r] = q.y;
            Qc[ld_c + 2][r] = q.z; Qc[ld_c + 3][r] = q.w;
            float4 w = *(const float4*)&g_qk[((size_t)(b * 256 + 192 + r)) * NN + n0 + ld_c];
            Kc[ld_c + 0][r] = w.x; Kc[ld_c + 1][r] = w.y;
            Kc[ld_c + 2][r] = w.z; Kc[ld_c + 3][r] = w.w;
        }
        __syncthreads();
        #pragma unroll 8
        for (int n = 0; n < 64; ++n) {
            float4 q4 = *(float4*)&Qc[n][ty * 4];
            const ull* kp = (const ull*)&Kc[n][0];
            ull k0 = kp[tx * 2], k1 = kp[tx * 2 + 1];
            float qa[4] = {q4.x, q4.y, q4.z, q4.w};
            #pragma unroll
            for (int i = 0; i < 4; ++i) {
                ull qd = dup2(qa[i]);
                fma2(acc2[i][0], qd, k0);
                fma2(acc2[i][1], qd, k1);
            }
        }
    }
    #pragma unroll
    for (int i = 0; i < 4; ++i) {
        float o0, o1, o2, o3;
        unpack2(acc2[i][0], o0, o1);
        unpack2(acc2[i][1], o2, o3);
        float* dst = &g_Gp[(b * 32 + chunk) * 4096 + (ty * 4 + i) * 64 + tx * 4];
        dst[0] = o0; dst[1] = o1; dst[2] = o2; dst[3] = o3;
    }
}

__global__ void chan_softmax() {
    int r = blockIdx.x;
    int b = blockIdx.y;
    int s = threadIdx.x;
    __shared__ float red[64];
    float v = 0.f;
    #pragma unroll
    for (int ch = 0; ch < 32; ++ch)
        v += g_Gp[(b * 32 + ch) * 4096 + r * 64 + s];
    red[s] = v;
    __syncthreads();
    for (int off = 32; off >= 1; off >>= 1) {
        if (s < off) red[s] = fmaxf(red[s], red[s + off]);
        __syncthreads();
    }
    float mx = red[0];
    __syncthreads();
    float e = __expf(v - mx);
    red[s] = e;
    __syncthreads();
    for (int off = 32; off >= 1; off >>= 1) {
        if (s < off) red[s] += red[s + off];
        __syncthreads();
    }
    g_A[b * 4096 + r * 64 + s] = e / red[0];
}

__global__ void __launch_bounds__(256) chan_out() {
    int b = blockIdx.y;
    int p = blockIdx.x * 256 + threadIdx.x;
    __shared__ __align__(16) float As[64][64];
    #pragma unroll
    for (int k = 0; k < 16; ++k)
        (&As[0][0])[threadIdx.x + k * 256] = g_A[b * 4096 + threadIdx.x + k * 256];
    __syncthreads();
    float kreg[64];
    #pragma unroll
    for (int s = 0; s < 64; ++s)
        kreg[s] = g_qk[((size_t)(b * 256 + 192 + s)) * NN + p];
    ull kp2[32];
    #pragma unroll
    for (int s = 0; s < 32; ++s) {
        ull r; asm("mov.b64 %0, {%1, %2};" : "=l"(r) : "f"(kreg[2 * s]), "f"(kreg[2 * s + 1]));
        kp2[s] = r;
    }
    #pragma unroll 2
    for (int r = 0; r < 64; ++r) {
        ull acc = 0;
        const ull* arow = (const ull*)&As[r][0];
        #pragma unroll
        for (int s = 0; s < 32; ++s)
            fma2(acc, arow[s], kp2[s]);
        float lo, hi;
        unpack2(acc, lo, hi);
        g_osc[((size_t)(b * 128 + 64 + r)) * NN + p] = lo + hi;
    }
}

// ---------------- final GEMM (128x128 tile) ----------------
__global__ void __launch_bounds__(256, 2) final_gemm(float* __restrict__ out) {
    int b = blockIdx.z;
    int o0 = blockIdx.y * 128;
    int p0 = blockIdx.x * 128;
    int t = threadIdx.x, tx = t & 15, ty = t >> 4;
    __shared__ __align__(16) float As[16][132];
    __shared__ __align__(16) float Bs[16][128];
    ull acc2[8][4] = {};
    for (int step = 0; step < 8; ++step) {
        int t0 = step * 16;
        __syncthreads();
        #pragma unroll
        for (int i = 0; i < 2; ++i) {
            int l = t + i * 256;
            int oA = l & 127, tq = l >> 7;
            float4 v = *(const float4*)&g_Wc[(o0 + oA) * 128 + t0 + tq * 4];
            As[tq * 4 + 0][oA] = v.x;
            As[tq * 4 + 1][oA] = v.y;
            As[tq * 4 + 2][oA] = v.z;
            As[tq * 4 + 3][oA] = v.w;
            int cB = l >> 5, p4 = (l & 31) * 4;
            *(float4*)&Bs[cB][p4] =
                *(const float4*)&g_osc[((size_t)(b * 128 + t0 + cB)) * NN + p0 + p4];
        }
        __syncthreads();
        #pragma unroll
        for (int c = 0; c < 16; ++c) {
            ulonglong2 a0 = *(const ulonglong2*)&As[c][ty * 8];
            ulonglong2 a1 = *(const ulonglong2*)&As[c][ty * 8 + 4];
            ulonglong2 b0 = *(const ulonglong2*)&Bs[c][tx * 8];
            ulonglong2 b1 = *(const ulonglong2*)&Bs[c][tx * 8 + 4];
            float af[8];
            unpack2(a0.x, af[0], af[1]); unpack2(a0.y, af[2], af[3]);
            unpack2(a1.x, af[4], af[5]); unpack2(a1.y, af[6], af[7]);
            #pragma unroll
            for (int i = 0; i < 8; ++i) {
                ull ad = dup2(af[i]);
                fma2(acc2[i][0], ad, b0.x);
                fma2(acc2[i][1], ad, b0.y);
                fma2(acc2[i][2], ad, b1.x);
                fma2(acc2[i][3], ad, b1.y);
            }
        }
    }
    #pragma unroll
    for (int i = 0; i < 8; ++i) {
        int o = o0 + ty * 8 + i;
        float bias = g_bout[o];
        float of[8];
        unpack2(acc2[i][0], of[0], of[1]); unpack2(acc2[i][1], of[2], of[3]);
        unpack2(acc2[i][2], of[4], of[5]); unpack2(acc2[i][3], of[6], of[7]);
        float4 v0 = {of[0] + bias, of[1] + bias, of[2] + bias, of[3] + bias};
        float4 v1 = {of[4] + bias, of[5] + bias, of[6] + bias, of[7] + bias};
        size_t base = ((size_t)(b * 512 + o)) * NN + p0 + tx * 8;
        *(float4*)&out[base] = v0;
        *(float4*)&out[base + 4] = v1;
    }
}

// ---------------- launch ----------------
extern "C" void kernel_launch(void* const* d_in, const int* in_sizes, int n_in,
                              void* d_out, int out_size) {
    const float* top  = (const float*)d_in[0];
    const float* bot  = (const float*)d_in[1];
    const float* wt   = (const float*)d_in[2];
    const float* bt   = (const float*)d_in[3];
    const float* wb   = (const float*)d_in[4];
    const float* bb   = (const float*)d_in[5];
    const float* s_w1 = (const float*)d_in[6];
    const float* s_b1 = (const float*)d_in[7];
    const float* s_w2 = (const float*)d_in[8];
    const float* s_b2 = (const float*)d_in[9];
    const float* s_wo = (const float*)d_in[10];
    const float* s_bo = (const float*)d_in[11];
    const float* c_wq = (const float*)d_in[12];
    const float* c_bq = (const float*)d_in[13];
    const float* c_wk = (const float*)d_in[14];
    const float* c_bk = (const float*)d_in[15];
    const float* c_wo = (const float*)d_in[16];
    const float* c_bo = (const float*)d_in[17];
    const float* f_w  = (const float*)d_in[18];
    const float* f_b  = (const float*)d_in[19];
    float* out = (float*)d_out;

    cudaFuncSetAttribute(spatial_passA, cudaFuncAttributeMaxDynamicSharedMemorySize, 65536);
    cudaFuncSetAttribute(spatial_passB, cudaFuncAttributeMaxDynamicSharedMemorySize, 49152);
    cudaFuncSetAttribute(qk_tc2, cudaFuncAttributeMaxDynamicSharedMemorySize, QK2_SMEM);

    fold_qk<<<512, 256>>>(wt, wb, s_w1, s_w2, c_wq, c_wk);
    fold_out<<<256, 256>>>(f_w, s_wo, c_wo);
    fold_bias<<<1, 512>>>(bt, bb, s_b1, s_b2, c_bq, c_bk, f_w, s_bo, c_bo, f_b,
                          s_w1, s_w2, c_wq, c_wk);
    conv_w<<<1024, 256>>>();
    conv_x<<<dim3(128, 32, 8), dim3(32, 8)>>>(top, bot);
    qk_tc2<<<dim3(32, 2, 8), 256, QK2_SMEM>>>();
    spatial_passA<<<dim3(32, 8), 256, 65536>>>();
    spatial_passB<<<dim3(32, 8), 256, 49152>>>();
    chan_gram<<<dim3(32, 8), 256>>>();
    chan_softmax<<<dim3(64, 8), 64>>>();
    chan_out<<<dim3(16, 8), 256>>>();
    final_gemm<<<dim3(32, 4, 8), 256>>>(out);
}

// round 7
// speedup vs baseline: 1.8508x; 1.5005x over previous
#include <cuda_runtime.h>
#include <cuda_bf16.h>
#include <stdint.h>
#include <math.h>

#define BB 8
#define NN 4096

typedef unsigned long long ull;

__device__ __forceinline__ ull dup2(float x) {
    ull r; asm("mov.b64 %0, {%1, %1};" : "=l"(r) : "f"(x)); return r;
}
__device__ __forceinline__ void unpack2(ull v, float& x, float& y) {
    asm("mov.b64 {%0, %1}, %2;" : "=f"(x), "=f"(y) : "l"(v));
}
__device__ __forceinline__ void fma2(ull& d, ull a, ull b) {
    asm("fma.rn.f32x2 %0, %1, %2, %0;" : "+l"(d) : "l"(a), "l"(b));
}

__device__ __forceinline__ unsigned smem_u32(const void* p) {
    unsigned a;
    asm("{ .reg .u64 t; cvta.to.shared.u64 t, %1; cvt.u32.u64 %0, t; }" : "=r"(a) : "l"(p));
    return a;
}
__device__ __forceinline__ void ldsm4(unsigned* r, unsigned addr) {
    asm volatile("ldmatrix.sync.aligned.m8n8.x4.shared.b16 {%0,%1,%2,%3}, [%4];"
        : "=r"(r[0]), "=r"(r[1]), "=r"(r[2]), "=r"(r[3]) : "r"(addr));
}
__device__ __forceinline__ void ldsm4t(unsigned* r, unsigned addr) {
    asm volatile("ldmatrix.sync.aligned.m8n8.x4.trans.shared.b16 {%0,%1,%2,%3}, [%4];"
        : "=r"(r[0]), "=r"(r[1]), "=r"(r[2]), "=r"(r[3]) : "r"(addr));
}
__device__ __forceinline__ void mma_bf16(float* c, const unsigned* a, const unsigned* b) {
    asm volatile("mma.sync.aligned.m16n8k16.row.col.f32.bf16.bf16.f32 "
        "{%0,%1,%2,%3}, {%4,%5,%6,%7}, {%8,%9}, {%0,%1,%2,%3};"
        : "+f"(c[0]), "+f"(c[1]), "+f"(c[2]), "+f"(c[3])
        : "r"(a[0]), "r"(a[1]), "r"(a[2]), "r"(a[3]), "r"(b[0]), "r"(b[1]));
}

// fast exp: poly exp2 on FMA pipe, no MUFU
__device__ __forceinline__ float fast_exp(float x) {
    float y = x * 1.4426950408889634f;
    float n = rintf(y);
    float f = y - n;
    float p = 1.3333558146e-3f;
    p = fmaf(p, f, 9.6181291076e-3f);
    p = fmaf(p, f, 5.5504108664e-2f);
    p = fmaf(p, f, 2.4022650696e-1f);
    p = fmaf(p, f, 6.9314718056e-1f);
    p = fmaf(p, f, 1.0f);
    int ni = (int)n;
    float s = __int_as_float((ni + 127) << 23);
    return p * s;
}

// ---------------- scratch ----------------
__device__ float g_Wtop[256 * 512];
__device__ float g_Wbot[256 * 512];
__device__ float g_bqk[256];
__device__ float g_Wc[512 * 128];
__device__ float g_bout[512];
__device__ float g_qk[(size_t)BB * 256 * NN];   // rows: 0-63 q1, 64-127 k1, 128-191 q2, 192-255 k2
__device__ __nv_bfloat16 g_E2[(size_t)BB * NN * NN];   // exp(S) bf16, 268 MB
__device__ float g_Zinv[BB * NN];
__device__ float g_Gp[BB * 32 * 64 * 64];
__device__ float g_A[BB * 64 * 64];
__device__ float g_osc[(size_t)BB * 128 * NN];  // rows 0-63 out_s, 64-127 out_c
__device__ __nv_bfloat16 g_Wh[256 * 1024];
__device__ __nv_bfloat16 g_Wl[256 * 1024];
__device__ __nv_bfloat16 g_Xh[(size_t)BB * NN * 1024];
__device__ __nv_bfloat16 g_Xl[(size_t)BB * NN * 1024];
__device__ __nv_bfloat16 g_QKTh[(size_t)BB * NN * 128];  // [b][p][j] j: 0-63 q1, 64-127 k1
__device__ __nv_bfloat16 g_QKTl[(size_t)BB * NN * 128];
__device__ __nv_bfloat16 g_KZh[(size_t)BB * 64 * NN];    // Kz = k1 * Zinv, [b][r][n]
__device__ __nv_bfloat16 g_KZl[(size_t)BB * 64 * NN];

// ---------------- weight folding ----------------
__global__ void fold_qk(const float* __restrict__ wt, const float* __restrict__ wb,
                        const float* __restrict__ sw1, const float* __restrict__ sw2,
                        const float* __restrict__ cwq, const float* __restrict__ cwk) {
    int idx = blockIdx.x * blockDim.x + threadIdx.x;
    int j = idx >> 9, c = idx & 511;
    const float* wrow; int uoff;
    if (j < 64)       { wrow = sw1 + j * 256;        uoff = 0;   }
    else if (j < 128) { wrow = sw2 + (j - 64) * 256; uoff = 0;   }
    else if (j < 192) { wrow = cwq + (j - 128) * 256; uoff = 256; }
    else              { wrow = cwk + (j - 192) * 256; uoff = 256; }
    float at = 0.f, ab = 0.f;
    #pragma unroll 8
    for (int u = 0; u < 256; ++u) {
        float w = wrow[u];
        at = fmaf(w, wt[(uoff + u) * 512 + c], at);
        ab = fmaf(w, wb[(uoff + u) * 512 + c], ab);
    }
    g_Wtop[idx] = at;
    g_Wbot[idx] = ab;
}

__global__ void fold_out(const float* __restrict__ fw, const float* __restrict__ swo,
                         const float* __restrict__ cwo) {
    int idx = blockIdx.x * blockDim.x + threadIdx.x;
    int o = idx >> 7, t = idx & 127;
    float acc = 0.f;
    if (t < 64) {
        #pragma unroll 8
        for (int u = 0; u < 256; ++u)
            acc = fmaf(fw[o * 512 + u], swo[u * 64 + t], acc);
    } else {
        int r = t - 64;
        #pragma unroll 8
        for (int u = 0; u < 256; ++u)
            acc = fmaf(fw[o * 512 + 256 + u], cwo[u * 64 + r], acc);
    }
    g_Wc[idx] = acc;
}

__global__ void fold_bias(const float* __restrict__ bt, const float* __restrict__ bb,
                          const float* __restrict__ sb1, const float* __restrict__ sb2,
                          const float* __restrict__ cbq, const float* __restrict__ cbk,
                          const float* __restrict__ fw,  const float* __restrict__ sbo,
                          const float* __restrict__ cbo, const float* __restrict__ fb,
                          const float* __restrict__ sw1, const float* __restrict__ sw2,
                          const float* __restrict__ cwq, const float* __restrict__ cwk) {
    int t = threadIdx.x;   // 512
    if (t < 256) {
        const float* wrow; int uoff; float ob;
        int j = t;
        if (j < 64)       { wrow = sw1 + j * 256;        uoff = 0;   ob = sb1[j];       }
        else if (j < 128) { wrow = sw2 + (j - 64) * 256; uoff = 0;   ob = sb2[j - 64];  }
        else if (j < 192) { wrow = cwq + (j - 128) * 256; uoff = 256; ob = cbq[j - 128]; }
        else              { wrow = cwk + (j - 192) * 256; uoff = 256; ob = cbk[j - 192]; }
        float s = ob;
        for (int u = 0; u < 256; ++u)
            s = fmaf(wrow[u], bt[uoff + u] + bb[uoff + u], s);
        g_bqk[j] = s;
    }
    float s2 = fb[t];
    for (int u = 0; u < 256; ++u) {
        s2 = fmaf(fw[t * 512 + u],       sbo[u], s2);
        s2 = fmaf(fw[t * 512 + 256 + u], cbo[u], s2);
    }
    g_bout[t] = s2;
}

// ---------------- bf16 hi/lo conversion of folded W ----------------
__global__ void conv_w() {
    int idx = blockIdx.x * 256 + threadIdx.x;
    int j = idx >> 10, c = idx & 1023;
    float v = (c < 512) ? g_Wtop[j * 512 + c] : g_Wbot[j * 512 + c - 512];
    __nv_bfloat16 h = __float2bfloat16(v);
    __nv_bfloat16 l = __float2bfloat16(v - __bfloat162float(h));
    g_Wh[idx] = h;
    g_Wl[idx] = l;
}

// ---------------- transpose + bf16 hi/lo of inputs ----------------
__global__ void conv_x(const float* __restrict__ top, const float* __restrict__ bot) {
    __shared__ float sh[32][33];
    int b = blockIdx.z;
    int c0 = blockIdx.y * 32;
    int p0 = blockIdx.x * 32;
    const float* src = (c0 < 512) ? top : bot;
    int cs = c0 & 511;
    int tx = threadIdx.x, ty = threadIdx.y;
    #pragma unroll
    for (int k = 0; k < 4; ++k) {
        int i = ty + k * 8;
        sh[i][tx] = src[((size_t)(b * 512 + cs + i)) * NN + p0 + tx];
    }
    __syncthreads();
    #pragma unroll
    for (int k = 0; k < 4; ++k) {
        int i = ty + k * 8;
        float v = sh[tx][i];
        __nv_bfloat16 h = __float2bfloat16(v);
        __nv_bfloat16 l = __float2bfloat16(v - __bfloat162float(h));
        size_t o = ((size_t)(b * NN + p0 + i)) * 1024 + c0 + tx;
        g_Xh[o] = h;
        g_Xl[o] = l;
    }
}

// ---------------- qk GEMM via HMMA (split hi/lo 3-pass) ----------------
#define TS (128 * 72 * 2)
#define QK2_SMEM (4 * TS)
__global__ void __launch_bounds__(256) qk_tc2() {
    extern __shared__ __align__(16) char smem[];
    unsigned sb = smem_u32(smem);
    int t = threadIdx.x;
    int wid = t >> 5, lid = t & 31;
    int b = blockIdx.z;
    int j0 = blockIdx.y * 128;
    int p0 = blockIdx.x * 128;
    int wr = wid & 1;
    int wc = wid >> 1;

    const __nv_bfloat16* srcs[4] = {
        g_Wh + (size_t)j0 * 1024,
        g_Wl + (size_t)j0 * 1024,
        g_Xh + ((size_t)b * NN + p0) * 1024,
        g_Xl + ((size_t)b * NN + p0) * 1024
    };

    unsigned aAddr = sb + (unsigned)((wr * 64 + (lid & 15)) * 144 + (lid >> 4) * 16);
    unsigned bAddr = sb + 2 * TS +
        (unsigned)((wc * 32 + ((lid >> 4) & 1) * 8 + (lid & 7)) * 144 + ((lid >> 3) & 1) * 16);

    float c[4][4][4] = {};

    for (int ch = 0; ch < 16; ++ch) {
        int c0 = ch * 64;
        __syncthreads();
        #pragma unroll
        for (int tile = 0; tile < 4; ++tile) {
            char* base = smem + tile * TS;
            const __nv_bfloat16* s = srcs[tile];
            #pragma unroll
            for (int rep = 0; rep < 4; ++rep) {
                int u = t + rep * 256;
                int r = u >> 3, q = u & 7;
                uint4 v = *(const uint4*)(s + (size_t)r * 1024 + c0 + q * 8);
                *(uint4*)(base + r * 144 + q * 16) = v;
            }
        }
        __syncthreads();
        #pragma unroll
        for (int ks = 0; ks < 4; ++ks) {
            unsigned bh[2][4], bl[2][4];
            ldsm4(bh[0], bAddr + ks * 32);
            ldsm4(bh[1], bAddr + 16 * 144 + ks * 32);
            ldsm4(bl[0], bAddr + TS + ks * 32);
            ldsm4(bl[1], bAddr + TS + 16 * 144 + ks * 32);
            #pragma unroll
            for (int mt = 0; mt < 4; ++mt) {
                unsigned ah[4], al[4];
                ldsm4(ah, aAddr + mt * 2304 + ks * 32);
                ldsm4(al, aAddr + TS + mt * 2304 + ks * 32);
                #pragma unroll
                for (int nt = 0; nt < 4; ++nt) {
                    const unsigned* bhp = &bh[nt >> 1][(nt & 1) * 2];
                    const unsigned* blp = &bl[nt >> 1][(nt & 1) * 2];
                    mma_bf16(c[mt][nt], ah, bhp);
                    mma_bf16(c[mt][nt], ah, blp);
                    mma_bf16(c[mt][nt], al, bhp);
                }
            }
        }
    }

    int g = lid >> 2, tig = lid & 3;
    #pragma unroll
    for (int mt = 0; mt < 4; ++mt) {
        int jrow0 = j0 + wr * 64 + mt * 16 + g;
        float b0 = g_bqk[jrow0], b1 = g_bqk[jrow0 + 8];
        size_t r0 = ((size_t)(b * 256 + jrow0)) * NN;
        size_t r1 = r0 + (size_t)8 * NN;
        #pragma unroll
        for (int nt = 0; nt < 4; ++nt) {
            int pc = p0 + wc * 32 + nt * 8 + tig * 2;
            float2 v0 = {c[mt][nt][0] + b0, c[mt][nt][1] + b0};
            float2 v1 = {c[mt][nt][2] + b1, c[mt][nt][3] + b1};
            *(float2*)&g_qk[r0 + pc] = v0;
            *(float2*)&g_qk[r1 + pc] = v1;
        }
    }
}

// ---------------- transpose q1/k1 rows to [p][j] bf16 hi/lo ----------------
__global__ void conv_qk() {
    __shared__ float sh[32][33];
    int b = blockIdx.z;
    int j0 = blockIdx.y * 32;   // 0..127
    int p0 = blockIdx.x * 32;
    int tx = threadIdx.x, ty = threadIdx.y;   // 32x8
    #pragma unroll
    for (int k = 0; k < 4; ++k) {
        int i = ty + k * 8;
        sh[i][tx] = g_qk[((size_t)(b * 256 + j0 + i)) * NN + p0 + tx];
    }
    __syncthreads();
    #pragma unroll
    for (int k = 0; k < 4; ++k) {
        int i = ty + k * 8;
        float v = sh[tx][i];
        __nv_bfloat16 h = __float2bfloat16(v);
        __nv_bfloat16 l = __float2bfloat16(v - __bfloat162float(h));
        size_t o = ((size_t)(b * NN + p0 + i)) * 128 + j0 + tx;
        g_QKTh[o] = h;
        g_QKTl[o] = l;
    }
}

// ---------------- spatial pass A via HMMA: E=exp(Q^T K) bf16, Zinv ----------------
// smem: Qh[0,18432) Ql Kh Kl zp(2048)
#define PAT (128 * 72 * 2)   // 18432
#define PA_SMEM (4 * PAT + 2048)
__global__ void __launch_bounds__(256) passA_tc() {
    extern __shared__ __align__(16) char smem[];
    unsigned sb = smem_u32(smem);
    int t = threadIdx.x;
    int wid = t >> 5, lid = t & 31;
    int b = blockIdx.y;
    int n0 = blockIdx.x * 128;
    int wr = wid & 1;
    int wc = wid >> 1;
    int g = lid >> 2, tig = lid & 3;

    // load QT hi/lo tiles once (rows n0..n0+127, cols 0..63)
    #pragma unroll
    for (int rep = 0; rep < 4; ++rep) {
        int u = t + rep * 256;
        int r = u >> 3, q = u & 7;
        size_t src = ((size_t)b * NN + n0 + r) * 128 + q * 8;
        *(uint4*)(smem + r * 144 + q * 16) = *(const uint4*)(g_QKTh + src);
        *(uint4*)(smem + PAT + r * 144 + q * 16) = *(const uint4*)(g_QKTl + src);
    }

    unsigned aAddrH = sb + (unsigned)((wr * 64 + (lid & 15)) * 144 + (lid >> 4) * 16);
    unsigned bAddrH = sb + 2 * PAT +
        (unsigned)((wc * 32 + ((lid >> 4) & 1) * 8 + (lid & 7)) * 144 + ((lid >> 3) & 1) * 16);

    float zacc[8] = {};
    size_t ebase = ((size_t)b) << 24;

    // prefetch KT chunk 0
    uint4 ph[4], pl[4];
    {
        #pragma unroll
        for (int rep = 0; rep < 4; ++rep) {
            int u = t + rep * 256;
            int r = u >> 3, q = u & 7;
            size_t src = ((size_t)b * NN + r) * 128 + 64 + q * 8;
            ph[rep] = *(const uint4*)(g_QKTh + src);
            pl[rep] = *(const uint4*)(g_QKTl + src);
        }
    }

    for (int ch = 0; ch < 32; ++ch) {
        int m0 = ch * 128;
        __syncthreads();
        #pragma unroll
        for (int rep = 0; rep < 4; ++rep) {
            int u = t + rep * 256;
            int r = u >> 3, q = u & 7;
            *(uint4*)(smem + 2 * PAT + r * 144 + q * 16) = ph[rep];
            *(uint4*)(smem + 3 * PAT + r * 144 + q * 16) = pl[rep];
        }
        __syncthreads();
        if (ch + 1 < 32) {
            int m1 = (ch + 1) * 128;
            #pragma unroll
            for (int rep = 0; rep < 4; ++rep) {
                int u = t + rep * 256;
                int r = u >> 3, q = u & 7;
                size_t src = ((size_t)b * NN + m1 + r) * 128 + 64 + q * 8;
                ph[rep] = *(const uint4*)(g_QKTh + src);
                pl[rep] = *(const uint4*)(g_QKTl + src);
            }
        }
        float c[4][4][4] = {};
        #pragma unroll
        for (int ks = 0; ks < 4; ++ks) {
            unsigned bh[2][4], bl[2][4];
            ldsm4(bh[0], bAddrH + ks * 32);
            ldsm4(bh[1], bAddrH + 16 * 144 + ks * 32);
            ldsm4(bl[0], bAddrH + PAT + ks * 32);
            ldsm4(bl[1], bAddrH + PAT + 16 * 144 + ks * 32);
            #pragma unroll
            for (int mt = 0; mt < 4; ++mt) {
                unsigned ah[4], al[4];
                ldsm4(ah, aAddrH + mt * 2304 + ks * 32);
                ldsm4(al, aAddrH + PAT + mt * 2304 + ks * 32);
                #pragma unroll
                for (int nt = 0; nt < 4; ++nt) {
                    const unsigned* bhp = &bh[nt >> 1][(nt & 1) * 2];
                    const unsigned* blp = &bl[nt >> 1][(nt & 1) * 2];
                    mma_bf16(c[mt][nt], ah, bhp);
                    mma_bf16(c[mt][nt], ah, blp);
                    mma_bf16(c[mt][nt], al, bhp);
                }
            }
        }
        // epilogue: exp + store bf16 E + z accumulate
        #pragma unroll
        for (int mt = 0; mt < 4; ++mt) {
            int n = n0 + wr * 64 + mt * 16 + g;
            #pragma unroll
            for (int nt = 0; nt < 4; ++nt) {
                int m = m0 + wc * 32 + nt * 8 + tig * 2;
                float e0 = fast_exp(c[mt][nt][0]);
                float e1 = fast_exp(c[mt][nt][1]);
                float e2 = fast_exp(c[mt][nt][2]);
                float e3 = fast_exp(c[mt][nt][3]);
                __nv_bfloat162 v0 = {__float2bfloat16(e0), __float2bfloat16(e1)};
                __nv_bfloat162 v1 = {__float2bfloat16(e2), __float2bfloat16(e3)};
                *(__nv_bfloat162*)&g_E2[ebase + (size_t)n * NN + m] = v0;
                *(__nv_bfloat162*)&g_E2[ebase + (size_t)(n + 8) * NN + m] = v1;
                zacc[mt * 2] += e0 + e1;
                zacc[mt * 2 + 1] += e2 + e3;
            }
        }
    }

    // Z reduction
    float* zp = (float*)(smem + 4 * PAT);
    #pragma unroll
    for (int s = 0; s < 8; ++s) {
        float v = zacc[s];
        v += __shfl_xor_sync(0xFFFFFFFF, v, 1);
        v += __shfl_xor_sync(0xFFFFFFFF, v, 2);
        if (tig == 0)
            zp[wc * 128 + wr * 64 + (s >> 1) * 16 + (s & 1) * 8 + g] = v;
    }
    __syncthreads();
    if (t < 128) {
        float s = zp[t] + zp[128 + t] + zp[256 + t] + zp[384 + t];
        g_Zinv[b * NN + n0 + t] = 1.0f / s;
    }
}

// ---------------- Kz = k1 * Zinv -> bf16 hi/lo [b][r][n] ----------------
__global__ void conv_kz() {
    int n = blockIdx.x * 256 + threadIdx.x;
    int r = blockIdx.y;
    int b = blockIdx.z;
    float v = g_qk[((size_t)(b * 256 + 64 + r)) * NN + n] * g_Zinv[b * NN + n];
    __nv_bfloat16 h = __float2bfloat16(v);
    __nv_bfloat16 l = __float2bfloat16(v - __bfloat162float(h));
    size_t o = ((size_t)b * 64 + r) * NN + n;
    g_KZh[o] = h;
    g_KZl[o] = l;
}

// ---------------- spatial pass B via HMMA: out_s = Kz @ E ----------------
// smem: Kzh[0,9216) Kzl[9216,18432) E[18432, 18432+17408)
#define PB_SMEM (2 * 9216 + 64 * 272)
__global__ void __launch_bounds__(256) passB_tc() {
    extern __shared__ __align__(16) char smem[];
    unsigned sb = smem_u32(smem);
    int t = threadIdx.x;
    int wid = t >> 5, lid = t & 31;
    int b = blockIdx.y;
    int m0 = blockIdx.x * 128;
    int g = lid >> 2, tig = lid & 3;

    unsigned aAddrH = sb + (unsigned)(((lid & 15)) * 144 + (lid >> 4) * 16);
    unsigned eAddr = sb + 18432 +
        (unsigned)(((lid & 7) + ((lid >> 3) & 1) * 8) * 272 + (wid * 16 + (lid >> 4) * 8) * 2);

    float c[4][2][4] = {};
    size_t ebase = ((size_t)b) << 24;

    // prefetch chunk 0
    uint4 kzh[2], kzl[2], ev[4];
    {
        #pragma unroll
        for (int rep = 0; rep < 2; ++rep) {
            int u = t + rep * 256;
            int r = u >> 3, q = u & 7;
            size_t src = ((size_t)b * 64 + r) * NN + q * 8;
            kzh[rep] = *(const uint4*)(g_KZh + src);
            kzl[rep] = *(const uint4*)(g_KZl + src);
        }
        #pragma unroll
        for (int rep = 0; rep < 4; ++rep) {
            int u = t + rep * 256;
            int r = u >> 4, q = u & 15;
            ev[rep] = *(const uint4*)(g_E2 + ebase + (size_t)r * NN + m0 + q * 8);
        }
    }

    for (int ch = 0; ch < 64; ++ch) {
        __syncthreads();
        #pragma unroll
        for (int rep = 0; rep < 2; ++rep) {
            int u = t + rep * 256;
            int r = u >> 3, q = u & 7;
            *(uint4*)(smem + r * 144 + q * 16) = kzh[rep];
            *(uint4*)(smem + 9216 + r * 144 + q * 16) = kzl[rep];
        }
        #pragma unroll
        for (int rep = 0; rep < 4; ++rep) {
            int u = t + rep * 256;
            int r = u >> 4, q = u & 15;
            *(uint4*)(smem + 18432 + r * 272 + q * 16) = ev[rep];
        }
        __syncthreads();
        if (ch + 1 < 64) {
            int n1 = (ch + 1) * 64;
            #pragma unroll
            for (int rep = 0; rep < 2; ++rep) {
                int u = t + rep * 256;
                int r = u >> 3, q = u & 7;
                size_t src = ((size_t)b * 64 + r) * NN + n1 + q * 8;
                kzh[rep] = *(const uint4*)(g_KZh + src);
                kzl[rep] = *(const uint4*)(g_KZl + src);
            }
            #pragma unroll
            for (int rep = 0; rep < 4; ++rep) {
                int u = t + rep * 256;
                int r = u >> 4, q = u & 15;
                ev[rep] = *(const uint4*)(g_E2 + ebase + (size_t)(n1 + r) * NN + m0 + q * 8);
            }
        }
        #pragma unroll
        for (int ks = 0; ks < 4; ++ks) {
            unsigned eb[4];
            ldsm4t(eb, eAddr + ks * 16 * 272);
            #pragma unroll
            for (int mt = 0; mt < 4; ++mt) {
                unsigned ah[4], al[4];
                ldsm4(ah, aAddrH + mt * 2304 + ks * 32);
                ldsm4(al, aAddrH + 9216 + mt * 2304 + ks * 32);
                #pragma unroll
                for (int nt = 0; nt < 2; ++nt) {
                    mma_bf16(c[mt][nt], ah, &eb[nt * 2]);
                    mma_bf16(c[mt][nt], al, &eb[nt * 2]);
                }
            }
        }
    }

    // epilogue: rows r = mt*16+g (+8), cols m = m0 + wid*16 + nt*8 + tig*2
    #pragma unroll
    for (int mt = 0; mt < 4; ++mt) {
        int r = mt * 16 + g;
        size_t r0 = ((size_t)(b * 128 + r)) * NN;
        size_t r1 = r0 + (size_t)8 * NN;
        #pragma unroll
        for (int nt = 0; nt < 2; ++nt) {
            int m = m0 + wid * 16 + nt * 8 + tig * 2;
            float2 v0 = {c[mt][nt][0], c[mt][nt][1]};
            float2 v1 = {c[mt][nt][2], c[mt][nt][3]};
            *(float2*)&g_osc[r0 + m] = v0;
            *(float2*)&g_osc[r1 + m] = v1;
        }
    }
}

// ---------------- channel Gram partials (32 chunks) ----------------
__global__ void __launch_bounds__(256) chan_gram() {
    int b = blockIdx.y;
    int chunk = blockIdx.x;
    int tx = threadIdx.x & 15, ty = threadIdx.x >> 4;
    __shared__ __align__(16) float Qc[64][68];
    __shared__ __align__(16) float Kc[64][68];
    ull acc2[4][2] = {};
    int ld_r = threadIdx.x >> 4;
    int ld_c = (threadIdx.x & 15) * 4;
    for (int sub = 0; sub < 2; ++sub) {
        int n0 = chunk * 128 + sub * 64;
        __syncthreads();
        #pragma unroll
        for (int k = 0; k < 4; ++k) {
            int r = ld_r + k * 16;
            float4 q = *(const float4*)&g_qk[((size_t)(b * 256 + 128 + r)) * NN + n0 + ld_c];
            Qc[ld_c + 0][r] = q.x; Qc[ld_c + 1][r] = q.y;
            Qc[ld_c + 2][r] = q.z; Qc[ld_c + 3][r] = q.w;
            float4 w = *(const float4*)&g_qk[((size_t)(b * 256 + 192 + r)) * NN + n0 + ld_c];
            Kc[ld_c + 0][r] = w.x; Kc[ld_c + 1][r] = w.y;
            Kc[ld_c + 2][r] = w.z; Kc[ld_c + 3][r] = w.w;
        }
        __syncthreads();
        #pragma unroll 8
        for (int n = 0; n < 64; ++n) {
            float4 q4 = *(float4*)&Qc[n][ty * 4];
            const ull* kp = (const ull*)&Kc[n][0];
            ull k0 = kp[tx * 2], k1 = kp[tx * 2 + 1];
            float qa[4] = {q4.x, q4.y, q4.z, q4.w};
            #pragma unroll
            for (int i = 0; i < 4; ++i) {
                ull qd = dup2(qa[i]);
                fma2(acc2[i][0], qd, k0);
                fma2(acc2[i][1], qd, k1);
            }
        }
    }
    #pragma unroll
    for (int i = 0; i < 4; ++i) {
        float o0, o1, o2, o3;
        unpack2(acc2[i][0], o0, o1);
        unpack2(acc2[i][1], o2, o3);
        float* dst = &g_Gp[(b * 32 + chunk) * 4096 + (ty * 4 + i) * 64 + tx * 4];
        dst[0] = o0; dst[1] = o1; dst[2] = o2; dst[3] = o3;
    }
}

__global__ void chan_softmax() {
    int r = blockIdx.x;
    int b = blockIdx.y;
    int s = threadIdx.x;
    __shared__ float red[64];
    float v = 0.f;
    #pragma unroll
    for (int ch = 0; ch < 32; ++ch)
        v += g_Gp[(b * 32 + ch) * 4096 + r * 64 + s];
    red[s] = v;
    __syncthreads();
    for (int off = 32; off >= 1; off >>= 1) {
        if (s < off) red[s] = fmaxf(red[s], red[s + off]);
        __syncthreads();
    }
    float mx = red[0];
    __syncthreads();
    float e = __expf(v - mx);
    red[s] = e;
    __syncthreads();
    for (int off = 32; off >= 1; off >>= 1) {
        if (s < off) red[s] += red[s + off];
        __syncthreads();
    }
    g_A[b * 4096 + r * 64 + s] = e / red[0];
}

__global__ void __launch_bounds__(256) chan_out() {
    int b = blockIdx.y;
    int p = blockIdx.x * 256 + threadIdx.x;
    __shared__ __align__(16) float As[64][64];
    #pragma unroll
    for (int k = 0; k < 16; ++k)
        (&As[0][0])[threadIdx.x + k * 256] = g_A[b * 4096 + threadIdx.x + k * 256];
    __syncthreads();
    float kreg[64];
    #pragma unroll
    for (int s = 0; s < 64; ++s)
        kreg[s] = g_qk[((size_t)(b * 256 + 192 + s)) * NN + p];
    ull kp2[32];
    #pragma unroll
    for (int s = 0; s < 32; ++s) {
        ull r; asm("mov.b64 %0, {%1, %2};" : "=l"(r) : "f"(kreg[2 * s]), "f"(kreg[2 * s + 1]));
        kp2[s] = r;
    }
    #pragma unroll 2
    for (int r = 0; r < 64; ++r) {
        ull acc = 0;
        const ull* arow = (const ull*)&As[r][0];
        #pragma unroll
        for (int s = 0; s < 32; ++s)
            fma2(acc, arow[s], kp2[s]);
        float lo, hi;
        unpack2(acc, lo, hi);
        g_osc[((size_t)(b * 128 + 64 + r)) * NN + p] = lo + hi;
    }
}

// ---------------- final GEMM (128x128 tile) ----------------
__global__ void __launch_bounds__(256, 2) final_gemm(float* __restrict__ out) {
    int b = blockIdx.z;
    int o0 = blockIdx.y * 128;
    int p0 = blockIdx.x * 128;
    int t = threadIdx.x, tx = t & 15, ty = t >> 4;
    __shared__ __align__(16) float As[16][132];
    __shared__ __align__(16) float Bs[16][128];
    ull acc2[8][4] = {};
    for (int step = 0; step < 8; ++step) {
        int t0 = step * 16;
        __syncthreads();
        #pragma unroll
        for (int i = 0; i < 2; ++i) {
            int l = t + i * 256;
            int oA = l & 127, tq = l >> 7;
            float4 v = *(const float4*)&g_Wc[(o0 + oA) * 128 + t0 + tq * 4];
            As[tq * 4 + 0][oA] = v.x;
            As[tq * 4 + 1][oA] = v.y;
            As[tq * 4 + 2][oA] = v.z;
            As[tq * 4 + 3][oA] = v.w;
            int cB = l >> 5, p4 = (l & 31) * 4;
            *(float4*)&Bs[cB][p4] =
                *(const float4*)&g_osc[((size_t)(b * 128 + t0 + cB)) * NN + p0 + p4];
        }
        __syncthreads();
        #pragma unroll
        for (int c = 0; c < 16; ++c) {
            ulonglong2 a0 = *(const ulonglong2*)&As[c][ty * 8];
            ulonglong2 a1 = *(const ulonglong2*)&As[c][ty * 8 + 4];
            ulonglong2 b0 = *(const ulonglong2*)&Bs[c][tx * 8];
            ulonglong2 b1 = *(const ulonglong2*)&Bs[c][tx * 8 + 4];
            float af[8];
            unpack2(a0.x, af[0], af[1]); unpack2(a0.y, af[2], af[3]);
            unpack2(a1.x, af[4], af[5]); unpack2(a1.y, af[6], af[7]);
            #pragma unroll
            for (int i = 0; i < 8; ++i) {
                ull ad = dup2(af[i]);
                fma2(acc2[i][0], ad, b0.x);
                fma2(acc2[i][1], ad, b0.y);
                fma2(acc2[i][2], ad, b1.x);
                fma2(acc2[i][3], ad, b1.y);
            }
        }
    }
    #pragma unroll
    for (int i = 0; i < 8; ++i) {
        int o = o0 + ty * 8 + i;
        float bias = g_bout[o];
        float of[8];
        unpack2(acc2[i][0], of[0], of[1]); unpack2(acc2[i][1], of[2], of[3]);
        unpack2(acc2[i][2], of[4], of[5]); unpack2(acc2[i][3], of[6], of[7]);
        float4 v0 = {of[0] + bias, of[1] + bias, of[2] + bias, of[3] + bias};
        float4 v1 = {of[4] + bias, of[5] + bias, of[6] + bias, of[7] + bias};
        size_t base = ((size_t)(b * 512 + o)) * NN + p0 + tx * 8;
        *(float4*)&out[base] = v0;
        *(float4*)&out[base + 4] = v1;
    }
}

// ---------------- launch ----------------
extern "C" void kernel_launch(void* const* d_in, const int* in_sizes, int n_in,
                              void* d_out, int out_size) {
    const float* top  = (const float*)d_in[0];
    const float* bot  = (const float*)d_in[1];
    const float* wt   = (const float*)d_in[2];
    const float* bt   = (const float*)d_in[3];
    const float* wb   = (const float*)d_in[4];
    const float* bb   = (const float*)d_in[5];
    const float* s_w1 = (const float*)d_in[6];
    const float* s_b1 = (const float*)d_in[7];
    const float* s_w2 = (const float*)d_in[8];
    const float* s_b2 = (const float*)d_in[9];
    const float* s_wo = (const float*)d_in[10];
    const float* s_bo = (const float*)d_in[11];
    const float* c_wq = (const float*)d_in[12];
    const float* c_bq = (const float*)d_in[13];
    const float* c_wk = (const float*)d_in[14];
    const float* c_bk = (const float*)d_in[15];
    const float* c_wo = (const float*)d_in[16];
    const float* c_bo = (const float*)d_in[17];
    const float* f_w  = (const float*)d_in[18];
    const float* f_b  = (const float*)d_in[19];
    float* out = (float*)d_out;

    cudaFuncSetAttribute(qk_tc2, cudaFuncAttributeMaxDynamicSharedMemorySize, QK2_SMEM);
    cudaFuncSetAttribute(passA_tc, cudaFuncAttributeMaxDynamicSharedMemorySize, PA_SMEM);
    cudaFuncSetAttribute(passB_tc, cudaFuncAttributeMaxDynamicSharedMemorySize, PB_SMEM);

    fold_qk<<<512, 256>>>(wt, wb, s_w1, s_w2, c_wq, c_wk);
    fold_out<<<256, 256>>>(f_w, s_wo, c_wo);
    fold_bias<<<1, 512>>>(bt, bb, s_b1, s_b2, c_bq, c_bk, f_w, s_bo, c_bo, f_b,
                          s_w1, s_w2, c_wq, c_wk);
    conv_w<<<1024, 256>>>();
    conv_x<<<dim3(128, 32, 8), dim3(32, 8)>>>(top, bot);
    qk_tc2<<<dim3(32, 2, 8), 256, QK2_SMEM>>>();
    conv_qk<<<dim3(128, 4, 8), dim3(32, 8)>>>();
    passA_tc<<<dim3(32, 8), 256, PA_SMEM>>>();
    conv_kz<<<dim3(16, 64, 8), 256>>>();
    passB_tc<<<dim3(32, 8), 256, PB_SMEM>>>();
    chan_gram<<<dim3(32, 8), 256>>>();
    chan_softmax<<<dim3(64, 8), 64>>>();
    chan_out<<<dim3(16, 8), 256>>>();
    final_gemm<<<dim3(32, 4, 8), 256>>>(out);
}

// round 8
// speedup vs baseline: 2.0961x; 1.1325x over previous
#include <cuda_runtime.h>
#include <cuda_bf16.h>
#include <stdint.h>
#include <math.h>

#define BB 8
#define NN 4096

typedef unsigned long long ull;

__device__ __forceinline__ ull dup2(float x) {
    ull r; asm("mov.b64 %0, {%1, %1};" : "=l"(r) : "f"(x)); return r;
}
__device__ __forceinline__ void unpack2(ull v, float& x, float& y) {
    asm("mov.b64 {%0, %1}, %2;" : "=f"(x), "=f"(y) : "l"(v));
}
__device__ __forceinline__ void fma2(ull& d, ull a, ull b) {
    asm("fma.rn.f32x2 %0, %1, %2, %0;" : "+l"(d) : "l"(a), "l"(b));
}

__device__ __forceinline__ unsigned smem_u32(const void* p) {
    unsigned a;
    asm("{ .reg .u64 t; cvta.to.shared.u64 t, %1; cvt.u32.u64 %0, t; }" : "=r"(a) : "l"(p));
    return a;
}
__device__ __forceinline__ void ldsm4(unsigned* r, unsigned addr) {
    asm volatile("ldmatrix.sync.aligned.m8n8.x4.shared.b16 {%0,%1,%2,%3}, [%4];"
        : "=r"(r[0]), "=r"(r[1]), "=r"(r[2]), "=r"(r[3]) : "r"(addr));
}
__device__ __forceinline__ void ldsm4t(unsigned* r, unsigned addr) {
    asm volatile("ldmatrix.sync.aligned.m8n8.x4.trans.shared.b16 {%0,%1,%2,%3}, [%4];"
        : "=r"(r[0]), "=r"(r[1]), "=r"(r[2]), "=r"(r[3]) : "r"(addr));
}
__device__ __forceinline__ void mma_bf16(float* c, const unsigned* a, const unsigned* b) {
    asm volatile("mma.sync.aligned.m16n8k16.row.col.f32.bf16.bf16.f32 "
        "{%0,%1,%2,%3}, {%4,%5,%6,%7}, {%8,%9}, {%0,%1,%2,%3};"
        : "+f"(c[0]), "+f"(c[1]), "+f"(c[2]), "+f"(c[3])
        : "r"(a[0]), "r"(a[1]), "r"(a[2]), "r"(a[3]), "r"(b[0]), "r"(b[1]));
}
__device__ __forceinline__ void cpa16(unsigned s, const void* g) {
    asm volatile("cp.async.ca.shared.global [%0], [%1], 16;" :: "r"(s), "l"(g));
}
#define CP_COMMIT() asm volatile("cp.async.commit_group;" ::: "memory")
#define CP_WAIT0() asm volatile("cp.async.wait_group 0;" ::: "memory")
#define CP_WAIT1() asm volatile("cp.async.wait_group 1;" ::: "memory")

// fast exp: poly exp2 on FMA pipe, no MUFU
__device__ __forceinline__ float fast_exp(float x) {
    float y = x * 1.4426950408889634f;
    float n = rintf(y);
    float f = y - n;
    float p = 1.3333558146e-3f;
    p = fmaf(p, f, 9.6181291076e-3f);
    p = fmaf(p, f, 5.5504108664e-2f);
    p = fmaf(p, f, 2.4022650696e-1f);
    p = fmaf(p, f, 6.9314718056e-1f);
    p = fmaf(p, f, 1.0f);
    int ni = (int)n;
    float s = __int_as_float((ni + 127) << 23);
    return p * s;
}

__device__ __forceinline__ void split_bf16(float v, __nv_bfloat16& h, __nv_bfloat16& l) {
    h = __float2bfloat16(v);
    l = __float2bfloat16(v - __bfloat162float(h));
}

// ---------------- scratch ----------------
__device__ float g_Wtop[256 * 512];
__device__ float g_Wbot[256 * 512];
__device__ float g_bqk[256];
__device__ float g_Wc[512 * 128];
__device__ float g_bout[512];
__device__ float g_qk[(size_t)BB * 256 * NN];
__device__ __nv_bfloat16 g_E2[(size_t)BB * NN * NN];
__device__ float g_Zinv[BB * NN];
__device__ float g_Gp[BB * 8 * 64 * 64];
__device__ float g_A[BB * 64 * 64];
__device__ __nv_bfloat16 g_Wh[256 * 1024];
__device__ __nv_bfloat16 g_Wl[256 * 1024];
__device__ __nv_bfloat16 g_Xh[(size_t)BB * NN * 1024];
__device__ __nv_bfloat16 g_Xl[(size_t)BB * NN * 1024];
__device__ __nv_bfloat16 g_QKTh[(size_t)BB * NN * 128];
__device__ __nv_bfloat16 g_QKTl[(size_t)BB * NN * 128];
__device__ __nv_bfloat16 g_KZh[(size_t)BB * 64 * NN];
__device__ __nv_bfloat16 g_KZl[(size_t)BB * 64 * NN];
__device__ __nv_bfloat16 g_OSh[(size_t)BB * 128 * NN];   // [b][t][p] t:0-63 out_s, 64-127 out_c
__device__ __nv_bfloat16 g_OSl[(size_t)BB * 128 * NN];
__device__ __nv_bfloat16 g_WCh[512 * 128];
__device__ __nv_bfloat16 g_WCl[512 * 128];
__device__ __nv_bfloat16 g_CH[(size_t)BB * 128 * NN];    // chan q2(0-63)/k2(64-127) bf16 hi
__device__ __nv_bfloat16 g_CL[(size_t)BB * 128 * NN];    // lo

// ---------------- weight folding ----------------
__global__ void fold_qk(const float* __restrict__ wt, const float* __restrict__ wb,
                        const float* __restrict__ sw1, const float* __restrict__ sw2,
                        const float* __restrict__ cwq, const float* __restrict__ cwk) {
    int idx = blockIdx.x * blockDim.x + threadIdx.x;
    int j = idx >> 9, c = idx & 511;
    const float* wrow; int uoff;
    if (j < 64)       { wrow = sw1 + j * 256;        uoff = 0;   }
    else if (j < 128) { wrow = sw2 + (j - 64) * 256; uoff = 0;   }
    else if (j < 192) { wrow = cwq + (j - 128) * 256; uoff = 256; }
    else              { wrow = cwk + (j - 192) * 256; uoff = 256; }
    float at = 0.f, ab = 0.f;
    #pragma unroll 8
    for (int u = 0; u < 256; ++u) {
        float w = wrow[u];
        at = fmaf(w, wt[(uoff + u) * 512 + c], at);
        ab = fmaf(w, wb[(uoff + u) * 512 + c], ab);
    }
    g_Wtop[idx] = at;
    g_Wbot[idx] = ab;
}

__global__ void fold_out(const float* __restrict__ fw, const float* __restrict__ swo,
                         const float* __restrict__ cwo) {
    int idx = blockIdx.x * blockDim.x + threadIdx.x;
    int o = idx >> 7, t = idx & 127;
    float acc = 0.f;
    if (t < 64) {
        #pragma unroll 8
        for (int u = 0; u < 256; ++u)
            acc = fmaf(fw[o * 512 + u], swo[u * 64 + t], acc);
    } else {
        int r = t - 64;
        #pragma unroll 8
        for (int u = 0; u < 256; ++u)
            acc = fmaf(fw[o * 512 + 256 + u], cwo[u * 64 + r], acc);
    }
    g_Wc[idx] = acc;
}

__global__ void fold_bias(const float* __restrict__ bt, const float* __restrict__ bb,
                          const float* __restrict__ sb1, const float* __restrict__ sb2,
                          const float* __restrict__ cbq, const float* __restrict__ cbk,
                          const float* __restrict__ fw,  const float* __restrict__ sbo,
                          const float* __restrict__ cbo, const float* __restrict__ fb,
                          const float* __restrict__ sw1, const float* __restrict__ sw2,
                          const float* __restrict__ cwq, const float* __restrict__ cwk) {
    int t = threadIdx.x;   // 512
    if (t < 256) {
        const float* wrow; int uoff; float ob;
        int j = t;
        if (j < 64)       { wrow = sw1 + j * 256;        uoff = 0;   ob = sb1[j];       }
        else if (j < 128) { wrow = sw2 + (j - 64) * 256; uoff = 0;   ob = sb2[j - 64];  }
        else if (j < 192) { wrow = cwq + (j - 128) * 256; uoff = 256; ob = cbq[j - 128]; }
        else              { wrow = cwk + (j - 192) * 256; uoff = 256; ob = cbk[j - 192]; }
        float s = ob;
        for (int u = 0; u < 256; ++u)
            s = fmaf(wrow[u], bt[uoff + u] + bb[uoff + u], s);
        g_bqk[j] = s;
    }
    float s2 = fb[t];
    for (int u = 0; u < 256; ++u) {
        s2 = fmaf(fw[t * 512 + u],       sbo[u], s2);
        s2 = fmaf(fw[t * 512 + 256 + u], cbo[u], s2);
    }
    g_bout[t] = s2;
}

// ---------------- converts ----------------
__global__ void conv_w() {
    int idx = blockIdx.x * 256 + threadIdx.x;
    int j = idx >> 10, c = idx & 1023;
    float v = (c < 512) ? g_Wtop[j * 512 + c] : g_Wbot[j * 512 + c - 512];
    __nv_bfloat16 h, l; split_bf16(v, h, l);
    g_Wh[idx] = h; g_Wl[idx] = l;
}

__global__ void conv_wc() {
    int idx = blockIdx.x * 256 + threadIdx.x;   // 65536
    __nv_bfloat16 h, l; split_bf16(g_Wc[idx], h, l);
    g_WCh[idx] = h; g_WCl[idx] = l;
}

__global__ void conv_cq() {   // g_qk rows 128-255 -> bf16 hi/lo row-major
    size_t idx = (size_t)blockIdx.x * 256 + threadIdx.x;   // 4194304
    int b = (int)(idx >> 19);
    size_t rem = idx & ((1u << 19) - 1);   // j*4096 + n
    float v = g_qk[((size_t)b * 256 + 128) * NN + rem];
    __nv_bfloat16 h, l; split_bf16(v, h, l);
    g_CH[((size_t)b * 128) * NN + rem] = h;
    g_CL[((size_t)b * 128) * NN + rem] = l;
}

__global__ void conv_x(const float* __restrict__ top, const float* __restrict__ bot) {
    __shared__ float sh[32][33];
    int b = blockIdx.z;
    int c0 = blockIdx.y * 32;
    int p0 = blockIdx.x * 32;
    const float* src = (c0 < 512) ? top : bot;
    int cs = c0 & 511;
    int tx = threadIdx.x, ty = threadIdx.y;
    #pragma unroll
    for (int k = 0; k < 4; ++k) {
        int i = ty + k * 8;
        sh[i][tx] = src[((size_t)(b * 512 + cs + i)) * NN + p0 + tx];
    }
    __syncthreads();
    #pragma unroll
    for (int k = 0; k < 4; ++k) {
        int i = ty + k * 8;
        float v = sh[tx][i];
        __nv_bfloat16 h, l; split_bf16(v, h, l);
        size_t o = ((size_t)(b * NN + p0 + i)) * 1024 + c0 + tx;
        g_Xh[o] = h; g_Xl[o] = l;
    }
}

// ---------------- qk GEMM via HMMA + cp.async double buffer ----------------
#define TS (128 * 72 * 2)
#define QK3_SMEM (8 * TS)
__global__ void __launch_bounds__(256) qk_tc3() {
    extern __shared__ __align__(16) char smem[];
    unsigned sb = smem_u32(smem);
    int t = threadIdx.x;
    int wid = t >> 5, lid = t & 31;
    int b = blockIdx.z;
    int j0 = blockIdx.y * 128;
    int p0 = blockIdx.x * 128;
    int wr = wid & 1;
    int wc = wid >> 1;

    const __nv_bfloat16* srcs[4] = {
        g_Wh + (size_t)j0 * 1024,
        g_Wl + (size_t)j0 * 1024,
        g_Xh + ((size_t)b * NN + p0) * 1024,
        g_Xl + ((size_t)b * NN + p0) * 1024
    };

    float c[4][4][4] = {};

    // prologue: chunk 0 -> buffer 0
    {
        #pragma unroll
        for (int tile = 0; tile < 4; ++tile) {
            unsigned base = sb + tile * TS;
            const __nv_bfloat16* s = srcs[tile];
            #pragma unroll
            for (int rep = 0; rep < 4; ++rep) {
                int u = t + rep * 256;
                int r = u >> 3, q = u & 7;
                cpa16(base + r * 144 + q * 16, s + (size_t)r * 1024 + q * 8);
            }
        }
        CP_COMMIT();
    }

    for (int ch = 0; ch < 16; ++ch) {
        if (ch + 1 < 16) {
            unsigned boff = ((ch + 1) & 1) * (4 * TS);
            int c0 = (ch + 1) * 64;
            #pragma unroll
            for (int tile = 0; tile < 4; ++tile) {
                unsigned base = sb + boff + tile * TS;
                const __nv_bfloat16* s = srcs[tile];
                #pragma unroll
                for (int rep = 0; rep < 4; ++rep) {
                    int u = t + rep * 256;
                    int r = u >> 3, q = u & 7;
                    cpa16(base + r * 144 + q * 16, s + (size_t)r * 1024 + c0 + q * 8);
                }
            }
            CP_COMMIT();
            CP_WAIT1();
        } else {
            CP_WAIT0();
        }
        __syncthreads();
        unsigned abase = sb + (ch & 1) * (4 * TS);
        unsigned aAddr = abase + (unsigned)((wr * 64 + (lid & 15)) * 144 + (lid >> 4) * 16);
        unsigned bAddr = abase + 2 * TS +
            (unsigned)((wc * 32 + ((lid >> 4) & 1) * 8 + (lid & 7)) * 144 + ((lid >> 3) & 1) * 16);
        #pragma unroll
        for (int ks = 0; ks < 4; ++ks) {
            unsigned bh[2][4], bl[2][4];
            ldsm4(bh[0], bAddr + ks * 32);
            ldsm4(bh[1], bAddr + 16 * 144 + ks * 32);
            ldsm4(bl[0], bAddr + TS + ks * 32);
            ldsm4(bl[1], bAddr + TS + 16 * 144 + ks * 32);
            #pragma unroll
            for (int mt = 0; mt < 4; ++mt) {
                unsigned ah[4], al[4];
                ldsm4(ah, aAddr + mt * 2304 + ks * 32);
                ldsm4(al, aAddr + TS + mt * 2304 + ks * 32);
                #pragma unroll
                for (int nt = 0; nt < 4; ++nt) {
                    const unsigned* bhp = &bh[nt >> 1][(nt & 1) * 2];
                    const unsigned* blp = &bl[nt >> 1][(nt & 1) * 2];
                    mma_bf16(c[mt][nt], ah, bhp);
                    mma_bf16(c[mt][nt], ah, blp);
                    mma_bf16(c[mt][nt], al, bhp);
                }
            }
        }
        __syncthreads();
    }

    int g = lid >> 2, tig = lid & 3;
    #pragma unroll
    for (int mt = 0; mt < 4; ++mt) {
        int jrow0 = j0 + wr * 64 + mt * 16 + g;
        float b0 = g_bqk[jrow0], b1 = g_bqk[jrow0 + 8];
        size_t r0 = ((size_t)(b * 256 + jrow0)) * NN;
        size_t r1 = r0 + (size_t)8 * NN;
        #pragma unroll
        for (int nt = 0; nt < 4; ++nt) {
            int pc = p0 + wc * 32 + nt * 8 + tig * 2;
            float2 v0 = {c[mt][nt][0] + b0, c[mt][nt][1] + b0};
            float2 v1 = {c[mt][nt][2] + b1, c[mt][nt][3] + b1};
            *(float2*)&g_qk[r0 + pc] = v0;
            *(float2*)&g_qk[r1 + pc] = v1;
        }
    }
}

// ---------------- transpose q1/k1 rows to [p][j] bf16 hi/lo ----------------
__global__ void conv_qk() {
    __shared__ float sh[32][33];
    int b = blockIdx.z;
    int j0 = blockIdx.y * 32;
    int p0 = blockIdx.x * 32;
    int tx = threadIdx.x, ty = threadIdx.y;
    #pragma unroll
    for (int k = 0; k < 4; ++k) {
        int i = ty + k * 8;
        sh[i][tx] = g_qk[((size_t)(b * 256 + j0 + i)) * NN + p0 + tx];
    }
    __syncthreads();
    #pragma unroll
    for (int k = 0; k < 4; ++k) {
        int i = ty + k * 8;
        float v = sh[tx][i];
        __nv_bfloat16 h, l; split_bf16(v, h, l);
        size_t o = ((size_t)(b * NN + p0 + i)) * 128 + j0 + tx;
        g_QKTh[o] = h; g_QKTl[o] = l;
    }
}

// ---------------- spatial pass A via HMMA ----------------
#define PAT (128 * 72 * 2)
#define PA_SMEM (4 * PAT + 2048)
__global__ void __launch_bounds__(256) passA_tc() {
    extern __shared__ __align__(16) char smem[];
    unsigned sb = smem_u32(smem);
    int t = threadIdx.x;
    int wid = t >> 5, lid = t & 31;
    int b = blockIdx.y;
    int n0 = blockIdx.x * 128;
    int wr = wid & 1;
    int wc = wid >> 1;
    int g = lid >> 2, tig = lid & 3;

    #pragma unroll
    for (int rep = 0; rep < 4; ++rep) {
        int u = t + rep * 256;
        int r = u >> 3, q = u & 7;
        size_t src = ((size_t)b * NN + n0 + r) * 128 + q * 8;
        *(uint4*)(smem + r * 144 + q * 16) = *(const uint4*)(g_QKTh + src);
        *(uint4*)(smem + PAT + r * 144 + q * 16) = *(const uint4*)(g_QKTl + src);
    }

    unsigned aAddrH = sb + (unsigned)((wr * 64 + (lid & 15)) * 144 + (lid >> 4) * 16);
    unsigned bAddrH = sb + 2 * PAT +
        (unsigned)((wc * 32 + ((lid >> 4) & 1) * 8 + (lid & 7)) * 144 + ((lid >> 3) & 1) * 16);

    float zacc[8] = {};
    size_t ebase = ((size_t)b) << 24;

    uint4 ph[4], pl[4];
    {
        #pragma unroll
        for (int rep = 0; rep < 4; ++rep) {
            int u = t + rep * 256;
            int r = u >> 3, q = u & 7;
            size_t src = ((size_t)b * NN + r) * 128 + 64 + q * 8;
            ph[rep] = *(const uint4*)(g_QKTh + src);
            pl[rep] = *(const uint4*)(g_QKTl + src);
        }
    }

    for (int ch = 0; ch < 32; ++ch) {
        int m0 = ch * 128;
        __syncthreads();
        #pragma unroll
        for (int rep = 0; rep < 4; ++rep) {
            int u = t + rep * 256;
            int r = u >> 3, q = u & 7;
            *(uint4*)(smem + 2 * PAT + r * 144 + q * 16) = ph[rep];
            *(uint4*)(smem + 3 * PAT + r * 144 + q * 16) = pl[rep];
        }
        __syncthreads();
        if (ch + 1 < 32) {
            int m1 = (ch + 1) * 128;
            #pragma unroll
            for (int rep = 0; rep < 4; ++rep) {
                int u = t + rep * 256;
                int r = u >> 3, q = u & 7;
                size_t src = ((size_t)b * NN + m1 + r) * 128 + 64 + q * 8;
                ph[rep] = *(const uint4*)(g_QKTh + src);
                pl[rep] = *(const uint4*)(g_QKTl + src);
            }
        }
        float c[4][4][4] = {};
        #pragma unroll
        for (int ks = 0; ks < 4; ++ks) {
            unsigned bh[2][4], bl[2][4];
            ldsm4(bh[0], bAddrH + ks * 32);
            ldsm4(bh[1], bAddrH + 16 * 144 + ks * 32);
            ldsm4(bl[0], bAddrH + PAT + ks * 32);
            ldsm4(bl[1], bAddrH + PAT + 16 * 144 + ks * 32);
            #pragma unroll
            for (int mt = 0; mt < 4; ++mt) {
                unsigned ah[4], al[4];
                ldsm4(ah, aAddrH + mt * 2304 + ks * 32);
                ldsm4(al, aAddrH + PAT + mt * 2304 + ks * 32);
                #pragma unroll
                for (int nt = 0; nt < 4; ++nt) {
                    const unsigned* bhp = &bh[nt >> 1][(nt & 1) * 2];
                    const unsigned* blp = &bl[nt >> 1][(nt & 1) * 2];
                    mma_bf16(c[mt][nt], ah, bhp);
                    mma_bf16(c[mt][nt], ah, blp);
                    mma_bf16(c[mt][nt], al, bhp);
                }
            }
        }
        #pragma unroll
        for (int mt = 0; mt < 4; ++mt) {
            int n = n0 + wr * 64 + mt * 16 + g;
            #pragma unroll
            for (int nt = 0; nt < 4; ++nt) {
                int m = m0 + wc * 32 + nt * 8 + tig * 2;
                float e0 = fast_exp(c[mt][nt][0]);
                float e1 = fast_exp(c[mt][nt][1]);
                float e2 = fast_exp(c[mt][nt][2]);
                float e3 = fast_exp(c[mt][nt][3]);
                __nv_bfloat162 v0 = {__float2bfloat16(e0), __float2bfloat16(e1)};
                __nv_bfloat162 v1 = {__float2bfloat16(e2), __float2bfloat16(e3)};
                *(__nv_bfloat162*)&g_E2[ebase + (size_t)n * NN + m] = v0;
                *(__nv_bfloat162*)&g_E2[ebase + (size_t)(n + 8) * NN + m] = v1;
                zacc[mt * 2] += e0 + e1;
                zacc[mt * 2 + 1] += e2 + e3;
            }
        }
    }

    float* zp = (float*)(smem + 4 * PAT);
    #pragma unroll
    for (int s = 0; s < 8; ++s) {
        float v = zacc[s];
        v += __shfl_xor_sync(0xFFFFFFFF, v, 1);
        v += __shfl_xor_sync(0xFFFFFFFF, v, 2);
        if (tig == 0)
            zp[wc * 128 + wr * 64 + (s >> 1) * 16 + (s & 1) * 8 + g] = v;
    }
    __syncthreads();
    if (t < 128) {
        float s = zp[t] + zp[128 + t] + zp[256 + t] + zp[384 + t];
        g_Zinv[b * NN + n0 + t] = 1.0f / s;
    }
}

// ---------------- Kz = k1 * Zinv -> bf16 hi/lo ----------------
__global__ void conv_kz() {
    int n = blockIdx.x * 256 + threadIdx.x;
    int r = blockIdx.y;
    int b = blockIdx.z;
    float v = g_qk[((size_t)(b * 256 + 64 + r)) * NN + n] * g_Zinv[b * NN + n];
    __nv_bfloat16 h, l; split_bf16(v, h, l);
    size_t o = ((size_t)b * 64 + r) * NN + n;
    g_KZh[o] = h; g_KZl[o] = l;
}

// ---------------- spatial pass B via HMMA: writes OS bf16 hi/lo ----------------
#define PB_SMEM (2 * 9216 + 64 * 272)
__global__ void __launch_bounds__(256) passB_tc() {
    extern __shared__ __align__(16) char smem[];
    unsigned sb = smem_u32(smem);
    int t = threadIdx.x;
    int wid = t >> 5, lid = t & 31;
    int b = blockIdx.y;
    int m0 = blockIdx.x * 128;
    int g = lid >> 2, tig = lid & 3;

    unsigned aAddrH = sb + (unsigned)(((lid & 15)) * 144 + (lid >> 4) * 16);
    unsigned eAddr = sb + 18432 +
        (unsigned)(((lid & 7) + ((lid >> 3) & 1) * 8) * 272 + (wid * 16 + (lid >> 4) * 8) * 2);

    float c[4][2][4] = {};
    size_t ebase = ((size_t)b) << 24;

    uint4 kzh[2], kzl[2], ev[4];
    {
        #pragma unroll
        for (int rep = 0; rep < 2; ++rep) {
            int u = t + rep * 256;
            int r = u >> 3, q = u & 7;
            size_t src = ((size_t)b * 64 + r) * NN + q * 8;
            kzh[rep] = *(const uint4*)(g_KZh + src);
            kzl[rep] = *(const uint4*)(g_KZl + src);
        }
        #pragma unroll
        for (int rep = 0; rep < 4; ++rep) {
            int u = t + rep * 256;
            int r = u >> 4, q = u & 15;
            ev[rep] = *(const uint4*)(g_E2 + ebase + (size_t)r * NN + m0 + q * 8);
        }
    }

    for (int ch = 0; ch < 64; ++ch) {
        __syncthreads();
        #pragma unroll
        for (int rep = 0; rep < 2; ++rep) {
            int u = t + rep * 256;
            int r = u >> 3, q = u & 7;
            *(uint4*)(smem + r * 144 + q * 16) = kzh[rep];
            *(uint4*)(smem + 9216 + r * 144 + q * 16) = kzl[rep];
        }
        #pragma unroll
        for (int rep = 0; rep < 4; ++rep) {
            int u = t + rep * 256;
            int r = u >> 4, q = u & 15;
            *(uint4*)(smem + 18432 + r * 272 + q * 16) = ev[rep];
        }
        __syncthreads();
        if (ch + 1 < 64) {
            int n1 = (ch + 1) * 64;
            #pragma unroll
            for (int rep = 0; rep < 2; ++rep) {
                int u = t + rep * 256;
                int r = u >> 3, q = u & 7;
                size_t src = ((size_t)b * 64 + r) * NN + n1 + q * 8;
                kzh[rep] = *(const uint4*)(g_KZh + src);
                kzl[rep] = *(const uint4*)(g_KZl + src);
            }
            #pragma unroll
            for (int rep = 0; rep < 4; ++rep) {
                int u = t + rep * 256;
                int r = u >> 4, q = u & 15;
                ev[rep] = *(const uint4*)(g_E2 + ebase + (size_t)(n1 + r) * NN + m0 + q * 8);
            }
        }
        #pragma unroll
        for (int ks = 0; ks < 4; ++ks) {
            unsigned eb[4];
            ldsm4t(eb, eAddr + ks * 16 * 272);
            #pragma unroll
            for (int mt = 0; mt < 4; ++mt) {
                unsigned ah[4], al[4];
                ldsm4(ah, aAddrH + mt * 2304 + ks * 32);
                ldsm4(al, aAddrH + 9216 + mt * 2304 + ks * 32);
                #pragma unroll
                for (int nt = 0; nt < 2; ++nt) {
                    mma_bf16(c[mt][nt], ah, &eb[nt * 2]);
                    mma_bf16(c[mt][nt], al, &eb[nt * 2]);
                }
            }
        }
    }

    #pragma unroll
    for (int mt = 0; mt < 4; ++mt) {
        int r = mt * 16 + g;
        size_t r0 = ((size_t)(b * 128 + r)) * NN;
        size_t r1 = r0 + (size_t)8 * NN;
        #pragma unroll
        for (int nt = 0; nt < 2; ++nt) {
            int m = m0 + wid * 16 + nt * 8 + tig * 2;
            __nv_bfloat16 h0, l0, h1, l1;
            split_bf16(c[mt][nt][0], h0, l0);
            split_bf16(c[mt][nt][1], h1, l1);
            *(__nv_bfloat162*)&g_OSh[r0 + m] = {h0, h1};
            *(__nv_bfloat162*)&g_OSl[r0 + m] = {l0, l1};
            split_bf16(c[mt][nt][2], h0, l0);
            split_bf16(c[mt][nt][3], h1, l1);
            *(__nv_bfloat162*)&g_OSh[r1 + m] = {h0, h1};
            *(__nv_bfloat162*)&g_OSl[r1 + m] = {l0, l1};
        }
    }
}

// ---------------- channel Gram via HMMA (8 chunks of 512 n) ----------------
__global__ void __launch_bounds__(128) chan_gram_tc() {
    __shared__ __align__(16) char csm[4 * 9216];   // Qh Ql Kh Kl: [64][64] bf16, row 144B
    unsigned sb = smem_u32(csm);
    int t = threadIdx.x;
    int wid = t >> 5, lid = t & 31;
    int b = blockIdx.y;
    int chunk = blockIdx.x;   // 0..7
    int wr = wid & 1, wc = wid >> 1;
    int g = lid >> 2, tig = lid & 3;

    unsigned aAddr = sb + (unsigned)((wr * 32 + (lid & 15)) * 144 + (lid >> 4) * 16);
    unsigned bAddr = sb + 2 * 9216 +
        (unsigned)((wc * 32 + ((lid >> 4) & 1) * 8 + (lid & 7)) * 144 + ((lid >> 3) & 1) * 16);

    float c[2][4][4] = {};

    for (int sub = 0; sub < 8; ++sub) {
        int n0 = chunk * 512 + sub * 64;
        __syncthreads();
        #pragma unroll
        for (int rep = 0; rep < 4; ++rep) {
            int u = t + rep * 128;
            int r = u >> 3, q = u & 7;
            size_t sq = ((size_t)(b * 128 + r)) * NN + n0 + q * 8;        // q2 rows 0-63
            size_t sk = ((size_t)(b * 128 + 64 + r)) * NN + n0 + q * 8;   // k2 rows 64-127
            *(uint4*)(csm + r * 144 + q * 16) = *(const uint4*)(g_CH + sq);
            *(uint4*)(csm + 9216 + r * 144 + q * 16) = *(const uint4*)(g_CL + sq);
            *(uint4*)(csm + 2 * 9216 + r * 144 + q * 16) = *(const uint4*)(g_CH + sk);
            *(uint4*)(csm + 3 * 9216 + r * 144 + q * 16) = *(const uint4*)(g_CL + sk);
        }
        __syncthreads();
        #pragma unroll
        for (int ks = 0; ks < 4; ++ks) {
            unsigned bh[2][4], bl[2][4];
            ldsm4(bh[0], bAddr + ks * 32);
            ldsm4(bh[1], bAddr + 16 * 144 + ks * 32);
            ldsm4(bl[0], bAddr + 9216 + ks * 32);
            ldsm4(bl[1], bAddr + 9216 + 16 * 144 + ks * 32);
            #pragma unroll
            for (int mt = 0; mt < 2; ++mt) {
                unsigned ah[4], al[4];
                ldsm4(ah, aAddr + mt * 2304 + ks * 32);
                ldsm4(al, aAddr + 9216 + mt * 2304 + ks * 32);
                #pragma unroll
                for (int nt = 0; nt < 4; ++nt) {
                    const unsigned* bhp = &bh[nt >> 1][(nt & 1) * 2];
                    const unsigned* blp = &bl[nt >> 1][(nt & 1) * 2];
                    mma_bf16(c[mt][nt], ah, bhp);
                    mma_bf16(c[mt][nt], ah, blp);
                    mma_bf16(c[mt][nt], al, bhp);
                }
            }
        }
    }

    float* gp = &g_Gp[(b * 8 + chunk) * 4096];
    #pragma unroll
    for (int mt = 0; mt < 2; ++mt) {
        int r = wr * 32 + mt * 16 + g;
        #pragma unroll
        for (int nt = 0; nt < 4; ++nt) {
            int s = wc * 32 + nt * 8 + tig * 2;
            *(float2*)&gp[r * 64 + s] = {c[mt][nt][0], c[mt][nt][1]};
            *(float2*)&gp[(r + 8) * 64 + s] = {c[mt][nt][2], c[mt][nt][3]};
        }
    }
}

__global__ void chan_softmax() {
    int r = blockIdx.x;
    int b = blockIdx.y;
    int s = threadIdx.x;
    __shared__ float red[64];
    float v = 0.f;
    #pragma unroll
    for (int ch = 0; ch < 8; ++ch)
        v += g_Gp[(b * 8 + ch) * 4096 + r * 64 + s];
    red[s] = v;
    __syncthreads();
    for (int off = 32; off >= 1; off >>= 1) {
        if (s < off) red[s] = fmaxf(red[s], red[s + off]);
        __syncthreads();
    }
    float mx = red[0];
    __syncthreads();
    float e = __expf(v - mx);
    red[s] = e;
    __syncthreads();
    for (int off = 32; off >= 1; off >>= 1) {
        if (s < off) red[s] += red[s + off];
        __syncthreads();
    }
    g_A[b * 4096 + r * 64 + s] = e / red[0];
}

__global__ void __launch_bounds__(256) chan_out() {
    int b = blockIdx.y;
    int p = blockIdx.x * 256 + threadIdx.x;
    __shared__ __align__(16) float As[64][64];
    #pragma unroll
    for (int k = 0; k < 16; ++k)
        (&As[0][0])[threadIdx.x + k * 256] = g_A[b * 4096 + threadIdx.x + k * 256];
    __syncthreads();
    float kreg[64];
    #pragma unroll
    for (int s = 0; s < 64; ++s)
        kreg[s] = g_qk[((size_t)(b * 256 + 192 + s)) * NN + p];
    ull kp2[32];
    #pragma unroll
    for (int s = 0; s < 32; ++s) {
        ull r; asm("mov.b64 %0, {%1, %2};" : "=l"(r) : "f"(kreg[2 * s]), "f"(kreg[2 * s + 1]));
        kp2[s] = r;
    }
    #pragma unroll 2
    for (int r = 0; r < 64; ++r) {
        ull acc = 0;
        const ull* arow = (const ull*)&As[r][0];
        #pragma unroll
        for (int s = 0; s < 32; ++s)
            fma2(acc, arow[s], kp2[s]);
        float lo, hi;
        unpack2(acc, lo, hi);
        float v = lo + hi;
        __nv_bfloat16 h, l; split_bf16(v, h, l);
        size_t o = ((size_t)(b * 128 + 64 + r)) * NN + p;
        g_OSh[o] = h; g_OSl[o] = l;
    }
}

// ---------------- final GEMM via HMMA (3-pass) ----------------
// smem: WCh[0,34816) WCl[34816,69632) OSh[69632,104448) OSl[104448,139264)
#define FT_SMEM 139264
__global__ void __launch_bounds__(256) final_tc(float* __restrict__ out) {
    extern __shared__ __align__(16) char smem[];
    unsigned sb = smem_u32(smem);
    int t = threadIdx.x;
    int wid = t >> 5, lid = t & 31;
    int b = blockIdx.z;
    int o0 = blockIdx.y * 128;
    int p0 = blockIdx.x * 128;
    int wr = wid & 1, wc = wid >> 1;
    int g = lid >> 2, tig = lid & 3;

    // load A (Wc) [128 o][128 t] and B (OS) [128 t][128 p]
    #pragma unroll
    for (int rep = 0; rep < 8; ++rep) {
        int u = t + rep * 256;
        int r = u >> 4, q = u & 15;
        *(uint4*)(smem + r * 272 + q * 16) = *(const uint4*)(g_WCh + (size_t)(o0 + r) * 128 + q * 8);
        *(uint4*)(smem + 34816 + r * 272 + q * 16) = *(const uint4*)(g_WCl + (size_t)(o0 + r) * 128 + q * 8);
        size_t bs = ((size_t)(b * 128 + r)) * NN + p0 + q * 8;
        *(uint4*)(smem + 69632 + r * 272 + q * 16) = *(const uint4*)(g_OSh + bs);
        *(uint4*)(smem + 104448 + r * 272 + q * 16) = *(const uint4*)(g_OSl + bs);
    }
    __syncthreads();

    unsigned aAddr = sb + (unsigned)((wr * 64 + (lid & 15)) * 272 + (lid >> 4) * 16);
    unsigned eAddr = sb + 69632 +
        (unsigned)(((lid & 7) + ((lid >> 3) & 1) * 8) * 272 + (wc * 32 + (lid >> 4) * 8) * 2);

    float c[4][4][4] = {};
    #pragma unroll
    for (int ks = 0; ks < 8; ++ks) {
        unsigned bh[2][4], bl[2][4];
        ldsm4t(bh[0], eAddr + ks * 16 * 272);
        ldsm4t(bh[1], eAddr + ks * 16 * 272 + 32);
        ldsm4t(bl[0], eAddr + 34816 + ks * 16 * 272);
        ldsm4t(bl[1], eAddr + 34816 + ks * 16 * 272 + 32);
        #pragma unroll
        for (int mt = 0; mt < 4; ++mt) {
            unsigned ah[4], al[4];
            ldsm4(ah, aAddr + mt * 16 * 272 + ks * 32);
            ldsm4(al, aAddr + 34816 + mt * 16 * 272 + ks * 32);
            #pragma unroll
            for (int nt = 0; nt < 4; ++nt) {
                const unsigned* bhp = &bh[nt >> 1][(nt & 1) * 2];
                const unsigned* blp = &bl[nt >> 1][(nt & 1) * 2];
                mma_bf16(c[mt][nt], ah, bhp);
                mma_bf16(c[mt][nt], ah, blp);
                mma_bf16(c[mt][nt], al, bhp);
            }
        }
    }

    #pragma unroll
    for (int mt = 0; mt < 4; ++mt) {
        int o = o0 + wr * 64 + mt * 16 + g;
        float b0 = g_bout[o], b1 = g_bout[o + 8];
        size_t r0 = ((size_t)(b * 512 + o)) * NN;
        size_t r1 = r0 + (size_t)8 * NN;
        #pragma unroll
        for (int nt = 0; nt < 4; ++nt) {
            int pc = p0 + wc * 32 + nt * 8 + tig * 2;
            float2 v0 = {c[mt][nt][0] + b0, c[mt][nt][1] + b0};
            float2 v1 = {c[mt][nt][2] + b1, c[mt][nt][3] + b1};
            *(float2*)&out[r0 + pc] = v0;
            *(float2*)&out[r1 + pc] = v1;
        }
    }
}

// ---------------- launch ----------------
extern "C" void kernel_launch(void* const* d_in, const int* in_sizes, int n_in,
                              void* d_out, int out_size) {
    const float* top  = (const float*)d_in[0];
    const float* bot  = (const float*)d_in[1];
    const float* wt   = (const float*)d_in[2];
    const float* bt   = (const float*)d_in[3];
    const float* wb   = (const float*)d_in[4];
    const float* bb   = (const float*)d_in[5];
    const float* s_w1 = (const float*)d_in[6];
    const float* s_b1 = (const float*)d_in[7];
    const float* s_w2 = (const float*)d_in[8];
    const float* s_b2 = (const float*)d_in[9];
    const float* s_wo = (const float*)d_in[10];
    const float* s_bo = (const float*)d_in[11];
    const float* c_wq = (const float*)d_in[12];
    const float* c_bq = (const float*)d_in[13];
    const float* c_wk = (const float*)d_in[14];
    const float* c_bk = (const float*)d_in[15];
    const float* c_wo = (const float*)d_in[16];
    const float* c_bo = (const float*)d_in[17];
    const float* f_w  = (const float*)d_in[18];
    const float* f_b  = (const float*)d_in[19];
    float* out = (float*)d_out;

    cudaFuncSetAttribute(qk_tc3, cudaFuncAttributeMaxDynamicSharedMemorySize, QK3_SMEM);
    cudaFuncSetAttribute(passA_tc, cudaFuncAttributeMaxDynamicSharedMemorySize, PA_SMEM);
    cudaFuncSetAttribute(passB_tc, cudaFuncAttributeMaxDynamicSharedMemorySize, PB_SMEM);
    cudaFuncSetAttribute(final_tc, cudaFuncAttributeMaxDynamicSharedMemorySize, FT_SMEM);

    fold_qk<<<512, 256>>>(wt, wb, s_w1, s_w2, c_wq, c_wk);
    fold_out<<<256, 256>>>(f_w, s_wo, c_wo);
    fold_bias<<<1, 512>>>(bt, bb, s_b1, s_b2, c_bq, c_bk, f_w, s_bo, c_bo, f_b,
                          s_w1, s_w2, c_wq, c_wk);
    conv_w<<<1024, 256>>>();
    conv_wc<<<256, 256>>>();
    conv_x<<<dim3(128, 32, 8), dim3(32, 8)>>>(top, bot);
    qk_tc3<<<dim3(32, 2, 8), 256, QK3_SMEM>>>();
    conv_qk<<<dim3(128, 4, 8), dim3(32, 8)>>>();
    conv_cq<<<16384, 256>>>();
    passA_tc<<<dim3(32, 8), 256, PA_SMEM>>>();
    conv_kz<<<dim3(16, 64, 8), 256>>>();
    passB_tc<<<dim3(32, 8), 256, PB_SMEM>>>();
    chan_gram_tc<<<dim3(8, 8), 128>>>();
    chan_softmax<<<dim3(64, 8), 64>>>();
    chan_out<<<dim3(16, 8), 256>>>();
    final_tc<<<dim3(32, 4, 8), 256, FT_SMEM>>>(out);
}

// round 9
// speedup vs baseline: 2.2234x; 1.0607x over previous
#include <cuda_runtime.h>
#include <cuda_bf16.h>
#include <stdint.h>
#include <math.h>

#define BB 8
#define NN 4096

typedef unsigned long long ull;

__device__ __forceinline__ ull dup2(float x) {
    ull r; asm("mov.b64 %0, {%1, %1};" : "=l"(r) : "f"(x)); return r;
}
__device__ __forceinline__ void unpack2(ull v, float& x, float& y) {
    asm("mov.b64 {%0, %1}, %2;" : "=f"(x), "=f"(y) : "l"(v));
}
__device__ __forceinline__ void fma2(ull& d, ull a, ull b) {
    asm("fma.rn.f32x2 %0, %1, %2, %0;" : "+l"(d) : "l"(a), "l"(b));
}

__device__ __forceinline__ unsigned smem_u32(const void* p) {
    unsigned a;
    asm("{ .reg .u64 t; cvta.to.shared.u64 t, %1; cvt.u32.u64 %0, t; }" : "=r"(a) : "l"(p));
    return a;
}
__device__ __forceinline__ void ldsm4(unsigned* r, unsigned addr) {
    asm volatile("ldmatrix.sync.aligned.m8n8.x4.shared.b16 {%0,%1,%2,%3}, [%4];"
        : "=r"(r[0]), "=r"(r[1]), "=r"(r[2]), "=r"(r[3]) : "r"(addr));
}
__device__ __forceinline__ void ldsm4t(unsigned* r, unsigned addr) {
    asm volatile("ldmatrix.sync.aligned.m8n8.x4.trans.shared.b16 {%0,%1,%2,%3}, [%4];"
        : "=r"(r[0]), "=r"(r[1]), "=r"(r[2]), "=r"(r[3]) : "r"(addr));
}
__device__ __forceinline__ void mma_bf16(float* c, const unsigned* a, const unsigned* b) {
    asm volatile("mma.sync.aligned.m16n8k16.row.col.f32.bf16.bf16.f32 "
        "{%0,%1,%2,%3}, {%4,%5,%6,%7}, {%8,%9}, {%0,%1,%2,%3};"
        : "+f"(c[0]), "+f"(c[1]), "+f"(c[2]), "+f"(c[3])
        : "r"(a[0]), "r"(a[1]), "r"(a[2]), "r"(a[3]), "r"(b[0]), "r"(b[1]));
}
__device__ __forceinline__ void cpa16(unsigned s, const void* g) {
    asm volatile("cp.async.ca.shared.global [%0], [%1], 16;" :: "r"(s), "l"(g));
}
#define CP_COMMIT() asm volatile("cp.async.commit_group;" ::: "memory")
#define CP_WAIT0() asm volatile("cp.async.wait_group 0;" ::: "memory")
#define CP_WAIT1() asm volatile("cp.async.wait_group 1;" ::: "memory")

__device__ __forceinline__ float fast_exp(float x) {
    float y = x * 1.4426950408889634f;
    float n = rintf(y);
    float f = y - n;
    float p = 1.3333558146e-3f;
    p = fmaf(p, f, 9.6181291076e-3f);
    p = fmaf(p, f, 5.5504108664e-2f);
    p = fmaf(p, f, 2.4022650696e-1f);
    p = fmaf(p, f, 6.9314718056e-1f);
    p = fmaf(p, f, 1.0f);
    int ni = (int)n;
    float s = __int_as_float((ni + 127) << 23);
    return p * s;
}

__device__ __forceinline__ void split_bf16(float v, __nv_bfloat16& h, __nv_bfloat16& l) {
    h = __float2bfloat16(v);
    l = __float2bfloat16(v - __bfloat162float(h));
}

// ---------------- scratch ----------------
__device__ float g_Wtop[256 * 512];
__device__ float g_Wbot[256 * 512];
__device__ float g_bqk[256];
__device__ float g_Wc[512 * 128];
__device__ float g_bout[512];
__device__ float g_qk[(size_t)BB * 128 * NN];            // rows: 0-63 q1, 64-127 k1 (fp32)
__device__ __nv_bfloat16 g_E2[(size_t)BB * NN * NN];
__device__ float g_Zinv[BB * NN];
__device__ float g_Gp[BB * 8 * 64 * 64];
__device__ float g_A[BB * 64 * 64];
__device__ __nv_bfloat16 g_Wh[256 * 1024];
__device__ __nv_bfloat16 g_Wl[256 * 1024];
__device__ __nv_bfloat16 g_Xh[(size_t)BB * NN * 1024];
__device__ __nv_bfloat16 g_Xl[(size_t)BB * NN * 1024];
__device__ __nv_bfloat16 g_QKTh[(size_t)BB * NN * 128];
__device__ __nv_bfloat16 g_QKTl[(size_t)BB * NN * 128];
__device__ __nv_bfloat16 g_KZh[(size_t)BB * 64 * NN];
__device__ __nv_bfloat16 g_KZl[(size_t)BB * 64 * NN];
__device__ __nv_bfloat16 g_OSh[(size_t)BB * 128 * NN];
__device__ __nv_bfloat16 g_OSl[(size_t)BB * 128 * NN];
__device__ __nv_bfloat16 g_WCh[512 * 128];
__device__ __nv_bfloat16 g_WCl[512 * 128];
__device__ __nv_bfloat16 g_CH[(size_t)BB * 128 * NN];    // chan q2(0-63)/k2(64-127) bf16 hi
__device__ __nv_bfloat16 g_CL[(size_t)BB * 128 * NN];

// ---------------- weight folding ----------------
__global__ void fold_qk(const float* __restrict__ wt, const float* __restrict__ wb,
                        const float* __restrict__ sw1, const float* __restrict__ sw2,
                        const float* __restrict__ cwq, const float* __restrict__ cwk) {
    int idx = blockIdx.x * blockDim.x + threadIdx.x;
    int j = idx >> 9, c = idx & 511;
    const float* wrow; int uoff;
    if (j < 64)       { wrow = sw1 + j * 256;        uoff = 0;   }
    else if (j < 128) { wrow = sw2 + (j - 64) * 256; uoff = 0;   }
    else if (j < 192) { wrow = cwq + (j - 128) * 256; uoff = 256; }
    else              { wrow = cwk + (j - 192) * 256; uoff = 256; }
    float at = 0.f, ab = 0.f;
    #pragma unroll 8
    for (int u = 0; u < 256; ++u) {
        float w = wrow[u];
        at = fmaf(w, wt[(uoff + u) * 512 + c], at);
        ab = fmaf(w, wb[(uoff + u) * 512 + c], ab);
    }
    g_Wtop[idx] = at;
    g_Wbot[idx] = ab;
}

__global__ void fold_out(const float* __restrict__ fw, const float* __restrict__ swo,
                         const float* __restrict__ cwo) {
    int idx = blockIdx.x * blockDim.x + threadIdx.x;
    int o = idx >> 7, t = idx & 127;
    float acc = 0.f;
    if (t < 64) {
        #pragma unroll 8
        for (int u = 0; u < 256; ++u)
            acc = fmaf(fw[o * 512 + u], swo[u * 64 + t], acc);
    } else {
        int r = t - 64;
        #pragma unroll 8
        for (int u = 0; u < 256; ++u)
            acc = fmaf(fw[o * 512 + 256 + u], cwo[u * 64 + r], acc);
    }
    g_Wc[idx] = acc;
}

__global__ void fold_bias(const float* __restrict__ bt, const float* __restrict__ bb,
                          const float* __restrict__ sb1, const float* __restrict__ sb2,
                          const float* __restrict__ cbq, const float* __restrict__ cbk,
                          const float* __restrict__ fw,  const float* __restrict__ sbo,
                          const float* __restrict__ cbo, const float* __restrict__ fb,
                          const float* __restrict__ sw1, const float* __restrict__ sw2,
                          const float* __restrict__ cwq, const float* __restrict__ cwk) {
    int t = threadIdx.x;   // 512
    if (t < 256) {
        const float* wrow; int uoff; float ob;
        int j = t;
        if (j < 64)       { wrow = sw1 + j * 256;        uoff = 0;   ob = sb1[j];       }
        else if (j < 128) { wrow = sw2 + (j - 64) * 256; uoff = 0;   ob = sb2[j - 64];  }
        else if (j < 192) { wrow = cwq + (j - 128) * 256; uoff = 256; ob = cbq[j - 128]; }
        else              { wrow = cwk + (j - 192) * 256; uoff = 256; ob = cbk[j - 192]; }
        float s = ob;
        for (int u = 0; u < 256; ++u)
            s = fmaf(wrow[u], bt[uoff + u] + bb[uoff + u], s);
        g_bqk[j] = s;
    }
    float s2 = fb[t];
    for (int u = 0; u < 256; ++u) {
        s2 = fmaf(fw[t * 512 + u],       sbo[u], s2);
        s2 = fmaf(fw[t * 512 + 256 + u], cbo[u], s2);
    }
    g_bout[t] = s2;
}

// ---------------- converts ----------------
__global__ void conv_w() {
    int idx = blockIdx.x * 256 + threadIdx.x;
    int j = idx >> 10, c = idx & 1023;
    float v = (c < 512) ? g_Wtop[j * 512 + c] : g_Wbot[j * 512 + c - 512];
    __nv_bfloat16 h, l; split_bf16(v, h, l);
    g_Wh[idx] = h; g_Wl[idx] = l;
}

__global__ void conv_wc() {
    int idx = blockIdx.x * 256 + threadIdx.x;   // 65536
    __nv_bfloat16 h, l; split_bf16(g_Wc[idx], h, l);
    g_WCh[idx] = h; g_WCl[idx] = l;
}

__global__ void conv_x(const float* __restrict__ top, const float* __restrict__ bot) {
    __shared__ float sh[32][33];
    int b = blockIdx.z;
    int c0 = blockIdx.y * 32;
    int p0 = blockIdx.x * 32;
    const float* src = (c0 < 512) ? top : bot;
    int cs = c0 & 511;
    int tx = threadIdx.x, ty = threadIdx.y;
    #pragma unroll
    for (int k = 0; k < 4; ++k) {
        int i = ty + k * 8;
        sh[i][tx] = src[((size_t)(b * 512 + cs + i)) * NN + p0 + tx];
    }
    __syncthreads();
    #pragma unroll
    for (int k = 0; k < 4; ++k) {
        int i = ty + k * 8;
        float v = sh[tx][i];
        __nv_bfloat16 h, l; split_bf16(v, h, l);
        size_t o = ((size_t)(b * NN + p0 + i)) * 1024 + c0 + tx;
        g_Xh[o] = h; g_Xl[o] = l;
    }
}

// ---------------- qk GEMM via HMMA + cp.async double buffer ----------------
#define TS (128 * 72 * 2)
#define QK3_SMEM (8 * TS)
__global__ void __launch_bounds__(256) qk_tc3() {
    extern __shared__ __align__(16) char smem[];
    unsigned sb = smem_u32(smem);
    int t = threadIdx.x;
    int wid = t >> 5, lid = t & 31;
    int b = blockIdx.z;
    int j0 = blockIdx.y * 128;
    int p0 = blockIdx.x * 128;
    int wr = wid & 1;
    int wc = wid >> 1;

    const __nv_bfloat16* srcs[4] = {
        g_Wh + (size_t)j0 * 1024,
        g_Wl + (size_t)j0 * 1024,
        g_Xh + ((size_t)b * NN + p0) * 1024,
        g_Xl + ((size_t)b * NN + p0) * 1024
    };

    float c[4][4][4] = {};

    {
        #pragma unroll
        for (int tile = 0; tile < 4; ++tile) {
            unsigned base = sb + tile * TS;
            const __nv_bfloat16* s = srcs[tile];
            #pragma unroll
            for (int rep = 0; rep < 4; ++rep) {
                int u = t + rep * 256;
                int r = u >> 3, q = u & 7;
                cpa16(base + r * 144 + q * 16, s + (size_t)r * 1024 + q * 8);
            }
        }
        CP_COMMIT();
    }

    for (int ch = 0; ch < 16; ++ch) {
        if (ch + 1 < 16) {
            unsigned boff = ((ch + 1) & 1) * (4 * TS);
            int c0 = (ch + 1) * 64;
            #pragma unroll
            for (int tile = 0; tile < 4; ++tile) {
                unsigned base = sb + boff + tile * TS;
                const __nv_bfloat16* s = srcs[tile];
                #pragma unroll
                for (int rep = 0; rep < 4; ++rep) {
                    int u = t + rep * 256;
                    int r = u >> 3, q = u & 7;
                    cpa16(base + r * 144 + q * 16, s + (size_t)r * 1024 + c0 + q * 8);
                }
            }
            CP_COMMIT();
            CP_WAIT1();
        } else {
            CP_WAIT0();
        }
        __syncthreads();
        unsigned abase = sb + (ch & 1) * (4 * TS);
        unsigned aAddr = abase + (unsigned)((wr * 64 + (lid & 15)) * 144 + (lid >> 4) * 16);
        unsigned bAddr = abase + 2 * TS +
            (unsigned)((wc * 32 + ((lid >> 4) & 1) * 8 + (lid & 7)) * 144 + ((lid >> 3) & 1) * 16);
        #pragma unroll
        for (int ks = 0; ks < 4; ++ks) {
            unsigned bh[2][4], bl[2][4];
            ldsm4(bh[0], bAddr + ks * 32);
            ldsm4(bh[1], bAddr + 16 * 144 + ks * 32);
            ldsm4(bl[0], bAddr + TS + ks * 32);
            ldsm4(bl[1], bAddr + TS + 16 * 144 + ks * 32);
            #pragma unroll
            for (int mt = 0; mt < 4; ++mt) {
                unsigned ah[4], al[4];
                ldsm4(ah, aAddr + mt * 2304 + ks * 32);
                ldsm4(al, aAddr + TS + mt * 2304 + ks * 32);
                #pragma unroll
                for (int nt = 0; nt < 4; ++nt) {
                    const unsigned* bhp = &bh[nt >> 1][(nt & 1) * 2];
                    const unsigned* blp = &bl[nt >> 1][(nt & 1) * 2];
                    mma_bf16(c[mt][nt], ah, bhp);
                    mma_bf16(c[mt][nt], ah, blp);
                    mma_bf16(c[mt][nt], al, bhp);
                }
            }
        }
        __syncthreads();
    }

    int g = lid >> 2, tig = lid & 3;
    if (blockIdx.y == 0) {
        // q1/k1: fp32 to g_qk
        #pragma unroll
        for (int mt = 0; mt < 4; ++mt) {
            int jrow0 = wr * 64 + mt * 16 + g;
            float b0 = g_bqk[jrow0], b1 = g_bqk[jrow0 + 8];
            size_t r0 = ((size_t)(b * 128 + jrow0)) * NN;
            size_t r1 = r0 + (size_t)8 * NN;
            #pragma unroll
            for (int nt = 0; nt < 4; ++nt) {
                int pc = p0 + wc * 32 + nt * 8 + tig * 2;
                float2 v0 = {c[mt][nt][0] + b0, c[mt][nt][1] + b0};
                float2 v1 = {c[mt][nt][2] + b1, c[mt][nt][3] + b1};
                *(float2*)&g_qk[r0 + pc] = v0;
                *(float2*)&g_qk[r1 + pc] = v1;
            }
        }
    } else {
        // q2/k2: bf16 hi/lo directly to CH/CL
        #pragma unroll
        for (int mt = 0; mt < 4; ++mt) {
            int jl = wr * 64 + mt * 16 + g;           // 0..127 local
            float b0 = g_bqk[128 + jl], b1 = g_bqk[128 + jl + 8];
            size_t r0 = ((size_t)(b * 128 + jl)) * NN;
            size_t r1 = r0 + (size_t)8 * NN;
            #pragma unroll
            for (int nt = 0; nt < 4; ++nt) {
                int pc = p0 + wc * 32 + nt * 8 + tig * 2;
                __nv_bfloat16 h0, l0, h1, l1;
                split_bf16(c[mt][nt][0] + b0, h0, l0);
                split_bf16(c[mt][nt][1] + b0, h1, l1);
                *(__nv_bfloat162*)&g_CH[r0 + pc] = {h0, h1};
                *(__nv_bfloat162*)&g_CL[r0 + pc] = {l0, l1};
                split_bf16(c[mt][nt][2] + b1, h0, l0);
                split_bf16(c[mt][nt][3] + b1, h1, l1);
                *(__nv_bfloat162*)&g_CH[r1 + pc] = {h0, h1};
                *(__nv_bfloat162*)&g_CL[r1 + pc] = {l0, l1};
            }
        }
    }
}

// ---------------- transpose q1/k1 rows to [p][j] bf16 hi/lo ----------------
__global__ void conv_qk() {
    __shared__ float sh[32][33];
    int b = blockIdx.z;
    int j0 = blockIdx.y * 32;
    int p0 = blockIdx.x * 32;
    int tx = threadIdx.x, ty = threadIdx.y;
    #pragma unroll
    for (int k = 0; k < 4; ++k) {
        int i = ty + k * 8;
        sh[i][tx] = g_qk[((size_t)(b * 128 + j0 + i)) * NN + p0 + tx];
    }
    __syncthreads();
    #pragma unroll
    for (int k = 0; k < 4; ++k) {
        int i = ty + k * 8;
        float v = sh[tx][i];
        __nv_bfloat16 h, l; split_bf16(v, h, l);
        size_t o = ((size_t)(b * NN + p0 + i)) * 128 + j0 + tx;
        g_QKTh[o] = h; g_QKTl[o] = l;
    }
}

// ---------------- spatial pass A via HMMA + cp.async double-buffered K ----------------
#define PAT 18432
#define PA_SMEM (6 * PAT + 2048)
__global__ void __launch_bounds__(256, 2) passA_tc() {
    extern __shared__ __align__(16) char smem[];
    unsigned sb = smem_u32(smem);
    int t = threadIdx.x;
    int wid = t >> 5, lid = t & 31;
    int b = blockIdx.y;
    int n0 = blockIdx.x * 128;
    int wr = wid & 1;
    int wc = wid >> 1;
    int g = lid >> 2, tig = lid & 3;

    // Q hi/lo resident
    #pragma unroll
    for (int rep = 0; rep < 4; ++rep) {
        int u = t + rep * 256;
        int r = u >> 3, q = u & 7;
        size_t src = ((size_t)b * NN + n0 + r) * 128 + q * 8;
        cpa16(sb + r * 144 + q * 16, g_QKTh + src);
        cpa16(sb + PAT + r * 144 + q * 16, g_QKTl + src);
    }
    // K chunk 0 into buf0
    #pragma unroll
    for (int rep = 0; rep < 4; ++rep) {
        int u = t + rep * 256;
        int r = u >> 3, q = u & 7;
        size_t src = ((size_t)b * NN + r) * 128 + 64 + q * 8;
        cpa16(sb + 2 * PAT + r * 144 + q * 16, g_QKTh + src);
        cpa16(sb + 3 * PAT + r * 144 + q * 16, g_QKTl + src);
    }
    CP_COMMIT();

    unsigned aAddrH = sb + (unsigned)((wr * 64 + (lid & 15)) * 144 + (lid >> 4) * 16);

    float zacc[8] = {};
    size_t ebase = ((size_t)b) << 24;

    for (int ch = 0; ch < 32; ++ch) {
        int m0 = ch * 128;
        if (ch + 1 < 32) {
            unsigned kb = 2 * PAT + ((ch + 1) & 1) * 2 * PAT;
            int m1 = (ch + 1) * 128;
            #pragma unroll
            for (int rep = 0; rep < 4; ++rep) {
                int u = t + rep * 256;
                int r = u >> 3, q = u & 7;
                size_t src = ((size_t)b * NN + m1 + r) * 128 + 64 + q * 8;
                cpa16(sb + kb + r * 144 + q * 16, g_QKTh + src);
                cpa16(sb + kb + PAT + r * 144 + q * 16, g_QKTl + src);
            }
            CP_COMMIT();
            CP_WAIT1();
        } else {
            CP_WAIT0();
        }
        __syncthreads();
        unsigned kb = 2 * PAT + (ch & 1) * 2 * PAT;
        unsigned bAddrH = sb + kb +
            (unsigned)((wc * 32 + ((lid >> 4) & 1) * 8 + (lid & 7)) * 144 + ((lid >> 3) & 1) * 16);
        float c[4][4][4] = {};
        #pragma unroll
        for (int ks = 0; ks < 4; ++ks) {
            unsigned bh[2][4], bl[2][4];
            ldsm4(bh[0], bAddrH + ks * 32);
            ldsm4(bh[1], bAddrH + 16 * 144 + ks * 32);
            ldsm4(bl[0], bAddrH + PAT + ks * 32);
            ldsm4(bl[1], bAddrH + PAT + 16 * 144 + ks * 32);
            #pragma unroll
            for (int mt = 0; mt < 4; ++mt) {
                unsigned ah[4], al[4];
                ldsm4(ah, aAddrH + mt * 2304 + ks * 32);
                ldsm4(al, aAddrH + PAT + mt * 2304 + ks * 32);
                #pragma unroll
                for (int nt = 0; nt < 4; ++nt) {
                    const unsigned* bhp = &bh[nt >> 1][(nt & 1) * 2];
                    const unsigned* blp = &bl[nt >> 1][(nt & 1) * 2];
                    mma_bf16(c[mt][nt], ah, bhp);
                    mma_bf16(c[mt][nt], ah, blp);
                    mma_bf16(c[mt][nt], al, bhp);
                }
            }
        }
        #pragma unroll
        for (int mt = 0; mt < 4; ++mt) {
            int n = n0 + wr * 64 + mt * 16 + g;
            #pragma unroll
            for (int nt = 0; nt < 4; ++nt) {
                int m = m0 + wc * 32 + nt * 8 + tig * 2;
                float e0 = fast_exp(c[mt][nt][0]);
                float e1 = fast_exp(c[mt][nt][1]);
                float e2 = fast_exp(c[mt][nt][2]);
                float e3 = fast_exp(c[mt][nt][3]);
                __nv_bfloat162 v0 = {__float2bfloat16(e0), __float2bfloat16(e1)};
                __nv_bfloat162 v1 = {__float2bfloat16(e2), __float2bfloat16(e3)};
                *(__nv_bfloat162*)&g_E2[ebase + (size_t)n * NN + m] = v0;
                *(__nv_bfloat162*)&g_E2[ebase + (size_t)(n + 8) * NN + m] = v1;
                zacc[mt * 2] += e0 + e1;
                zacc[mt * 2 + 1] += e2 + e3;
            }
        }
        __syncthreads();
    }

    float* zp = (float*)(smem + 6 * PAT);
    #pragma unroll
    for (int s = 0; s < 8; ++s) {
        float v = zacc[s];
        v += __shfl_xor_sync(0xFFFFFFFF, v, 1);
        v += __shfl_xor_sync(0xFFFFFFFF, v, 2);
        if (tig == 0)
            zp[wc * 128 + wr * 64 + (s >> 1) * 16 + (s & 1) * 8 + g] = v;
    }
    __syncthreads();
    if (t < 128) {
        float s = zp[t] + zp[128 + t] + zp[256 + t] + zp[384 + t];
        g_Zinv[b * NN + n0 + t] = 1.0f / s;
    }
}

// ---------------- Kz = k1 * Zinv -> bf16 hi/lo ----------------
__global__ void conv_kz() {
    int n = blockIdx.x * 256 + threadIdx.x;
    int r = blockIdx.y;
    int b = blockIdx.z;
    float v = g_qk[((size_t)(b * 128 + 64 + r)) * NN + n] * g_Zinv[b * NN + n];
    __nv_bfloat16 h, l; split_bf16(v, h, l);
    size_t o = ((size_t)b * 64 + r) * NN + n;
    g_KZh[o] = h; g_KZl[o] = l;
}

// ---------------- spatial pass B via HMMA + cp.async double buffer ----------------
#define PBS 35840   // stage: Kzh 9216 + Kzl 9216 + E 17408
#define PB_SMEM (2 * PBS)
__global__ void __launch_bounds__(256, 2) passB_tc() {
    extern __shared__ __align__(16) char smem[];
    unsigned sb = smem_u32(smem);
    int t = threadIdx.x;
    int wid = t >> 5, lid = t & 31;
    int b = blockIdx.y;
    int m0 = blockIdx.x * 128;
    int g = lid >> 2, tig = lid & 3;

    float c[4][2][4] = {};
    size_t ebase = ((size_t)b) << 24;

    // chunk 0 into buf0
    {
        #pragma unroll
        for (int rep = 0; rep < 2; ++rep) {
            int u = t + rep * 256;
            int r = u >> 3, q = u & 7;
            size_t src = ((size_t)b * 64 + r) * NN + q * 8;
            cpa16(sb + r * 144 + q * 16, g_KZh + src);
            cpa16(sb + 9216 + r * 144 + q * 16, g_KZl + src);
        }
        #pragma unroll
        for (int rep = 0; rep < 4; ++rep) {
            int u = t + rep * 256;
            int r = u >> 4, q = u & 15;
            cpa16(sb + 18432 + r * 272 + q * 16, g_E2 + ebase + (size_t)r * NN + m0 + q * 8);
        }
        CP_COMMIT();
    }

    for (int ch = 0; ch < 64; ++ch) {
        if (ch + 1 < 64) {
            unsigned boff = ((ch + 1) & 1) * PBS;
            int n1 = (ch + 1) * 64;
            #pragma unroll
            for (int rep = 0; rep < 2; ++rep) {
                int u = t + rep * 256;
                int r = u >> 3, q = u & 7;
                size_t src = ((size_t)b * 64 + r) * NN + n1 + q * 8;
                cpa16(sb + boff + r * 144 + q * 16, g_KZh + src);
                cpa16(sb + boff + 9216 + r * 144 + q * 16, g_KZl + src);
            }
            #pragma unroll
            for (int rep = 0; rep < 4; ++rep) {
                int u = t + rep * 256;
                int r = u >> 4, q = u & 15;
                cpa16(sb + boff + 18432 + r * 272 + q * 16,
                      g_E2 + ebase + (size_t)(n1 + r) * NN + m0 + q * 8);
            }
            CP_COMMIT();
            CP_WAIT1();
        } else {
            CP_WAIT0();
        }
        __syncthreads();
        unsigned boff = (ch & 1) * PBS;
        unsigned aAddrH = sb + boff + (unsigned)(((lid & 15)) * 144 + (lid >> 4) * 16);
        unsigned eAddr = sb + boff + 18432 +
            (unsigned)(((lid & 7) + ((lid >> 3) & 1) * 8) * 272 + (wid * 16 + (lid >> 4) * 8) * 2);
        #pragma unroll
        for (int ks = 0; ks < 4; ++ks) {
            unsigned eb[4];
            ldsm4t(eb, eAddr + ks * 16 * 272);
            #pragma unroll
            for (int mt = 0; mt < 4; ++mt) {
                unsigned ah[4], al[4];
                ldsm4(ah, aAddrH + mt * 2304 + ks * 32);
                ldsm4(al, aAddrH + 9216 + mt * 2304 + ks * 32);
                #pragma unroll
                for (int nt = 0; nt < 2; ++nt) {
                    mma_bf16(c[mt][nt], ah, &eb[nt * 2]);
                    mma_bf16(c[mt][nt], al, &eb[nt * 2]);
                }
            }
        }
        __syncthreads();
    }

    #pragma unroll
    for (int mt = 0; mt < 4; ++mt) {
        int r = mt * 16 + g;
        size_t r0 = ((size_t)(b * 128 + r)) * NN;
        size_t r1 = r0 + (size_t)8 * NN;
        #pragma unroll
        for (int nt = 0; nt < 2; ++nt) {
            int m = m0 + wid * 16 + nt * 8 + tig * 2;
            __nv_bfloat16 h0, l0, h1, l1;
            split_bf16(c[mt][nt][0], h0, l0);
            split_bf16(c[mt][nt][1], h1, l1);
            *(__nv_bfloat162*)&g_OSh[r0 + m] = {h0, h1};
            *(__nv_bfloat162*)&g_OSl[r0 + m] = {l0, l1};
            split_bf16(c[mt][nt][2], h0, l0);
            split_bf16(c[mt][nt][3], h1, l1);
            *(__nv_bfloat162*)&g_OSh[r1 + m] = {h0, h1};
            *(__nv_bfloat162*)&g_OSl[r1 + m] = {l0, l1};
        }
    }
}

// ---------------- channel Gram via HMMA (8 chunks of 512 n) ----------------
__global__ void __launch_bounds__(128) chan_gram_tc() {
    __shared__ __align__(16) char csm[4 * 9216];
    unsigned sb = smem_u32(csm);
    int t = threadIdx.x;
    int wid = t >> 5, lid = t & 31;
    int b = blockIdx.y;
    int chunk = blockIdx.x;
    int wr = wid & 1, wc = wid >> 1;
    int g = lid >> 2, tig = lid & 3;

    unsigned aAddr = sb + (unsigned)((wr * 32 + (lid & 15)) * 144 + (lid >> 4) * 16);
    unsigned bAddr = sb + 2 * 9216 +
        (unsigned)((wc * 32 + ((lid >> 4) & 1) * 8 + (lid & 7)) * 144 + ((lid >> 3) & 1) * 16);

    float c[2][4][4] = {};

    for (int sub = 0; sub < 8; ++sub) {
        int n0 = chunk * 512 + sub * 64;
        __syncthreads();
        #pragma unroll
        for (int rep = 0; rep < 4; ++rep) {
            int u = t + rep * 128;
            int r = u >> 3, q = u & 7;
            size_t sq = ((size_t)(b * 128 + r)) * NN + n0 + q * 8;
            size_t sk = ((size_t)(b * 128 + 64 + r)) * NN + n0 + q * 8;
            *(uint4*)(csm + r * 144 + q * 16) = *(const uint4*)(g_CH + sq);
            *(uint4*)(csm + 9216 + r * 144 + q * 16) = *(const uint4*)(g_CL + sq);
            *(uint4*)(csm + 2 * 9216 + r * 144 + q * 16) = *(const uint4*)(g_CH + sk);
            *(uint4*)(csm + 3 * 9216 + r * 144 + q * 16) = *(const uint4*)(g_CL + sk);
        }
        __syncthreads();
        #pragma unroll
        for (int ks = 0; ks < 4; ++ks) {
            unsigned bh[2][4], bl[2][4];
            ldsm4(bh[0], bAddr + ks * 32);
            ldsm4(bh[1], bAddr + 16 * 144 + ks * 32);
            ldsm4(bl[0], bAddr + 9216 + ks * 32);
            ldsm4(bl[1], bAddr + 9216 + 16 * 144 + ks * 32);
            #pragma unroll
            for (int mt = 0; mt < 2; ++mt) {
                unsigned ah[4], al[4];
                ldsm4(ah, aAddr + mt * 2304 + ks * 32);
                ldsm4(al, aAddr + 9216 + mt * 2304 + ks * 32);
                #pragma unroll
                for (int nt = 0; nt < 4; ++nt) {
                    const unsigned* bhp = &bh[nt >> 1][(nt & 1) * 2];
                    const unsigned* blp = &bl[nt >> 1][(nt & 1) * 2];
                    mma_bf16(c[mt][nt], ah, bhp);
                    mma_bf16(c[mt][nt], ah, blp);
                    mma_bf16(c[mt][nt], al, bhp);
                }
            }
        }
    }

    float* gp = &g_Gp[(b * 8 + chunk) * 4096];
    #pragma unroll
    for (int mt = 0; mt < 2; ++mt) {
        int r = wr * 32 + mt * 16 + g;
        #pragma unroll
        for (int nt = 0; nt < 4; ++nt) {
            int s = wc * 32 + nt * 8 + tig * 2;
            *(float2*)&gp[r * 64 + s] = {c[mt][nt][0], c[mt][nt][1]};
            *(float2*)&gp[(r + 8) * 64 + s] = {c[mt][nt][2], c[mt][nt][3]};
        }
    }
}

__global__ void chan_softmax() {
    int r = blockIdx.x;
    int b = blockIdx.y;
    int s = threadIdx.x;
    __shared__ float red[64];
    float v = 0.f;
    #pragma unroll
    for (int ch = 0; ch < 8; ++ch)
        v += g_Gp[(b * 8 + ch) * 4096 + r * 64 + s];
    red[s] = v;
    __syncthreads();
    for (int off = 32; off >= 1; off >>= 1) {
        if (s < off) red[s] = fmaxf(red[s], red[s + off]);
        __syncthreads();
    }
    float mx = red[0];
    __syncthreads();
    float e = __expf(v - mx);
    red[s] = e;
    __syncthreads();
    for (int off = 32; off >= 1; off >>= 1) {
        if (s < off) red[s] += red[s + off];
        __syncthreads();
    }
    g_A[b * 4096 + r * 64 + s] = e / red[0];
}

__global__ void __launch_bounds__(256) chan_out() {
    int b = blockIdx.y;
    int p = blockIdx.x * 256 + threadIdx.x;
    __shared__ __align__(16) float As[64][64];
    #pragma unroll
    for (int k = 0; k < 16; ++k)
        (&As[0][0])[threadIdx.x + k * 256] = g_A[b * 4096 + threadIdx.x + k * 256];
    __syncthreads();
    float kreg[64];
    #pragma unroll
    for (int s = 0; s < 64; ++s) {
        size_t o = ((size_t)(b * 128 + 64 + s)) * NN + p;
        kreg[s] = __bfloat162float(g_CH[o]) + __bfloat162float(g_CL[o]);
    }
    ull kp2[32];
    #pragma unroll
    for (int s = 0; s < 32; ++s) {
        ull r; asm("mov.b64 %0, {%1, %2};" : "=l"(r) : "f"(kreg[2 * s]), "f"(kreg[2 * s + 1]));
        kp2[s] = r;
    }
    #pragma unroll 2
    for (int r = 0; r < 64; ++r) {
        ull acc = 0;
        const ull* arow = (const ull*)&As[r][0];
        #pragma unroll
        for (int s = 0; s < 32; ++s)
            fma2(acc, arow[s], kp2[s]);
        float lo, hi;
        unpack2(acc, lo, hi);
        float v = lo + hi;
        __nv_bfloat16 h, l; split_bf16(v, h, l);
        size_t o = ((size_t)(b * 128 + 64 + r)) * NN + p;
        g_OSh[o] = h; g_OSl[o] = l;
    }
}

// ---------------- final GEMM via HMMA (3-pass) ----------------
#define FT_SMEM 139264
__global__ void __launch_bounds__(256) final_tc(float* __restrict__ out) {
    extern __shared__ __align__(16) char smem[];
    unsigned sb = smem_u32(smem);
    int t = threadIdx.x;
    int wid = t >> 5, lid = t & 31;
    int b = blockIdx.z;
    int o0 = blockIdx.y * 128;
    int p0 = blockIdx.x * 128;
    int wr = wid & 1, wc = wid >> 1;
    int g = lid >> 2, tig = lid & 3;

    #pragma unroll
    for (int rep = 0; rep < 8; ++rep) {
        int u = t + rep * 256;
        int r = u >> 4, q = u & 15;
        *(uint4*)(smem + r * 272 + q * 16) = *(const uint4*)(g_WCh + (size_t)(o0 + r) * 128 + q * 8);
        *(uint4*)(smem + 34816 + r * 272 + q * 16) = *(const uint4*)(g_WCl + (size_t)(o0 + r) * 128 + q * 8);
        size_t bs = ((size_t)(b * 128 + r)) * NN + p0 + q * 8;
        *(uint4*)(smem + 69632 + r * 272 + q * 16) = *(const uint4*)(g_OSh + bs);
        *(uint4*)(smem + 104448 + r * 272 + q * 16) = *(const uint4*)(g_OSl + bs);
    }
    __syncthreads();

    unsigned aAddr = sb + (unsigned)((wr * 64 + (lid & 15)) * 272 + (lid >> 4) * 16);
    unsigned eAddr = sb + 69632 +
        (unsigned)(((lid & 7) + ((lid >> 3) & 1) * 8) * 272 + (wc * 32 + (lid >> 4) * 8) * 2);

    float c[4][4][4] = {};
    #pragma unroll
    for (int ks = 0; ks < 8; ++ks) {
        unsigned bh[2][4], bl[2][4];
        ldsm4t(bh[0], eAddr + ks * 16 * 272);
        ldsm4t(bh[1], eAddr + ks * 16 * 272 + 32);
        ldsm4t(bl[0], eAddr + 34816 + ks * 16 * 272);
        ldsm4t(bl[1], eAddr + 34816 + ks * 16 * 272 + 32);
        #pragma unroll
        for (int mt = 0; mt < 4; ++mt) {
            unsigned ah[4], al[4];
            ldsm4(ah, aAddr + mt * 16 * 272 + ks * 32);
            ldsm4(al, aAddr + 34816 + mt * 16 * 272 + ks * 32);
            #pragma unroll
            for (int nt = 0; nt < 4; ++nt) {
                const unsigned* bhp = &bh[nt >> 1][(nt & 1) * 2];
                const unsigned* blp = &bl[nt >> 1][(nt & 1) * 2];
                mma_bf16(c[mt][nt], ah, bhp);
                mma_bf16(c[mt][nt], ah, blp);
                mma_bf16(c[mt][nt], al, bhp);
            }
        }
    }

    #pragma unroll
    for (int mt = 0; mt < 4; ++mt) {
        int o = o0 + wr * 64 + mt * 16 + g;
        float b0 = g_bout[o], b1 = g_bout[o + 8];
        size_t r0 = ((size_t)(b * 512 + o)) * NN;
        size_t r1 = r0 + (size_t)8 * NN;
        #pragma unroll
        for (int nt = 0; nt < 4; ++nt) {
            int pc = p0 + wc * 32 + nt * 8 + tig * 2;
            float2 v0 = {c[mt][nt][0] + b0, c[mt][nt][1] + b0};
            float2 v1 = {c[mt][nt][2] + b1, c[mt][nt][3] + b1};
            *(float2*)&out[r0 + pc] = v0;
            *(float2*)&out[r1 + pc] = v1;
        }
    }
}

// ---------------- launch ----------------
extern "C" void kernel_launch(void* const* d_in, const int* in_sizes, int n_in,
                              void* d_out, int out_size) {
    const float* top  = (const float*)d_in[0];
    const float* bot  = (const float*)d_in[1];
    const float* wt   = (const float*)d_in[2];
    const float* bt   = (const float*)d_in[3];
    const float* wb   = (const float*)d_in[4];
    const float* bb   = (const float*)d_in[5];
    const float* s_w1 = (const float*)d_in[6];
    const float* s_b1 = (const float*)d_in[7];
    const float* s_w2 = (const float*)d_in[8];
    const float* s_b2 = (const float*)d_in[9];
    const float* s_wo = (const float*)d_in[10];
    const float* s_bo = (const float*)d_in[11];
    const float* c_wq = (const float*)d_in[12];
    const float* c_bq = (const float*)d_in[13];
    const float* c_wk = (const float*)d_in[14];
    const float* c_bk = (const float*)d_in[15];
    const float* c_wo = (const float*)d_in[16];
    const float* c_bo = (const float*)d_in[17];
    const float* f_w  = (const float*)d_in[18];
    const float* f_b  = (const float*)d_in[19];
    float* out = (float*)d_out;

    cudaFuncSetAttribute(qk_tc3, cudaFuncAttributeMaxDynamicSharedMemorySize, QK3_SMEM);
    cudaFuncSetAttribute(passA_tc, cudaFuncAttributeMaxDynamicSharedMemorySize, PA_SMEM);
    cudaFuncSetAttribute(passB_tc, cudaFuncAttributeMaxDynamicSharedMemorySize, PB_SMEM);
    cudaFuncSetAttribute(final_tc, cudaFuncAttributeMaxDynamicSharedMemorySize, FT_SMEM);

    fold_qk<<<512, 256>>>(wt, wb, s_w1, s_w2, c_wq, c_wk);
    fold_out<<<256, 256>>>(f_w, s_wo, c_wo);
    fold_bias<<<1, 512>>>(bt, bb, s_b1, s_b2, c_bq, c_bk, f_w, s_bo, c_bo, f_b,
                          s_w1, s_w2, c_wq, c_wk);
    conv_w<<<1024, 256>>>();
    conv_wc<<<256, 256>>>();
    conv_x<<<dim3(128, 32, 8), dim3(32, 8)>>>(top, bot);
    qk_tc3<<<dim3(32, 2, 8), 256, QK3_SMEM>>>();
    conv_qk<<<dim3(128, 4, 8), dim3(32, 8)>>>();
    passA_tc<<<dim3(32, 8), 256, PA_SMEM>>>();
    conv_kz<<<dim3(16, 64, 8), 256>>>();
    passB_tc<<<dim3(32, 8), 256, PB_SMEM>>>();
    chan_gram_tc<<<dim3(8, 8), 128>>>();
    chan_softmax<<<dim3(64, 8), 64>>>();
    chan_out<<<dim3(16, 8), 256>>>();
    final_tc<<<dim3(32, 4, 8), 256, FT_SMEM>>>(out);
}

// round 10
// speedup vs baseline: 2.3515x; 1.0576x over previous
#include <cuda_runtime.h>
#include <cuda_bf16.h>
#include <stdint.h>
#include <math.h>

#define BB 8
#define NN 4096

typedef unsigned long long ull;

__device__ __forceinline__ ull dup2(float x) {
    ull r; asm("mov.b64 %0, {%1, %1};" : "=l"(r) : "f"(x)); return r;
}
__device__ __forceinline__ void unpack2(ull v, float& x, float& y) {
    asm("mov.b64 {%0, %1}, %2;" : "=f"(x), "=f"(y) : "l"(v));
}
__device__ __forceinline__ void fma2(ull& d, ull a, ull b) {
    asm("fma.rn.f32x2 %0, %1, %2, %0;" : "+l"(d) : "l"(a), "l"(b));
}

__device__ __forceinline__ unsigned smem_u32(const void* p) {
    unsigned a;
    asm("{ .reg .u64 t; cvta.to.shared.u64 t, %1; cvt.u32.u64 %0, t; }" : "=r"(a) : "l"(p));
    return a;
}
__device__ __forceinline__ void ldsm4(unsigned* r, unsigned addr) {
    asm volatile("ldmatrix.sync.aligned.m8n8.x4.shared.b16 {%0,%1,%2,%3}, [%4];"
        : "=r"(r[0]), "=r"(r[1]), "=r"(r[2]), "=r"(r[3]) : "r"(addr));
}
__device__ __forceinline__ void ldsm4t(unsigned* r, unsigned addr) {
    asm volatile("ldmatrix.sync.aligned.m8n8.x4.trans.shared.b16 {%0,%1,%2,%3}, [%4];"
        : "=r"(r[0]), "=r"(r[1]), "=r"(r[2]), "=r"(r[3]) : "r"(addr));
}
__device__ __forceinline__ void mma_bf16(float* c, const unsigned* a, const unsigned* b) {
    asm volatile("mma.sync.aligned.m16n8k16.row.col.f32.bf16.bf16.f32 "
        "{%0,%1,%2,%3}, {%4,%5,%6,%7}, {%8,%9}, {%0,%1,%2,%3};"
        : "+f"(c[0]), "+f"(c[1]), "+f"(c[2]), "+f"(c[3])
        : "r"(a[0]), "r"(a[1]), "r"(a[2]), "r"(a[3]), "r"(b[0]), "r"(b[1]));
}
__device__ __forceinline__ void cpa16(unsigned s, const void* g) {
    asm volatile("cp.async.ca.shared.global [%0], [%1], 16;" :: "r"(s), "l"(g));
}
#define CP_COMMIT() asm volatile("cp.async.commit_group;" ::: "memory")
#define CP_WAIT0() asm volatile("cp.async.wait_group 0;" ::: "memory")
#define CP_WAIT1() asm volatile("cp.async.wait_group 1;" ::: "memory")

__device__ __forceinline__ float fast_exp(float x) {
    float y = x * 1.4426950408889634f;
    float n = rintf(y);
    float f = y - n;
    float p = 1.3333558146e-3f;
    p = fmaf(p, f, 9.6181291076e-3f);
    p = fmaf(p, f, 5.5504108664e-2f);
    p = fmaf(p, f, 2.4022650696e-1f);
    p = fmaf(p, f, 6.9314718056e-1f);
    p = fmaf(p, f, 1.0f);
    int ni = (int)n;
    float s = __int_as_float((ni + 127) << 23);
    return p * s;
}

__device__ __forceinline__ void split_bf16(float v, __nv_bfloat16& h, __nv_bfloat16& l) {
    h = __float2bfloat16(v);
    l = __float2bfloat16(v - __bfloat162float(h));
}

// ---------------- scratch ----------------
__device__ float g_bqk[256];
__device__ float g_bout[512];
__device__ float g_qk[(size_t)BB * 128 * NN];            // rows: 0-63 q1, 64-127 k1 (fp32)
__device__ __nv_bfloat16 g_E2[(size_t)BB * NN * NN];
__device__ float g_Zinv[BB * NN];
__device__ float g_Gp[BB * 8 * 64 * 64];
__device__ float g_A[BB * 64 * 64];
__device__ __nv_bfloat16 g_Wh[256 * 1024];
__device__ __nv_bfloat16 g_Wl[256 * 1024];
__device__ __nv_bfloat16 g_Xh[(size_t)BB * NN * 1024];
__device__ __nv_bfloat16 g_Xl[(size_t)BB * NN * 1024];
__device__ __nv_bfloat16 g_QKTh[(size_t)BB * NN * 128];
__device__ __nv_bfloat16 g_QKTl[(size_t)BB * NN * 128];
__device__ __nv_bfloat16 g_KZh[(size_t)BB * 64 * NN];
__device__ __nv_bfloat16 g_KZl[(size_t)BB * 64 * NN];
__device__ __nv_bfloat16 g_OSh[(size_t)BB * 128 * NN];
__device__ __nv_bfloat16 g_OSl[(size_t)BB * 128 * NN];
__device__ __nv_bfloat16 g_WCh[512 * 128];
__device__ __nv_bfloat16 g_WCl[512 * 128];
__device__ __nv_bfloat16 g_CH[(size_t)BB * 128 * NN];    // chan q2(0-63)/k2(64-127) bf16 hi
__device__ __nv_bfloat16 g_CL[(size_t)BB * 128 * NN];

// ---------------- fused weight folding + bf16 split ----------------
__global__ void fold_qkw(const float* __restrict__ wt, const float* __restrict__ wb,
                         const float* __restrict__ sw1, const float* __restrict__ sw2,
                         const float* __restrict__ cwq, const float* __restrict__ cwk) {
    int idx = blockIdx.x * blockDim.x + threadIdx.x;
    int j = idx >> 9, c = idx & 511;
    const float* wrow; int uoff;
    if (j < 64)       { wrow = sw1 + j * 256;        uoff = 0;   }
    else if (j < 128) { wrow = sw2 + (j - 64) * 256; uoff = 0;   }
    else if (j < 192) { wrow = cwq + (j - 128) * 256; uoff = 256; }
    else              { wrow = cwk + (j - 192) * 256; uoff = 256; }
    float at = 0.f, ab = 0.f;
    #pragma unroll 8
    for (int u = 0; u < 256; ++u) {
        float w = wrow[u];
        at = fmaf(w, wt[(uoff + u) * 512 + c], at);
        ab = fmaf(w, wb[(uoff + u) * 512 + c], ab);
    }
    __nv_bfloat16 h, l;
    split_bf16(at, h, l);
    g_Wh[j * 1024 + c] = h; g_Wl[j * 1024 + c] = l;
    split_bf16(ab, h, l);
    g_Wh[j * 1024 + 512 + c] = h; g_Wl[j * 1024 + 512 + c] = l;
}

__global__ void fold_outc(const float* __restrict__ fw, const float* __restrict__ swo,
                          const float* __restrict__ cwo) {
    int idx = blockIdx.x * blockDim.x + threadIdx.x;
    int o = idx >> 7, t = idx & 127;
    float acc = 0.f;
    if (t < 64) {
        #pragma unroll 8
        for (int u = 0; u < 256; ++u)
            acc = fmaf(fw[o * 512 + u], swo[u * 64 + t], acc);
    } else {
        int r = t - 64;
        #pragma unroll 8
        for (int u = 0; u < 256; ++u)
            acc = fmaf(fw[o * 512 + 256 + u], cwo[u * 64 + r], acc);
    }
    __nv_bfloat16 h, l; split_bf16(acc, h, l);
    g_WCh[idx] = h; g_WCl[idx] = l;
}

__global__ void fold_bias(const float* __restrict__ bt, const float* __restrict__ bb,
                          const float* __restrict__ sb1, const float* __restrict__ sb2,
                          const float* __restrict__ cbq, const float* __restrict__ cbk,
                          const float* __restrict__ fw,  const float* __restrict__ sbo,
                          const float* __restrict__ cbo, const float* __restrict__ fb,
                          const float* __restrict__ sw1, const float* __restrict__ sw2,
                          const float* __restrict__ cwq, const float* __restrict__ cwk) {
    int t = threadIdx.x;   // 512
    if (t < 256) {
        const float* wrow; int uoff; float ob;
        int j = t;
        if (j < 64)       { wrow = sw1 + j * 256;        uoff = 0;   ob = sb1[j];       }
        else if (j < 128) { wrow = sw2 + (j - 64) * 256; uoff = 0;   ob = sb2[j - 64];  }
        else if (j < 192) { wrow = cwq + (j - 128) * 256; uoff = 256; ob = cbq[j - 128]; }
        else              { wrow = cwk + (j - 192) * 256; uoff = 256; ob = cbk[j - 192]; }
        float s = ob;
        for (int u = 0; u < 256; ++u)
            s = fmaf(wrow[u], bt[uoff + u] + bb[uoff + u], s);
        g_bqk[j] = s;
    }
    float s2 = fb[t];
    for (int u = 0; u < 256; ++u) {
        s2 = fmaf(fw[t * 512 + u],       sbo[u], s2);
        s2 = fmaf(fw[t * 512 + 256 + u], cbo[u], s2);
    }
    g_bout[t] = s2;
}

__global__ void conv_x(const float* __restrict__ top, const float* __restrict__ bot) {
    __shared__ float sh[32][33];
    int b = blockIdx.z;
    int c0 = blockIdx.y * 32;
    int p0 = blockIdx.x * 32;
    const float* src = (c0 < 512) ? top : bot;
    int cs = c0 & 511;
    int tx = threadIdx.x, ty = threadIdx.y;
    #pragma unroll
    for (int k = 0; k < 4; ++k) {
        int i = ty + k * 8;
        sh[i][tx] = src[((size_t)(b * 512 + cs + i)) * NN + p0 + tx];
    }
    __syncthreads();
    #pragma unroll
    for (int k = 0; k < 4; ++k) {
        int i = ty + k * 8;
        float v = sh[tx][i];
        __nv_bfloat16 h, l; split_bf16(v, h, l);
        size_t o = ((size_t)(b * NN + p0 + i)) * 1024 + c0 + tx;
        g_Xh[o] = h; g_Xl[o] = l;
    }
}

// ---------------- qk GEMM via HMMA + cp.async double buffer ----------------
#define TS (128 * 72 * 2)
#define QK3_SMEM (8 * TS)
__global__ void __launch_bounds__(256) qk_tc3() {
    extern __shared__ __align__(16) char smem[];
    unsigned sb = smem_u32(smem);
    int t = threadIdx.x;
    int wid = t >> 5, lid = t & 31;
    int b = blockIdx.z;
    int j0 = blockIdx.y * 128;
    int p0 = blockIdx.x * 128;
    int wr = wid & 1;
    int wc = wid >> 1;

    const __nv_bfloat16* srcs[4] = {
        g_Wh + (size_t)j0 * 1024,
        g_Wl + (size_t)j0 * 1024,
        g_Xh + ((size_t)b * NN + p0) * 1024,
        g_Xl + ((size_t)b * NN + p0) * 1024
    };

    float c[4][4][4] = {};

    {
        #pragma unroll
        for (int tile = 0; tile < 4; ++tile) {
            unsigned base = sb + tile * TS;
            const __nv_bfloat16* s = srcs[tile];
            #pragma unroll
            for (int rep = 0; rep < 4; ++rep) {
                int u = t + rep * 256;
                int r = u >> 3, q = u & 7;
                cpa16(base + r * 144 + q * 16, s + (size_t)r * 1024 + q * 8);
            }
        }
        CP_COMMIT();
    }

    for (int ch = 0; ch < 16; ++ch) {
        if (ch + 1 < 16) {
            unsigned boff = ((ch + 1) & 1) * (4 * TS);
            int c0 = (ch + 1) * 64;
            #pragma unroll
            for (int tile = 0; tile < 4; ++tile) {
                unsigned base = sb + boff + tile * TS;
                const __nv_bfloat16* s = srcs[tile];
                #pragma unroll
                for (int rep = 0; rep < 4; ++rep) {
                    int u = t + rep * 256;
                    int r = u >> 3, q = u & 7;
                    cpa16(base + r * 144 + q * 16, s + (size_t)r * 1024 + c0 + q * 8);
                }
            }
            CP_COMMIT();
            CP_WAIT1();
        } else {
            CP_WAIT0();
        }
        __syncthreads();
        unsigned abase = sb + (ch & 1) * (4 * TS);
        unsigned aAddr = abase + (unsigned)((wr * 64 + (lid & 15)) * 144 + (lid >> 4) * 16);
        unsigned bAddr = abase + 2 * TS +
            (unsigned)((wc * 32 + ((lid >> 4) & 1) * 8 + (lid & 7)) * 144 + ((lid >> 3) & 1) * 16);
        #pragma unroll
        for (int ks = 0; ks < 4; ++ks) {
            unsigned bh[2][4], bl[2][4];
            ldsm4(bh[0], bAddr + ks * 32);
            ldsm4(bh[1], bAddr + 16 * 144 + ks * 32);
            ldsm4(bl[0], bAddr + TS + ks * 32);
            ldsm4(bl[1], bAddr + TS + 16 * 144 + ks * 32);
            #pragma unroll
            for (int mt = 0; mt < 4; ++mt) {
                unsigned ah[4], al[4];
                ldsm4(ah, aAddr + mt * 2304 + ks * 32);
                ldsm4(al, aAddr + TS + mt * 2304 + ks * 32);
                #pragma unroll
                for (int nt = 0; nt < 4; ++nt) {
                    const unsigned* bhp = &bh[nt >> 1][(nt & 1) * 2];
                    const unsigned* blp = &bl[nt >> 1][(nt & 1) * 2];
                    mma_bf16(c[mt][nt], ah, bhp);
                    mma_bf16(c[mt][nt], ah, blp);
                    mma_bf16(c[mt][nt], al, bhp);
                }
            }
        }
        __syncthreads();
    }

    int g = lid >> 2, tig = lid & 3;
    if (blockIdx.y == 0) {
        #pragma unroll
        for (int mt = 0; mt < 4; ++mt) {
            int jrow0 = wr * 64 + mt * 16 + g;
            float b0 = g_bqk[jrow0], b1 = g_bqk[jrow0 + 8];
            size_t r0 = ((size_t)(b * 128 + jrow0)) * NN;
            size_t r1 = r0 + (size_t)8 * NN;
            #pragma unroll
            for (int nt = 0; nt < 4; ++nt) {
                int pc = p0 + wc * 32 + nt * 8 + tig * 2;
                float2 v0 = {c[mt][nt][0] + b0, c[mt][nt][1] + b0};
                float2 v1 = {c[mt][nt][2] + b1, c[mt][nt][3] + b1};
                *(float2*)&g_qk[r0 + pc] = v0;
                *(float2*)&g_qk[r1 + pc] = v1;
            }
        }
    } else {
        #pragma unroll
        for (int mt = 0; mt < 4; ++mt) {
            int jl = wr * 64 + mt * 16 + g;
            float b0 = g_bqk[128 + jl], b1 = g_bqk[128 + jl + 8];
            size_t r0 = ((size_t)(b * 128 + jl)) * NN;
            size_t r1 = r0 + (size_t)8 * NN;
            #pragma unroll
            for (int nt = 0; nt < 4; ++nt) {
                int pc = p0 + wc * 32 + nt * 8 + tig * 2;
                __nv_bfloat16 h0, l0, h1, l1;
                split_bf16(c[mt][nt][0] + b0, h0, l0);
                split_bf16(c[mt][nt][1] + b0, h1, l1);
                *(__nv_bfloat162*)&g_CH[r0 + pc] = {h0, h1};
                *(__nv_bfloat162*)&g_CL[r0 + pc] = {l0, l1};
                split_bf16(c[mt][nt][2] + b1, h0, l0);
                split_bf16(c[mt][nt][3] + b1, h1, l1);
                *(__nv_bfloat162*)&g_CH[r1 + pc] = {h0, h1};
                *(__nv_bfloat162*)&g_CL[r1 + pc] = {l0, l1};
            }
        }
    }
}

// ---------------- transpose q1/k1 rows to [p][j] bf16 hi/lo ----------------
__global__ void conv_qk() {
    __shared__ float sh[32][33];
    int b = blockIdx.z;
    int j0 = blockIdx.y * 32;
    int p0 = blockIdx.x * 32;
    int tx = threadIdx.x, ty = threadIdx.y;
    #pragma unroll
    for (int k = 0; k < 4; ++k) {
        int i = ty + k * 8;
        sh[i][tx] = g_qk[((size_t)(b * 128 + j0 + i)) * NN + p0 + tx];
    }
    __syncthreads();
    #pragma unroll
    for (int k = 0; k < 4; ++k) {
        int i = ty + k * 8;
        float v = sh[tx][i];
        __nv_bfloat16 h, l; split_bf16(v, h, l);
        size_t o = ((size_t)(b * NN + p0 + i)) * 128 + j0 + tx;
        g_QKTh[o] = h; g_QKTl[o] = l;
    }
}

// ---------------- spatial pass A ----------------
#define PAT 18432
#define PA_SMEM (6 * PAT + 2048)
__global__ void __launch_bounds__(256, 2) passA_tc() {
    extern __shared__ __align__(16) char smem[];
    unsigned sb = smem_u32(smem);
    int t = threadIdx.x;
    int wid = t >> 5, lid = t & 31;
    int b = blockIdx.y;
    int n0 = blockIdx.x * 128;
    int wr = wid & 1;
    int wc = wid >> 1;
    int g = lid >> 2, tig = lid & 3;

    #pragma unroll
    for (int rep = 0; rep < 4; ++rep) {
        int u = t + rep * 256;
        int r = u >> 3, q = u & 7;
        size_t src = ((size_t)b * NN + n0 + r) * 128 + q * 8;
        cpa16(sb + r * 144 + q * 16, g_QKTh + src);
        cpa16(sb + PAT + r * 144 + q * 16, g_QKTl + src);
    }
    #pragma unroll
    for (int rep = 0; rep < 4; ++rep) {
        int u = t + rep * 256;
        int r = u >> 3, q = u & 7;
        size_t src = ((size_t)b * NN + r) * 128 + 64 + q * 8;
        cpa16(sb + 2 * PAT + r * 144 + q * 16, g_QKTh + src);
        cpa16(sb + 3 * PAT + r * 144 + q * 16, g_QKTl + src);
    }
    CP_COMMIT();

    unsigned aAddrH = sb + (unsigned)((wr * 64 + (lid & 15)) * 144 + (lid >> 4) * 16);

    float zacc[8] = {};
    size_t ebase = ((size_t)b) << 24;

    for (int ch = 0; ch < 32; ++ch) {
        int m0 = ch * 128;
        if (ch + 1 < 32) {
            unsigned kb = 2 * PAT + ((ch + 1) & 1) * 2 * PAT;
            int m1 = (ch + 1) * 128;
            #pragma unroll
            for (int rep = 0; rep < 4; ++rep) {
                int u = t + rep * 256;
                int r = u >> 3, q = u & 7;
                size_t src = ((size_t)b * NN + m1 + r) * 128 + 64 + q * 8;
                cpa16(sb + kb + r * 144 + q * 16, g_QKTh + src);
                cpa16(sb + kb + PAT + r * 144 + q * 16, g_QKTl + src);
            }
            CP_COMMIT();
            CP_WAIT1();
        } else {
            CP_WAIT0();
        }
        __syncthreads();
        unsigned kb = 2 * PAT + (ch & 1) * 2 * PAT;
        unsigned bAddrH = sb + kb +
            (unsigned)((wc * 32 + ((lid >> 4) & 1) * 8 + (lid & 7)) * 144 + ((lid >> 3) & 1) * 16);
        float c[4][4][4] = {};
        #pragma unroll
        for (int ks = 0; ks < 4; ++ks) {
            unsigned bh[2][4], bl[2][4];
            ldsm4(bh[0], bAddrH + ks * 32);
            ldsm4(bh[1], bAddrH + 16 * 144 + ks * 32);
            ldsm4(bl[0], bAddrH + PAT + ks * 32);
            ldsm4(bl[1], bAddrH + PAT + 16 * 144 + ks * 32);
            #pragma unroll
            for (int mt = 0; mt < 4; ++mt) {
                unsigned ah[4], al[4];
                ldsm4(ah, aAddrH + mt * 2304 + ks * 32);
                ldsm4(al, aAddrH + PAT + mt * 2304 + ks * 32);
                #pragma unroll
                for (int nt = 0; nt < 4; ++nt) {
                    const unsigned* bhp = &bh[nt >> 1][(nt & 1) * 2];
                    const unsigned* blp = &bl[nt >> 1][(nt & 1) * 2];
                    mma_bf16(c[mt][nt], ah, bhp);
                    mma_bf16(c[mt][nt], ah, blp);
                    mma_bf16(c[mt][nt], al, bhp);
                }
            }
        }
        #pragma unroll
        for (int mt = 0; mt < 4; ++mt) {
            int n = n0 + wr * 64 + mt * 16 + g;
            #pragma unroll
            for (int nt = 0; nt < 4; ++nt) {
                int m = m0 + wc * 32 + nt * 8 + tig * 2;
                float e0 = fast_exp(c[mt][nt][0]);
                float e1 = fast_exp(c[mt][nt][1]);
                float e2 = fast_exp(c[mt][nt][2]);
                float e3 = fast_exp(c[mt][nt][3]);
                __nv_bfloat162 v0 = {__float2bfloat16(e0), __float2bfloat16(e1)};
                __nv_bfloat162 v1 = {__float2bfloat16(e2), __float2bfloat16(e3)};
                *(__nv_bfloat162*)&g_E2[ebase + (size_t)n * NN + m] = v0;
                *(__nv_bfloat162*)&g_E2[ebase + (size_t)(n + 8) * NN + m] = v1;
                zacc[mt * 2] += e0 + e1;
                zacc[mt * 2 + 1] += e2 + e3;
            }
        }
        __syncthreads();
    }

    float* zp = (float*)(smem + 6 * PAT);
    #pragma unroll
    for (int s = 0; s < 8; ++s) {
        float v = zacc[s];
        v += __shfl_xor_sync(0xFFFFFFFF, v, 1);
        v += __shfl_xor_sync(0xFFFFFFFF, v, 2);
        if (tig == 0)
            zp[wc * 128 + wr * 64 + (s >> 1) * 16 + (s & 1) * 8 + g] = v;
    }
    __syncthreads();
    if (t < 128) {
        float s = zp[t] + zp[128 + t] + zp[256 + t] + zp[384 + t];
        g_Zinv[b * NN + n0 + t] = 1.0f / s;
    }
}

// ---------------- Kz = k1 * Zinv -> bf16 hi/lo ----------------
__global__ void conv_kz() {
    int n = blockIdx.x * 256 + threadIdx.x;
    int r = blockIdx.y;
    int b = blockIdx.z;
    float v = g_qk[((size_t)(b * 128 + 64 + r)) * NN + n] * g_Zinv[b * NN + n];
    __nv_bfloat16 h, l; split_bf16(v, h, l);
    size_t o = ((size_t)b * 64 + r) * NN + n;
    g_KZh[o] = h; g_KZl[o] = l;
}

// ---------------- spatial pass B ----------------
#define PBS 35840
#define PB_SMEM (2 * PBS)
__global__ void __launch_bounds__(256, 2) passB_tc() {
    extern __shared__ __align__(16) char smem[];
    unsigned sb = smem_u32(smem);
    int t = threadIdx.x;
    int wid = t >> 5, lid = t & 31;
    int b = blockIdx.y;
    int m0 = blockIdx.x * 128;
    int g = lid >> 2, tig = lid & 3;

    float c[4][2][4] = {};
    size_t ebase = ((size_t)b) << 24;

    {
        #pragma unroll
        for (int rep = 0; rep < 2; ++rep) {
            int u = t + rep * 256;
            int r = u >> 3, q = u & 7;
            size_t src = ((size_t)b * 64 + r) * NN + q * 8;
            cpa16(sb + r * 144 + q * 16, g_KZh + src);
            cpa16(sb + 9216 + r * 144 + q * 16, g_KZl + src);
        }
        #pragma unroll
        for (int rep = 0; rep < 4; ++rep) {
            int u = t + rep * 256;
            int r = u >> 4, q = u & 15;
            cpa16(sb + 18432 + r * 272 + q * 16, g_E2 + ebase + (size_t)r * NN + m0 + q * 8);
        }
        CP_COMMIT();
    }

    for (int ch = 0; ch < 64; ++ch) {
        if (ch + 1 < 64) {
            unsigned boff = ((ch + 1) & 1) * PBS;
            int n1 = (ch + 1) * 64;
            #pragma unroll
            for (int rep = 0; rep < 2; ++rep) {
                int u = t + rep * 256;
                int r = u >> 3, q = u & 7;
                size_t src = ((size_t)b * 64 + r) * NN + n1 + q * 8;
                cpa16(sb + boff + r * 144 + q * 16, g_KZh + src);
                cpa16(sb + boff + 9216 + r * 144 + q * 16, g_KZl + src);
            }
            #pragma unroll
            for (int rep = 0; rep < 4; ++rep) {
                int u = t + rep * 256;
                int r = u >> 4, q = u & 15;
                cpa16(sb + boff + 18432 + r * 272 + q * 16,
                      g_E2 + ebase + (size_t)(n1 + r) * NN + m0 + q * 8);
            }
            CP_COMMIT();
            CP_WAIT1();
        } else {
            CP_WAIT0();
        }
        __syncthreads();
        unsigned boff = (ch & 1) * PBS;
        unsigned aAddrH = sb + boff + (unsigned)(((lid & 15)) * 144 + (lid >> 4) * 16);
        unsigned eAddr = sb + boff + 18432 +
            (unsigned)(((lid & 7) + ((lid >> 3) & 1) * 8) * 272 + (wid * 16 + (lid >> 4) * 8) * 2);
        #pragma unroll
        for (int ks = 0; ks < 4; ++ks) {
            unsigned eb[4];
            ldsm4t(eb, eAddr + ks * 16 * 272);
            #pragma unroll
            for (int mt = 0; mt < 4; ++mt) {
                unsigned ah[4], al[4];
                ldsm4(ah, aAddrH + mt * 2304 + ks * 32);
                ldsm4(al, aAddrH + 9216 + mt * 2304 + ks * 32);
                #pragma unroll
                for (int nt = 0; nt < 2; ++nt) {
                    mma_bf16(c[mt][nt], ah, &eb[nt * 2]);
                    mma_bf16(c[mt][nt], al, &eb[nt * 2]);
                }
            }
        }
        __syncthreads();
    }

    #pragma unroll
    for (int mt = 0; mt < 4; ++mt) {
        int r = mt * 16 + g;
        size_t r0 = ((size_t)(b * 128 + r)) * NN;
        size_t r1 = r0 + (size_t)8 * NN;
        #pragma unroll
        for (int nt = 0; nt < 2; ++nt) {
            int m = m0 + wid * 16 + nt * 8 + tig * 2;
            __nv_bfloat16 h0, l0, h1, l1;
            split_bf16(c[mt][nt][0], h0, l0);
            split_bf16(c[mt][nt][1], h1, l1);
            *(__nv_bfloat162*)&g_OSh[r0 + m] = {h0, h1};
            *(__nv_bfloat162*)&g_OSl[r0 + m] = {l0, l1};
            split_bf16(c[mt][nt][2], h0, l0);
            split_bf16(c[mt][nt][3], h1, l1);
            *(__nv_bfloat162*)&g_OSh[r1 + m] = {h0, h1};
            *(__nv_bfloat162*)&g_OSl[r1 + m] = {l0, l1};
        }
    }
}

// ---------------- channel Gram via HMMA ----------------
__global__ void __launch_bounds__(128) chan_gram_tc() {
    __shared__ __align__(16) char csm[4 * 9216];
    unsigned sb = smem_u32(csm);
    int t = threadIdx.x;
    int wid = t >> 5, lid = t & 31;
    int b = blockIdx.y;
    int chunk = blockIdx.x;
    int wr = wid & 1, wc = wid >> 1;
    int g = lid >> 2, tig = lid & 3;

    unsigned aAddr = sb + (unsigned)((wr * 32 + (lid & 15)) * 144 + (lid >> 4) * 16);
    unsigned bAddr = sb + 2 * 9216 +
        (unsigned)((wc * 32 + ((lid >> 4) & 1) * 8 + (lid & 7)) * 144 + ((lid >> 3) & 1) * 16);

    float c[2][4][4] = {};

    for (int sub = 0; sub < 8; ++sub) {
        int n0 = chunk * 512 + sub * 64;
        __syncthreads();
        #pragma unroll
        for (int rep = 0; rep < 4; ++rep) {
            int u = t + rep * 128;
            int r = u >> 3, q = u & 7;
            size_t sq = ((size_t)(b * 128 + r)) * NN + n0 + q * 8;
            size_t sk = ((size_t)(b * 128 + 64 + r)) * NN + n0 + q * 8;
            *(uint4*)(csm + r * 144 + q * 16) = *(const uint4*)(g_CH + sq);
            *(uint4*)(csm + 9216 + r * 144 + q * 16) = *(const uint4*)(g_CL + sq);
            *(uint4*)(csm + 2 * 9216 + r * 144 + q * 16) = *(const uint4*)(g_CH + sk);
            *(uint4*)(csm + 3 * 9216 + r * 144 + q * 16) = *(const uint4*)(g_CL + sk);
        }
        __syncthreads();
        #pragma unroll
        for (int ks = 0; ks < 4; ++ks) {
            unsigned bh[2][4], bl[2][4];
            ldsm4(bh[0], bAddr + ks * 32);
            ldsm4(bh[1], bAddr + 16 * 144 + ks * 32);
            ldsm4(bl[0], bAddr + 9216 + ks * 32);
            ldsm4(bl[1], bAddr + 9216 + 16 * 144 + ks * 32);
            #pragma unroll
            for (int mt = 0; mt < 2; ++mt) {
                unsigned ah[4], al[4];
                ldsm4(ah, aAddr + mt * 2304 + ks * 32);
                ldsm4(al, aAddr + 9216 + mt * 2304 + ks * 32);
                #pragma unroll
                for (int nt = 0; nt < 4; ++nt) {
                    const unsigned* bhp = &bh[nt >> 1][(nt & 1) * 2];
                    const unsigned* blp = &bl[nt >> 1][(nt & 1) * 2];
                    mma_bf16(c[mt][nt], ah, bhp);
                    mma_bf16(c[mt][nt], ah, blp);
                    mma_bf16(c[mt][nt], al, bhp);
                }
            }
        }
    }

    float* gp = &g_Gp[(b * 8 + chunk) * 4096];
    #pragma unroll
    for (int mt = 0; mt < 2; ++mt) {
        int r = wr * 32 + mt * 16 + g;
        #pragma unroll
        for (int nt = 0; nt < 4; ++nt) {
            int s = wc * 32 + nt * 8 + tig * 2;
            *(float2*)&gp[r * 64 + s] = {c[mt][nt][0], c[mt][nt][1]};
            *(float2*)&gp[(r + 8) * 64 + s] = {c[mt][nt][2], c[mt][nt][3]};
        }
    }
}

__global__ void chan_softmax() {
    int r = blockIdx.x;
    int b = blockIdx.y;
    int s = threadIdx.x;
    __shared__ float red[64];
    float v = 0.f;
    #pragma unroll
    for (int ch = 0; ch < 8; ++ch)
        v += g_Gp[(b * 8 + ch) * 4096 + r * 64 + s];
    red[s] = v;
    __syncthreads();
    for (int off = 32; off >= 1; off >>= 1) {
        if (s < off) red[s] = fmaxf(red[s], red[s + off]);
        __syncthreads();
    }
    float mx = red[0];
    __syncthreads();
    float e = __expf(v - mx);
    red[s] = e;
    __syncthreads();
    for (int off = 32; off >= 1; off >>= 1) {
        if (s < off) red[s] += red[s + off];
        __syncthreads();
    }
    g_A[b * 4096 + r * 64 + s] = e / red[0];
}

__global__ void __launch_bounds__(256) chan_out() {
    int b = blockIdx.y;
    int p = blockIdx.x * 256 + threadIdx.x;
    __shared__ __align__(16) float As[64][64];
    #pragma unroll
    for (int k = 0; k < 16; ++k)
        (&As[0][0])[threadIdx.x + k * 256] = g_A[b * 4096 + threadIdx.x + k * 256];
    __syncthreads();
    float kreg[64];
    #pragma unroll
    for (int s = 0; s < 64; ++s) {
        size_t o = ((size_t)(b * 128 + 64 + s)) * NN + p;
        kreg[s] = __bfloat162float(g_CH[o]) + __bfloat162float(g_CL[o]);
    }
    ull kp2[32];
    #pragma unroll
    for (int s = 0; s < 32; ++s) {
        ull r; asm("mov.b64 %0, {%1, %2};" : "=l"(r) : "f"(kreg[2 * s]), "f"(kreg[2 * s + 1]));
        kp2[s] = r;
    }
    #pragma unroll 2
    for (int r = 0; r < 64; ++r) {
        ull acc = 0;
        const ull* arow = (const ull*)&As[r][0];
        #pragma unroll
        for (int s = 0; s < 32; ++s)
            fma2(acc, arow[s], kp2[s]);
        float lo, hi;
        unpack2(acc, lo, hi);
        float v = lo + hi;
        __nv_bfloat16 h, l; split_bf16(v, h, l);
        size_t o = ((size_t)(b * 128 + 64 + r)) * NN + p;
        g_OSh[o] = h; g_OSl[o] = l;
    }
}

// ---------------- final GEMM via HMMA (3-pass) ----------------
#define FT_SMEM 139264
__global__ void __launch_bounds__(256) final_tc(float* __restrict__ out) {
    extern __shared__ __align__(16) char smem[];
    unsigned sb = smem_u32(smem);
    int t = threadIdx.x;
    int wid = t >> 5, lid = t & 31;
    int b = blockIdx.z;
    int o0 = blockIdx.y * 128;
    int p0 = blockIdx.x * 128;
    int wr = wid & 1, wc = wid >> 1;
    int g = lid >> 2, tig = lid & 3;

    #pragma unroll
    for (int rep = 0; rep < 8; ++rep) {
        int u = t + rep * 256;
        int r = u >> 4, q = u & 15;
        *(uint4*)(smem + r * 272 + q * 16) = *(const uint4*)(g_WCh + (size_t)(o0 + r) * 128 + q * 8);
        *(uint4*)(smem + 34816 + r * 272 + q * 16) = *(const uint4*)(g_WCl + (size_t)(o0 + r) * 128 + q * 8);
        size_t bs = ((size_t)(b * 128 + r)) * NN + p0 + q * 8;
        *(uint4*)(smem + 69632 + r * 272 + q * 16) = *(const uint4*)(g_OSh + bs);
        *(uint4*)(smem + 104448 + r * 272 + q * 16) = *(const uint4*)(g_OSl + bs);
    }
    __syncthreads();

    unsigned aAddr = sb + (unsigned)((wr * 64 + (lid & 15)) * 272 + (lid >> 4) * 16);
    unsigned eAddr = sb + 69632 +
        (unsigned)(((lid & 7) + ((lid >> 3) & 1) * 8) * 272 + (wc * 32 + (lid >> 4) * 8) * 2);

    float c[4][4][4] = {};
    #pragma unroll
    for (int ks = 0; ks < 8; ++ks) {
        unsigned bh[2][4], bl[2][4];
        ldsm4t(bh[0], eAddr + ks * 16 * 272);
        ldsm4t(bh[1], eAddr + ks * 16 * 272 + 32);
        ldsm4t(bl[0], eAddr + 34816 + ks * 16 * 272);
        ldsm4t(bl[1], eAddr + 34816 + ks * 16 * 272 + 32);
        #pragma unroll
        for (int mt = 0; mt < 4; ++mt) {
            unsigned ah[4], al[4];
            ldsm4(ah, aAddr + mt * 16 * 272 + ks * 32);
            ldsm4(al, aAddr + 34816 + mt * 16 * 272 + ks * 32);
            #pragma unroll
            for (int nt = 0; nt < 4; ++nt) {
                const unsigned* bhp = &bh[nt >> 1][(nt & 1) * 2];
                const unsigned* blp = &bl[nt >> 1][(nt & 1) * 2];
                mma_bf16(c[mt][nt], ah, bhp);
                mma_bf16(c[mt][nt], ah, blp);
                mma_bf16(c[mt][nt], al, bhp);
            }
        }
    }

    #pragma unroll
    for (int mt = 0; mt < 4; ++mt) {
        int o = o0 + wr * 64 + mt * 16 + g;
        float b0 = g_bout[o], b1 = g_bout[o + 8];
        size_t r0 = ((size_t)(b * 512 + o)) * NN;
        size_t r1 = r0 + (size_t)8 * NN;
        #pragma unroll
        for (int nt = 0; nt < 4; ++nt) {
            int pc = p0 + wc * 32 + nt * 8 + tig * 2;
            float2 v0 = {c[mt][nt][0] + b0, c[mt][nt][1] + b0};
            float2 v1 = {c[mt][nt][2] + b1, c[mt][nt][3] + b1};
            *(float2*)&out[r0 + pc] = v0;
            *(float2*)&out[r1 + pc] = v1;
        }
    }
}

// ---------------- launch ----------------
extern "C" void kernel_launch(void* const* d_in, const int* in_sizes, int n_in,
                              void* d_out, int out_size) {
    const float* top  = (const float*)d_in[0];
    const float* bot  = (const float*)d_in[1];
    const float* wt   = (const float*)d_in[2];
    const float* bt   = (const float*)d_in[3];
    const float* wb   = (const float*)d_in[4];
    const float* bb   = (const float*)d_in[5];
    const float* s_w1 = (const float*)d_in[6];
    const float* s_b1 = (const float*)d_in[7];
    const float* s_w2 = (const float*)d_in[8];
    const float* s_b2 = (const float*)d_in[9];
    const float* s_wo = (const float*)d_in[10];
    const float* s_bo = (const float*)d_in[11];
    const float* c_wq = (const float*)d_in[12];
    const float* c_bq = (const float*)d_in[13];
    const float* c_wk = (const float*)d_in[14];
    const float* c_bk = (const float*)d_in[15];
    const float* c_wo = (const float*)d_in[16];
    const float* c_bo = (const float*)d_in[17];
    const float* f_w  = (const float*)d_in[18];
    const float* f_b  = (const float*)d_in[19];
    float* out = (float*)d_out;

    static cudaStream_t s2 = 0;
    static cudaEvent_t evStart = 0, evPre = 0, evQk = 0, evChan = 0;
    if (!s2) {
        cudaStreamCreateWithFlags(&s2, cudaStreamNonBlocking);
        cudaEventCreateWithFlags(&evStart, cudaEventDisableTiming);
        cudaEventCreateWithFlags(&evPre, cudaEventDisableTiming);
        cudaEventCreateWithFlags(&evQk, cudaEventDisableTiming);
        cudaEventCreateWithFlags(&evChan, cudaEventDisableTiming);
        cudaFuncSetAttribute(qk_tc3, cudaFuncAttributeMaxDynamicSharedMemorySize, QK3_SMEM);
        cudaFuncSetAttribute(passA_tc, cudaFuncAttributeMaxDynamicSharedMemorySize, PA_SMEM);
        cudaFuncSetAttribute(passB_tc, cudaFuncAttributeMaxDynamicSharedMemorySize, PB_SMEM);
        cudaFuncSetAttribute(final_tc, cudaFuncAttributeMaxDynamicSharedMemorySize, FT_SMEM);
    }

    // fork s2 off the main (capture) stream
    cudaEventRecord(evStart, 0);
    cudaStreamWaitEvent(s2, evStart, 0);

    // s0: weight folds; s2: input convert + output-weight fold
    fold_qkw<<<512, 256>>>(wt, wb, s_w1, s_w2, c_wq, c_wk);
    fold_bias<<<1, 512>>>(bt, bb, s_b1, s_b2, c_bq, c_bk, f_w, s_bo, c_bo, f_b,
                          s_w1, s_w2, c_wq, c_wk);
    conv_x<<<dim3(128, 32, 8), dim3(32, 8), 0, s2>>>(top, bot);
    fold_outc<<<256, 256, 0, s2>>>(f_w, s_wo, c_wo);
    cudaEventRecord(evPre, s2);
    cudaStreamWaitEvent(0, evPre, 0);

    // s0: big qk GEMM
    qk_tc3<<<dim3(32, 2, 8), 256, QK3_SMEM>>>();
    cudaEventRecord(evQk, 0);

    // s2: channel branch (depends only on qk output CH/CL)
    cudaStreamWaitEvent(s2, evQk, 0);
    chan_gram_tc<<<dim3(8, 8), 128, 0, s2>>>();
    chan_softmax<<<dim3(64, 8), 64, 0, s2>>>();
    chan_out<<<dim3(16, 8), 256, 0, s2>>>();
    cudaEventRecord(evChan, s2);

    // s0: spatial branch
    conv_qk<<<dim3(128, 4, 8), dim3(32, 8)>>>();
    passA_tc<<<dim3(32, 8), 256, PA_SMEM>>>();
    conv_kz<<<dim3(16, 64, 8), 256>>>();
    passB_tc<<<dim3(32, 8), 256, PB_SMEM>>>();

    // join and finish
    cudaStreamWaitEvent(0, evChan, 0);
    final_tc<<<dim3(32, 4, 8), 256, FT_SMEM>>>(out);
}

// round 11
// speedup vs baseline: 2.3635x; 1.0051x over previous
#include <cuda_runtime.h>
#include <cuda_bf16.h>
#include <stdint.h>
#include <math.h>

#define BB 8
#define NN 4096

typedef unsigned long long ull;

__device__ __forceinline__ ull dup2(float x) {
    ull r; asm("mov.b64 %0, {%1, %1};" : "=l"(r) : "f"(x)); return r;
}
__device__ __forceinline__ void unpack2(ull v, float& x, float& y) {
    asm("mov.b64 {%0, %1}, %2;" : "=f"(x), "=f"(y) : "l"(v));
}
__device__ __forceinline__ void fma2(ull& d, ull a, ull b) {
    asm("fma.rn.f32x2 %0, %1, %2, %0;" : "+l"(d) : "l"(a), "l"(b));
}

__device__ __forceinline__ unsigned smem_u32(const void* p) {
    unsigned a;
    asm("{ .reg .u64 t; cvta.to.shared.u64 t, %1; cvt.u32.u64 %0, t; }" : "=r"(a) : "l"(p));
    return a;
}
__device__ __forceinline__ void ldsm4(unsigned* r, unsigned addr) {
    asm volatile("ldmatrix.sync.aligned.m8n8.x4.shared.b16 {%0,%1,%2,%3}, [%4];"
        : "=r"(r[0]), "=r"(r[1]), "=r"(r[2]), "=r"(r[3]) : "r"(addr));
}
__device__ __forceinline__ void ldsm4t(unsigned* r, unsigned addr) {
    asm volatile("ldmatrix.sync.aligned.m8n8.x4.trans.shared.b16 {%0,%1,%2,%3}, [%4];"
        : "=r"(r[0]), "=r"(r[1]), "=r"(r[2]), "=r"(r[3]) : "r"(addr));
}
__device__ __forceinline__ void mma_bf16(float* c, const unsigned* a, const unsigned* b) {
    asm volatile("mma.sync.aligned.m16n8k16.row.col.f32.bf16.bf16.f32 "
        "{%0,%1,%2,%3}, {%4,%5,%6,%7}, {%8,%9}, {%0,%1,%2,%3};"
        : "+f"(c[0]), "+f"(c[1]), "+f"(c[2]), "+f"(c[3])
        : "r"(a[0]), "r"(a[1]), "r"(a[2]), "r"(a[3]), "r"(b[0]), "r"(b[1]));
}
__device__ __forceinline__ void cpa16(unsigned s, const void* g) {
    asm volatile("cp.async.ca.shared.global [%0], [%1], 16;" :: "r"(s), "l"(g));
}
#define CP_COMMIT() asm volatile("cp.async.commit_group;" ::: "memory")
#define CP_WAIT0() asm volatile("cp.async.wait_group 0;" ::: "memory")
#define CP_WAIT1() asm volatile("cp.async.wait_group 1;" ::: "memory")

// packed f32x2 exp: magic-number round + 5-term exp2 poly, all on FMA pipe
__device__ __forceinline__ void fexp2x(float x0, float x1, float& r0, float& r1) {
    ull x; asm("mov.b64 %0, {%1, %2};" : "=l"(x) : "f"(x0), "f"(x1));
    ull y; asm("mul.rn.f32x2 %0, %1, %2;" : "=l"(y) : "l"(x), "l"(dup2(1.4426950408889634f)));
    ull tt; asm("add.rn.f32x2 %0, %1, %2;" : "=l"(tt) : "l"(y), "l"(dup2(12582912.0f)));
    ull n; asm("add.rn.f32x2 %0, %1, %2;" : "=l"(n) : "l"(tt), "l"(dup2(-12582912.0f)));
    ull f = y; fma2(f, n, dup2(-1.0f));                       // f = y - n
    ull p = dup2(9.6181291076e-3f);  fma2(p, dup2(1.3333558146e-3f), f);
    ull p2 = dup2(5.5504108664e-2f); fma2(p2, p, f);
    ull p3 = dup2(2.4022650696e-1f); fma2(p3, p2, f);
    ull p4 = dup2(6.9314718056e-1f); fma2(p4, p3, f);
    ull p5 = dup2(1.0f);             fma2(p5, p4, f);
    unsigned i0, i1;
    asm("mov.b64 {%0, %1}, %2;" : "=r"(i0), "=r"(i1) : "l"(tt));
    float s0 = __uint_as_float((i0 + 127u) << 23);
    float s1 = __uint_as_float((i1 + 127u) << 23);
    float q0, q1; unpack2(p5, q0, q1);
    r0 = q0 * s0; r1 = q1 * s1;
}

__device__ __forceinline__ void fma2s(ull& d, ull a, ull b) { fma2(d, a, b); }

__device__ __forceinline__ void split_bf16(float v, __nv_bfloat16& h, __nv_bfloat16& l) {
    h = __float2bfloat16(v);
    l = __float2bfloat16(v - __bfloat162float(h));
}

// ---------------- scratch ----------------
__device__ float g_bqk[256];
__device__ float g_bout[512];
__device__ float g_qk[(size_t)BB * 128 * NN];            // rows 64-127: k1 fp32 (rows 0-63 unused)
__device__ __nv_bfloat16 g_E2[(size_t)BB * NN * NN];
__device__ float g_Zinv[BB * NN];
__device__ float g_Gp[BB * 8 * 64 * 64];
__device__ float g_A[BB * 64 * 64];
__device__ __nv_bfloat16 g_Wh[256 * 1024];
__device__ __nv_bfloat16 g_Wl[256 * 1024];
__device__ __nv_bfloat16 g_Xh[(size_t)BB * NN * 1024];
__device__ __nv_bfloat16 g_Xl[(size_t)BB * NN * 1024];
__device__ __nv_bfloat16 g_QKTh[(size_t)BB * NN * 128];
__device__ __nv_bfloat16 g_QKTl[(size_t)BB * NN * 128];
__device__ __nv_bfloat16 g_KZh[(size_t)BB * 64 * NN];
__device__ __nv_bfloat16 g_KZl[(size_t)BB * 64 * NN];
__device__ __nv_bfloat16 g_OSh[(size_t)BB * 128 * NN];
__device__ __nv_bfloat16 g_OSl[(size_t)BB * 128 * NN];
__device__ __nv_bfloat16 g_WCh[512 * 128];
__device__ __nv_bfloat16 g_WCl[512 * 128];
__device__ __nv_bfloat16 g_CH[(size_t)BB * 128 * NN];
__device__ __nv_bfloat16 g_CL[(size_t)BB * 128 * NN];

// ---------------- fused weight folding + bf16 split ----------------
__global__ void fold_qkw(const float* __restrict__ wt, const float* __restrict__ wb,
                         const float* __restrict__ sw1, const float* __restrict__ sw2,
                         const float* __restrict__ cwq, const float* __restrict__ cwk) {
    int idx = blockIdx.x * blockDim.x + threadIdx.x;
    int j = idx >> 9, c = idx & 511;
    const float* wrow; int uoff;
    if (j < 64)       { wrow = sw1 + j * 256;        uoff = 0;   }
    else if (j < 128) { wrow = sw2 + (j - 64) * 256; uoff = 0;   }
    else if (j < 192) { wrow = cwq + (j - 128) * 256; uoff = 256; }
    else              { wrow = cwk + (j - 192) * 256; uoff = 256; }
    float at = 0.f, ab = 0.f;
    #pragma unroll 8
    for (int u = 0; u < 256; ++u) {
        float w = wrow[u];
        at = fmaf(w, wt[(uoff + u) * 512 + c], at);
        ab = fmaf(w, wb[(uoff + u) * 512 + c], ab);
    }
    __nv_bfloat16 h, l;
    split_bf16(at, h, l);
    g_Wh[j * 1024 + c] = h; g_Wl[j * 1024 + c] = l;
    split_bf16(ab, h, l);
    g_Wh[j * 1024 + 512 + c] = h; g_Wl[j * 1024 + 512 + c] = l;
}

__global__ void fold_outc(const float* __restrict__ fw, const float* __restrict__ swo,
                          const float* __restrict__ cwo) {
    int idx = blockIdx.x * blockDim.x + threadIdx.x;
    int o = idx >> 7, t = idx & 127;
    float acc = 0.f;
    if (t < 64) {
        #pragma unroll 8
        for (int u = 0; u < 256; ++u)
            acc = fmaf(fw[o * 512 + u], swo[u * 64 + t], acc);
    } else {
        int r = t - 64;
        #pragma unroll 8
        for (int u = 0; u < 256; ++u)
            acc = fmaf(fw[o * 512 + 256 + u], cwo[u * 64 + r], acc);
    }
    __nv_bfloat16 h, l; split_bf16(acc, h, l);
    g_WCh[idx] = h; g_WCl[idx] = l;
}

__global__ void fold_bias(const float* __restrict__ bt, const float* __restrict__ bb,
                          const float* __restrict__ sb1, const float* __restrict__ sb2,
                          const float* __restrict__ cbq, const float* __restrict__ cbk,
                          const float* __restrict__ fw,  const float* __restrict__ sbo,
                          const float* __restrict__ cbo, const float* __restrict__ fb,
                          const float* __restrict__ sw1, const float* __restrict__ sw2,
                          const float* __restrict__ cwq, const float* __restrict__ cwk) {
    int t = threadIdx.x;   // 512
    if (t < 256) {
        const float* wrow; int uoff; float ob;
        int j = t;
        if (j < 64)       { wrow = sw1 + j * 256;        uoff = 0;   ob = sb1[j];       }
        else if (j < 128) { wrow = sw2 + (j - 64) * 256; uoff = 0;   ob = sb2[j - 64];  }
        else if (j < 192) { wrow = cwq + (j - 128) * 256; uoff = 256; ob = cbq[j - 128]; }
        else              { wrow = cwk + (j - 192) * 256; uoff = 256; ob = cbk[j - 192]; }
        float s = ob;
        for (int u = 0; u < 256; ++u)
            s = fmaf(wrow[u], bt[uoff + u] + bb[uoff + u], s);
        g_bqk[j] = s;
    }
    float s2 = fb[t];
    for (int u = 0; u < 256; ++u) {
        s2 = fmaf(fw[t * 512 + u],       sbo[u], s2);
        s2 = fmaf(fw[t * 512 + 256 + u], cbo[u], s2);
    }
    g_bout[t] = s2;
}

__global__ void conv_x(const float* __restrict__ top, const float* __restrict__ bot) {
    __shared__ float sh[32][33];
    int b = blockIdx.z;
    int c0 = blockIdx.y * 32;
    int p0 = blockIdx.x * 32;
    const float* src = (c0 < 512) ? top : bot;
    int cs = c0 & 511;
    int tx = threadIdx.x, ty = threadIdx.y;
    #pragma unroll
    for (int k = 0; k < 4; ++k) {
        int i = ty + k * 8;
        sh[i][tx] = src[((size_t)(b * 512 + cs + i)) * NN + p0 + tx];
    }
    __syncthreads();
    #pragma unroll
    for (int k = 0; k < 4; ++k) {
        int i = ty + k * 8;
        float v = sh[tx][i];
        __nv_bfloat16 h, l; split_bf16(v, h, l);
        size_t o = ((size_t)(b * NN + p0 + i)) * 1024 + c0 + tx;
        g_Xh[o] = h; g_Xl[o] = l;
    }
}

// ---------------- qk GEMM via HMMA + cp.async double buffer ----------------
// y==0 epilogue also produces transposed QKT bf16 hi/lo via smem staging.
#define TS (128 * 72 * 2)
#define QK3_SMEM (8 * TS)
__global__ void __launch_bounds__(256) qk_tc3() {
    extern __shared__ __align__(16) char smem[];
    unsigned sb = smem_u32(smem);
    int t = threadIdx.x;
    int wid = t >> 5, lid = t & 31;
    int b = blockIdx.z;
    int j0 = blockIdx.y * 128;
    int p0 = blockIdx.x * 128;
    int wr = wid & 1;
    int wc = wid >> 1;

    const __nv_bfloat16* srcs[4] = {
        g_Wh + (size_t)j0 * 1024,
        g_Wl + (size_t)j0 * 1024,
        g_Xh + ((size_t)b * NN + p0) * 1024,
        g_Xl + ((size_t)b * NN + p0) * 1024
    };

    float c[4][4][4] = {};

    {
        #pragma unroll
        for (int tile = 0; tile < 4; ++tile) {
            unsigned base = sb + tile * TS;
            const __nv_bfloat16* s = srcs[tile];
            #pragma unroll
            for (int rep = 0; rep < 4; ++rep) {
                int u = t + rep * 256;
                int r = u >> 3, q = u & 7;
                cpa16(base + r * 144 + q * 16, s + (size_t)r * 1024 + q * 8);
            }
        }
        CP_COMMIT();
    }

    for (int ch = 0; ch < 16; ++ch) {
        if (ch + 1 < 16) {
            unsigned boff = ((ch + 1) & 1) * (4 * TS);
            int c0 = (ch + 1) * 64;
            #pragma unroll
            for (int tile = 0; tile < 4; ++tile) {
                unsigned base = sb + boff + tile * TS;
                const __nv_bfloat16* s = srcs[tile];
                #pragma unroll
                for (int rep = 0; rep < 4; ++rep) {
                    int u = t + rep * 256;
                    int r = u >> 3, q = u & 7;
                    cpa16(base + r * 144 + q * 16, s + (size_t)r * 1024 + c0 + q * 8);
                }
            }
            CP_COMMIT();
            CP_WAIT1();
        } else {
            CP_WAIT0();
        }
        __syncthreads();
        unsigned abase = sb + (ch & 1) * (4 * TS);
        unsigned aAddr = abase + (unsigned)((wr * 64 + (lid & 15)) * 144 + (lid >> 4) * 16);
        unsigned bAddr = abase + 2 * TS +
            (unsigned)((wc * 32 + ((lid >> 4) & 1) * 8 + (lid & 7)) * 144 + ((lid >> 3) & 1) * 16);
        #pragma unroll
        for (int ks = 0; ks < 4; ++ks) {
            unsigned bh[2][4], bl[2][4];
            ldsm4(bh[0], bAddr + ks * 32);
            ldsm4(bh[1], bAddr + 16 * 144 + ks * 32);
            ldsm4(bl[0], bAddr + TS + ks * 32);
            ldsm4(bl[1], bAddr + TS + 16 * 144 + ks * 32);
            #pragma unroll
            for (int mt = 0; mt < 4; ++mt) {
                unsigned ah[4], al[4];
                ldsm4(ah, aAddr + mt * 2304 + ks * 32);
                ldsm4(al, aAddr + TS + mt * 2304 + ks * 32);
                #pragma unroll
                for (int nt = 0; nt < 4; ++nt) {
                    const unsigned* bhp = &bh[nt >> 1][(nt & 1) * 2];
                    const unsigned* blp = &bl[nt >> 1][(nt & 1) * 2];
                    mma_bf16(c[mt][nt], ah, bhp);
                    mma_bf16(c[mt][nt], ah, blp);
                    mma_bf16(c[mt][nt], al, bhp);
                }
            }
        }
        __syncthreads();
    }

    int g = lid >> 2, tig = lid & 3;
    if (blockIdx.y == 0) {
        // q1/k1: stage bf16 hi/lo transpose in smem, write QKT; k1 rows also fp32 to g_qk
        __nv_bfloat16* Th = (__nv_bfloat16*)smem;          // [128][136]
        __nv_bfloat16* Tl = Th + 128 * 136;
        #pragma unroll
        for (int mt = 0; mt < 4; ++mt) {
            int jrow = wr * 64 + mt * 16 + g;
            float b0 = g_bqk[jrow], b1 = g_bqk[jrow + 8];
            #pragma unroll
            for (int nt = 0; nt < 4; ++nt) {
                int p = wc * 32 + nt * 8 + tig * 2;
                float v0 = c[mt][nt][0] + b0;
                float v1 = c[mt][nt][1] + b0;
                float v2 = c[mt][nt][2] + b1;
                float v3 = c[mt][nt][3] + b1;
                __nv_bfloat16 h, l;
                split_bf16(v0, h, l); Th[p * 136 + jrow] = h;       Tl[p * 136 + jrow] = l;
                split_bf16(v1, h, l); Th[(p + 1) * 136 + jrow] = h; Tl[(p + 1) * 136 + jrow] = l;
                split_bf16(v2, h, l); Th[p * 136 + jrow + 8] = h;   Tl[p * 136 + jrow + 8] = l;
                split_bf16(v3, h, l); Th[(p + 1) * 136 + jrow + 8] = h; Tl[(p + 1) * 136 + jrow + 8] = l;
                if (wr == 1) {
                    size_t r0 = ((size_t)(b * 128 + jrow)) * NN;
                    size_t r1 = r0 + (size_t)8 * NN;
                    *(float2*)&g_qk[r0 + p0 + p] = {v0, v1};
                    *(float2*)&g_qk[r1 + p0 + p] = {v2, v3};
                }
            }
        }
        __syncthreads();
        #pragma unroll
        for (int rep = 0; rep < 8; ++rep) {
            int u = t + rep * 256;
            int r = u >> 4, q = u & 15;
            size_t dst = ((size_t)(b * NN + p0 + r)) * 128 + q * 8;
            *(uint4*)(g_QKTh + dst) = *(const uint4*)&Th[r * 136 + q * 8];
            *(uint4*)(g_QKTl + dst) = *(const uint4*)&Tl[r * 136 + q * 8];
        }
    } else {
        #pragma unroll
        for (int mt = 0; mt < 4; ++mt) {
            int jl = wr * 64 + mt * 16 + g;
            float b0 = g_bqk[128 + jl], b1 = g_bqk[128 + jl + 8];
            size_t r0 = ((size_t)(b * 128 + jl)) * NN;
            size_t r1 = r0 + (size_t)8 * NN;
            #pragma unroll
            for (int nt = 0; nt < 4; ++nt) {
                int pc = p0 + wc * 32 + nt * 8 + tig * 2;
                __nv_bfloat16 h0, l0, h1, l1;
                split_bf16(c[mt][nt][0] + b0, h0, l0);
                split_bf16(c[mt][nt][1] + b0, h1, l1);
                *(__nv_bfloat162*)&g_CH[r0 + pc] = {h0, h1};
                *(__nv_bfloat162*)&g_CL[r0 + pc] = {l0, l1};
                split_bf16(c[mt][nt][2] + b1, h0, l0);
                split_bf16(c[mt][nt][3] + b1, h1, l1);
                *(__nv_bfloat162*)&g_CH[r1 + pc] = {h0, h1};
                *(__nv_bfloat162*)&g_CL[r1 + pc] = {l0, l1};
            }
        }
    }
}

// ---------------- spatial pass A (HMMA + packed exp + fused Kz epilogue) ----------------
#define PAT 18432
#define PA_SMEM (6 * PAT + 2048 + 512)
__global__ void __launch_bounds__(256, 2) passA_tc() {
    extern __shared__ __align__(16) char smem[];
    unsigned sb = smem_u32(smem);
    int t = threadIdx.x;
    int wid = t >> 5, lid = t & 31;
    int b = blockIdx.y;
    int n0 = blockIdx.x * 128;
    int wr = wid & 1;
    int wc = wid >> 1;
    int g = lid >> 2, tig = lid & 3;

    #pragma unroll
    for (int rep = 0; rep < 4; ++rep) {
        int u = t + rep * 256;
        int r = u >> 3, q = u & 7;
        size_t src = ((size_t)b * NN + n0 + r) * 128 + q * 8;
        cpa16(sb + r * 144 + q * 16, g_QKTh + src);
        cpa16(sb + PAT + r * 144 + q * 16, g_QKTl + src);
    }
    #pragma unroll
    for (int rep = 0; rep < 4; ++rep) {
        int u = t + rep * 256;
        int r = u >> 3, q = u & 7;
        size_t src = ((size_t)b * NN + r) * 128 + 64 + q * 8;
        cpa16(sb + 2 * PAT + r * 144 + q * 16, g_QKTh + src);
        cpa16(sb + 3 * PAT + r * 144 + q * 16, g_QKTl + src);
    }
    CP_COMMIT();

    unsigned aAddrH = sb + (unsigned)((wr * 64 + (lid & 15)) * 144 + (lid >> 4) * 16);

    float zacc[8] = {};
    size_t ebase = ((size_t)b) << 24;

    for (int ch = 0; ch < 32; ++ch) {
        int m0 = ch * 128;
        if (ch + 1 < 32) {
            unsigned kb = 2 * PAT + ((ch + 1) & 1) * 2 * PAT;
            int m1 = (ch + 1) * 128;
            #pragma unroll
            for (int rep = 0; rep < 4; ++rep) {
                int u = t + rep * 256;
                int r = u >> 3, q = u & 7;
                size_t src = ((size_t)b * NN + m1 + r) * 128 + 64 + q * 8;
                cpa16(sb + kb + r * 144 + q * 16, g_QKTh + src);
                cpa16(sb + kb + PAT + r * 144 + q * 16, g_QKTl + src);
            }
            CP_COMMIT();
            CP_WAIT1();
        } else {
            CP_WAIT0();
        }
        __syncthreads();
        unsigned kb = 2 * PAT + (ch & 1) * 2 * PAT;
        unsigned bAddrH = sb + kb +
            (unsigned)((wc * 32 + ((lid >> 4) & 1) * 8 + (lid & 7)) * 144 + ((lid >> 3) & 1) * 16);
        float c[4][4][4] = {};
        #pragma unroll
        for (int ks = 0; ks < 4; ++ks) {
            unsigned bh[2][4], bl[2][4];
            ldsm4(bh[0], bAddrH + ks * 32);
            ldsm4(bh[1], bAddrH + 16 * 144 + ks * 32);
            ldsm4(bl[0], bAddrH + PAT + ks * 32);
            ldsm4(bl[1], bAddrH + PAT + 16 * 144 + ks * 32);
            #pragma unroll
            for (int mt = 0; mt < 4; ++mt) {
                unsigned ah[4], al[4];
                ldsm4(ah, aAddrH + mt * 2304 + ks * 32);
                ldsm4(al, aAddrH + PAT + mt * 2304 + ks * 32);
                #pragma unroll
                for (int nt = 0; nt < 4; ++nt) {
                    const unsigned* bhp = &bh[nt >> 1][(nt & 1) * 2];
                    const unsigned* blp = &bl[nt >> 1][(nt & 1) * 2];
                    mma_bf16(c[mt][nt], ah, bhp);
                    mma_bf16(c[mt][nt], ah, blp);
                    mma_bf16(c[mt][nt], al, bhp);
                }
            }
        }
        #pragma unroll
        for (int mt = 0; mt < 4; ++mt) {
            int n = n0 + wr * 64 + mt * 16 + g;
            #pragma unroll
            for (int nt = 0; nt < 4; ++nt) {
                int m = m0 + wc * 32 + nt * 8 + tig * 2;
                float e0, e1, e2, e3;
                fexp2x(c[mt][nt][0], c[mt][nt][1], e0, e1);
                fexp2x(c[mt][nt][2], c[mt][nt][3], e2, e3);
                __nv_bfloat162 v0 = {__float2bfloat16(e0), __float2bfloat16(e1)};
                __nv_bfloat162 v1 = {__float2bfloat16(e2), __float2bfloat16(e3)};
                *(__nv_bfloat162*)&g_E2[ebase + (size_t)n * NN + m] = v0;
                *(__nv_bfloat162*)&g_E2[ebase + (size_t)(n + 8) * NN + m] = v1;
                zacc[mt * 2] += e0 + e1;
                zacc[mt * 2 + 1] += e2 + e3;
            }
        }
        __syncthreads();
    }

    float* zp = (float*)(smem + 6 * PAT);
    float* zsm = (float*)(smem + 6 * PAT + 2048);   // 128 Zinv values
    #pragma unroll
    for (int s = 0; s < 8; ++s) {
        float v = zacc[s];
        v += __shfl_xor_sync(0xFFFFFFFF, v, 1);
        v += __shfl_xor_sync(0xFFFFFFFF, v, 2);
        if (tig == 0)
            zp[wc * 128 + wr * 64 + (s >> 1) * 16 + (s & 1) * 8 + g] = v;
    }
    __syncthreads();
    if (t < 128) {
        float s = zp[t] + zp[128 + t] + zp[256 + t] + zp[384 + t];
        float zi = 1.0f / s;
        g_Zinv[b * NN + n0 + t] = zi;
        zsm[t] = zi;
    }
    __syncthreads();

    // fused Kz epilogue: Kz[r][n] = k1[r][n] * Zinv[n], bf16 hi/lo
    #pragma unroll
    for (int rep = 0; rep < 8; ++rep) {
        int idx = t + rep * 256;          // 0..2047
        int r = idx >> 5;                 // 0..63
        int nq = (idx & 31) * 4;          // 0..124
        float4 k4 = *(const float4*)&g_qk[((size_t)(b * 128 + 64 + r)) * NN + n0 + nq];
        float v0 = k4.x * zsm[nq];
        float v1 = k4.y * zsm[nq + 1];
        float v2 = k4.z * zsm[nq + 2];
        float v3 = k4.w * zsm[nq + 3];
        __nv_bfloat16 h0, l0, h1, l1;
        size_t o = ((size_t)b * 64 + r) * NN + n0 + nq;
        split_bf16(v0, h0, l0); split_bf16(v1, h1, l1);
        *(__nv_bfloat162*)&g_KZh[o] = {h0, h1};
        *(__nv_bfloat162*)&g_KZl[o] = {l0, l1};
        split_bf16(v2, h0, l0); split_bf16(v3, h1, l1);
        *(__nv_bfloat162*)&g_KZh[o + 2] = {h0, h1};
        *(__nv_bfloat162*)&g_KZl[o + 2] = {l0, l1};
    }
}

// ---------------- spatial pass B ----------------
#define PBS 35840
#define PB_SMEM (2 * PBS)
__global__ void __launch_bounds__(256, 2) passB_tc() {
    extern __shared__ __align__(16) char smem[];
    unsigned sb = smem_u32(smem);
    int t = threadIdx.x;
    int wid = t >> 5, lid = t & 31;
    int b = blockIdx.y;
    int m0 = blockIdx.x * 128;
    int g = lid >> 2, tig = lid & 3;

    float c[4][2][4] = {};
    size_t ebase = ((size_t)b) << 24;

    {
        #pragma unroll
        for (int rep = 0; rep < 2; ++rep) {
            int u = t + rep * 256;
            int r = u >> 3, q = u & 7;
            size_t src = ((size_t)b * 64 + r) * NN + q * 8;
            cpa16(sb + r * 144 + q * 16, g_KZh + src);
            cpa16(sb + 9216 + r * 144 + q * 16, g_KZl + src);
        }
        #pragma unroll
        for (int rep = 0; rep < 4; ++rep) {
            int u = t + rep * 256;
            int r = u >> 4, q = u & 15;
            cpa16(sb + 18432 + r * 272 + q * 16, g_E2 + ebase + (size_t)r * NN + m0 + q * 8);
        }
        CP_COMMIT();
    }

    for (int ch = 0; ch < 64; ++ch) {
        if (ch + 1 < 64) {
            unsigned boff = ((ch + 1) & 1) * PBS;
            int n1 = (ch + 1) * 64;
            #pragma unroll
            for (int rep = 0; rep < 2; ++rep) {
                int u = t + rep * 256;
                int r = u >> 3, q = u & 7;
                size_t src = ((size_t)b * 64 + r) * NN + n1 + q * 8;
                cpa16(sb + boff + r * 144 + q * 16, g_KZh + src);
                cpa16(sb + boff + 9216 + r * 144 + q * 16, g_KZl + src);
            }
            #pragma unroll
            for (int rep = 0; rep < 4; ++rep) {
                int u = t + rep * 256;
                int r = u >> 4, q = u & 15;
                cpa16(sb + boff + 18432 + r * 272 + q * 16,
                      g_E2 + ebase + (size_t)(n1 + r) * NN + m0 + q * 8);
            }
            CP_COMMIT();
            CP_WAIT1();
        } else {
            CP_WAIT0();
        }
        __syncthreads();
        unsigned boff = (ch & 1) * PBS;
        unsigned aAddrH = sb + boff + (unsigned)(((lid & 15)) * 144 + (lid >> 4) * 16);
        unsigned eAddr = sb + boff + 18432 +
            (unsigned)(((lid & 7) + ((lid >> 3) & 1) * 8) * 272 + (wid * 16 + (lid >> 4) * 8) * 2);
        #pragma unroll
        for (int ks = 0; ks < 4; ++ks) {
            unsigned eb[4];
            ldsm4t(eb, eAddr + ks * 16 * 272);
            #pragma unroll
            for (int mt = 0; mt < 4; ++mt) {
                unsigned ah[4], al[4];
                ldsm4(ah, aAddrH + mt * 2304 + ks * 32);
                ldsm4(al, aAddrH + 9216 + mt * 2304 + ks * 32);
                #pragma unroll
                for (int nt = 0; nt < 2; ++nt) {
                    mma_bf16(c[mt][nt], ah, &eb[nt * 2]);
                    mma_bf16(c[mt][nt], al, &eb[nt * 2]);
                }
            }
        }
        __syncthreads();
    }

    #pragma unroll
    for (int mt = 0; mt < 4; ++mt) {
        int r = mt * 16 + g;
        size_t r0 = ((size_t)(b * 128 + r)) * NN;
        size_t r1 = r0 + (size_t)8 * NN;
        #pragma unroll
        for (int nt = 0; nt < 2; ++nt) {
            int m = m0 + wid * 16 + nt * 8 + tig * 2;
            __nv_bfloat16 h0, l0, h1, l1;
            split_bf16(c[mt][nt][0], h0, l0);
            split_bf16(c[mt][nt][1], h1, l1);
            *(__nv_bfloat162*)&g_OSh[r0 + m] = {h0, h1};
            *(__nv_bfloat162*)&g_OSl[r0 + m] = {l0, l1};
            split_bf16(c[mt][nt][2], h0, l0);
            split_bf16(c[mt][nt][3], h1, l1);
            *(__nv_bfloat162*)&g_OSh[r1 + m] = {h0, h1};
            *(__nv_bfloat162*)&g_OSl[r1 + m] = {l0, l1};
        }
    }
}

// ---------------- channel Gram via HMMA ----------------
__global__ void __launch_bounds__(128) chan_gram_tc() {
    __shared__ __align__(16) char csm[4 * 9216];
    unsigned sb = smem_u32(csm);
    int t = threadIdx.x;
    int wid = t >> 5, lid = t & 31;
    int b = blockIdx.y;
    int chunk = blockIdx.x;
    int wr = wid & 1, wc = wid >> 1;
    int g = lid >> 2, tig = lid & 3;

    unsigned aAddr = sb + (unsigned)((wr * 32 + (lid & 15)) * 144 + (lid >> 4) * 16);
    unsigned bAddr = sb + 2 * 9216 +
        (unsigned)((wc * 32 + ((lid >> 4) & 1) * 8 + (lid & 7)) * 144 + ((lid >> 3) & 1) * 16);

    float c[2][4][4] = {};

    for (int sub = 0; sub < 8; ++sub) {
        int n0 = chunk * 512 + sub * 64;
        __syncthreads();
        #pragma unroll
        for (int rep = 0; rep < 4; ++rep) {
            int u = t + rep * 128;
            int r = u >> 3, q = u & 7;
            size_t sq = ((size_t)(b * 128 + r)) * NN + n0 + q * 8;
            size_t sk = ((size_t)(b * 128 + 64 + r)) * NN + n0 + q * 8;
            *(uint4*)(csm + r * 144 + q * 16) = *(const uint4*)(g_CH + sq);
            *(uint4*)(csm + 9216 + r * 144 + q * 16) = *(const uint4*)(g_CL + sq);
            *(uint4*)(csm + 2 * 9216 + r * 144 + q * 16) = *(const uint4*)(g_CH + sk);
            *(uint4*)(csm + 3 * 9216 + r * 144 + q * 16) = *(const uint4*)(g_CL + sk);
        }
        __syncthreads();
        #pragma unroll
        for (int ks = 0; ks < 4; ++ks) {
            unsigned bh[2][4], bl[2][4];
            ldsm4(bh[0], bAddr + ks * 32);
            ldsm4(bh[1], bAddr + 16 * 144 + ks * 32);
            ldsm4(bl[0], bAddr + 9216 + ks * 32);
            ldsm4(bl[1], bAddr + 9216 + 16 * 144 + ks * 32);
            #pragma unroll
            for (int mt = 0; mt < 2; ++mt) {
                unsigned ah[4], al[4];
                ldsm4(ah, aAddr + mt * 2304 + ks * 32);
                ldsm4(al, aAddr + 9216 + mt * 2304 + ks * 32);
                #pragma unroll
                for (int nt = 0; nt < 4; ++nt) {
                    const unsigned* bhp = &bh[nt >> 1][(nt & 1) * 2];
                    const unsigned* blp = &bl[nt >> 1][(nt & 1) * 2];
                    mma_bf16(c[mt][nt], ah, bhp);
                    mma_bf16(c[mt][nt], ah, blp);
                    mma_bf16(c[mt][nt], al, bhp);
                }
            }
        }
    }

    float* gp = &g_Gp[(b * 8 + chunk) * 4096];
    #pragma unroll
    for (int mt = 0; mt < 2; ++mt) {
        int r = wr * 32 + mt * 16 + g;
        #pragma unroll
        for (int nt = 0; nt < 4; ++nt) {
            int s = wc * 32 + nt * 8 + tig * 2;
            *(float2*)&gp[r * 64 + s] = {c[mt][nt][0], c[mt][nt][1]};
            *(float2*)&gp[(r + 8) * 64 + s] = {c[mt][nt][2], c[mt][nt][3]};
        }
    }
}

__global__ void chan_softmax() {
    int r = blockIdx.x;
    int b = blockIdx.y;
    int s = threadIdx.x;
    __shared__ float red[64];
    float v = 0.f;
    #pragma unroll
    for (int ch = 0; ch < 8; ++ch)
        v += g_Gp[(b * 8 + ch) * 4096 + r * 64 + s];
    red[s] = v;
    __syncthreads();
    for (int off = 32; off >= 1; off >>= 1) {
        if (s < off) red[s] = fmaxf(red[s], red[s + off]);
        __syncthreads();
    }
    float mx = red[0];
    __syncthreads();
    float e = __expf(v - mx);
    red[s] = e;
    __syncthreads();
    for (int off = 32; off >= 1; off >>= 1) {
        if (s < off) red[s] += red[s + off];
        __syncthreads();
    }
    g_A[b * 4096 + r * 64 + s] = e / red[0];
}

__global__ void __launch_bounds__(256) chan_out() {
    int b = blockIdx.y;
    int p = blockIdx.x * 256 + threadIdx.x;
    __shared__ __align__(16) float As[64][64];
    #pragma unroll
    for (int k = 0; k < 16; ++k)
        (&As[0][0])[threadIdx.x + k * 256] = g_A[b * 4096 + threadIdx.x + k * 256];
    __syncthreads();
    float kreg[64];
    #pragma unroll
    for (int s = 0; s < 64; ++s) {
        size_t o = ((size_t)(b * 128 + 64 + s)) * NN + p;
        kreg[s] = __bfloat162float(g_CH[o]) + __bfloat162float(g_CL[o]);
    }
    ull kp2[32];
    #pragma unroll
    for (int s = 0; s < 32; ++s) {
        ull r; asm("mov.b64 %0, {%1, %2};" : "=l"(r) : "f"(kreg[2 * s]), "f"(kreg[2 * s + 1]));
        kp2[s] = r;
    }
    #pragma unroll 2
    for (int r = 0; r < 64; ++r) {
        ull acc = 0;
        const ull* arow = (const ull*)&As[r][0];
        #pragma unroll
        for (int s = 0; s < 32; ++s)
            fma2s(acc, arow[s], kp2[s]);
        float lo, hi;
        unpack2(acc, lo, hi);
        float v = lo + hi;
        __nv_bfloat16 h, l; split_bf16(v, h, l);
        size_t o = ((size_t)(b * 128 + 64 + r)) * NN + p;
        g_OSh[o] = h; g_OSl[o] = l;
    }
}

// ---------------- final GEMM via HMMA (3-pass) ----------------
#define FT_SMEM 139264
__global__ void __launch_bounds__(256) final_tc(float* __restrict__ out) {
    extern __shared__ __align__(16) char smem[];
    unsigned sb = smem_u32(smem);
    int t = threadIdx.x;
    int wid = t >> 5, lid = t & 31;
    int b = blockIdx.z;
    int o0 = blockIdx.y * 128;
    int p0 = blockIdx.x * 128;
    int wr = wid & 1, wc = wid >> 1;
    int g = lid >> 2, tig = lid & 3;

    #pragma unroll
    for (int rep = 0; rep < 8; ++rep) {
        int u = t + rep * 256;
        int r = u >> 4, q = u & 15;
        *(uint4*)(smem + r * 272 + q * 16) = *(const uint4*)(g_WCh + (size_t)(o0 + r) * 128 + q * 8);
        *(uint4*)(smem + 34816 + r * 272 + q * 16) = *(const uint4*)(g_WCl + (size_t)(o0 + r) * 128 + q * 8);
        size_t bs = ((size_t)(b * 128 + r)) * NN + p0 + q * 8;
        *(uint4*)(smem + 69632 + r * 272 + q * 16) = *(const uint4*)(g_OSh + bs);
        *(uint4*)(smem + 104448 + r * 272 + q * 16) = *(const uint4*)(g_OSl + bs);
    }
    __syncthreads();

    unsigned aAddr = sb + (unsigned)((wr * 64 + (lid & 15)) * 272 + (lid >> 4) * 16);
    unsigned eAddr = sb + 69632 +
        (unsigned)(((lid & 7) + ((lid >> 3) & 1) * 8) * 272 + (wc * 32 + (lid >> 4) * 8) * 2);

    float c[4][4][4] = {};
    #pragma unroll
    for (int ks = 0; ks < 8; ++ks) {
        unsigned bh[2][4], bl[2][4];
        ldsm4t(bh[0], eAddr + ks * 16 * 272);
        ldsm4t(bh[1], eAddr + ks * 16 * 272 + 32);
        ldsm4t(bl[0], eAddr + 34816 + ks * 16 * 272);
        ldsm4t(bl[1], eAddr + 34816 + ks * 16 * 272 + 32);
        #pragma unroll
        for (int mt = 0; mt < 4; ++mt) {
            unsigned ah[4], al[4];
            ldsm4(ah, aAddr + mt * 16 * 272 + ks * 32);
            ldsm4(al, aAddr + 34816 + mt * 16 * 272 + ks * 32);
            #pragma unroll
            for (int nt = 0; nt < 4; ++nt) {
                const unsigned* bhp = &bh[nt >> 1][(nt & 1) * 2];
                const unsigned* blp = &bl[nt >> 1][(nt & 1) * 2];
                mma_bf16(c[mt][nt], ah, bhp);
                mma_bf16(c[mt][nt], ah, blp);
                mma_bf16(c[mt][nt], al, bhp);
            }
        }
    }

    #pragma unroll
    for (int mt = 0; mt < 4; ++mt) {
        int o = o0 + wr * 64 + mt * 16 + g;
        float b0 = g_bout[o], b1 = g_bout[o + 8];
        size_t r0 = ((size_t)(b * 512 + o)) * NN;
        size_t r1 = r0 + (size_t)8 * NN;
        #pragma unroll
        for (int nt = 0; nt < 4; ++nt) {
            int pc = p0 + wc * 32 + nt * 8 + tig * 2;
            float2 v0 = {c[mt][nt][0] + b0, c[mt][nt][1] + b0};
            float2 v1 = {c[mt][nt][2] + b1, c[mt][nt][3] + b1};
            *(float2*)&out[r0 + pc] = v0;
            *(float2*)&out[r1 + pc] = v1;
        }
    }
}

// ---------------- launch ----------------
extern "C" void kernel_launch(void* const* d_in, const int* in_sizes, int n_in,
                              void* d_out, int out_size) {
    const float* top  = (const float*)d_in[0];
    const float* bot  = (const float*)d_in[1];
    const float* wt   = (const float*)d_in[2];
    const float* bt   = (const float*)d_in[3];
    const float* wb   = (const float*)d_in[4];
    const float* bb   = (const float*)d_in[5];
    const float* s_w1 = (const float*)d_in[6];
    const float* s_b1 = (const float*)d_in[7];
    const float* s_w2 = (const float*)d_in[8];
    const float* s_b2 = (const float*)d_in[9];
    const float* s_wo = (const float*)d_in[10];
    const float* s_bo = (const float*)d_in[11];
    const float* c_wq = (const float*)d_in[12];
    const float* c_bq = (const float*)d_in[13];
    const float* c_wk = (const float*)d_in[14];
    const float* c_bk = (const float*)d_in[15];
    const float* c_wo = (const float*)d_in[16];
    const float* c_bo = (const float*)d_in[17];
    const float* f_w  = (const float*)d_in[18];
    const float* f_b  = (const float*)d_in[19];
    float* out = (float*)d_out;

    static cudaStream_t s2 = 0;
    static cudaEvent_t evStart = 0, evPre = 0, evQk = 0, evChan = 0;
    if (!s2) {
        cudaStreamCreateWithFlags(&s2, cudaStreamNonBlocking);
        cudaEventCreateWithFlags(&evStart, cudaEventDisableTiming);
        cudaEventCreateWithFlags(&evPre, cudaEventDisableTiming);
        cudaEventCreateWithFlags(&evQk, cudaEventDisableTiming);
        cudaEventCreateWithFlags(&evChan, cudaEventDisableTiming);
        cudaFuncSetAttribute(qk_tc3, cudaFuncAttributeMaxDynamicSharedMemorySize, QK3_SMEM);
        cudaFuncSetAttribute(passA_tc, cudaFuncAttributeMaxDynamicSharedMemorySize, PA_SMEM);
        cudaFuncSetAttribute(passB_tc, cudaFuncAttributeMaxDynamicSharedMemorySize, PB_SMEM);
        cudaFuncSetAttribute(final_tc, cudaFuncAttributeMaxDynamicSharedMemorySize, FT_SMEM);
    }

    // fork s2
    cudaEventRecord(evStart, 0);
    cudaStreamWaitEvent(s2, evStart, 0);

    // pre-phase: s0 folds, s2 input convert (fold_outc deferred)
    fold_qkw<<<512, 256>>>(wt, wb, s_w1, s_w2, c_wq, c_wk);
    fold_bias<<<1, 512>>>(bt, bb, s_b1, s_b2, c_bq, c_bk, f_w, s_bo, c_bo, f_b,
                          s_w1, s_w2, c_wq, c_wk);
    conv_x<<<dim3(128, 32, 8), dim3(32, 8), 0, s2>>>(top, bot);
    cudaEventRecord(evPre, s2);
    cudaStreamWaitEvent(0, evPre, 0);

    // big qk GEMM (also produces QKT + CH/CL)
    qk_tc3<<<dim3(32, 2, 8), 256, QK3_SMEM>>>();
    cudaEventRecord(evQk, 0);

    // s2: output-weight fold + channel branch
    cudaStreamWaitEvent(s2, evQk, 0);
    fold_outc<<<256, 256, 0, s2>>>(f_w, s_wo, c_wo);
    chan_gram_tc<<<dim3(8, 8), 128, 0, s2>>>();
    chan_softmax<<<dim3(64, 8), 64, 0, s2>>>();
    chan_out<<<dim3(16, 8), 256, 0, s2>>>();
    cudaEventRecord(evChan, s2);

    // s0: spatial branch (conv_qk and conv_kz are fused away)
    passA_tc<<<dim3(32, 8), 256, PA_SMEM>>>();
    passB_tc<<<dim3(32, 8), 256, PB_SMEM>>>();

    // join and finish
    cudaStreamWaitEvent(0, evChan, 0);
    final_tc<<<dim3(32, 4, 8), 256, FT_SMEM>>>(out);
}